// round 2
// baseline (speedup 1.0000x reference)
#include <cuda_runtime.h>
#include <math.h>

#define BN 8
#define NP 8192
#define MP 1024
#define KNB 17

// ---------------- scratch (device globals; no allocation) ----------------
__device__ float g_gvec[BN * 128];
__device__ float g_f1[BN * NP * 128];     // after c1 MLP  (point-major [b*NP+n][128])
__device__ float g_f2[BN * NP * 128];     // after cs MLP
__device__ float g_down[BN * MP * 3];
__device__ int   g_knn[BN * MP * KNB];

// ---------------- global-feature MLP: 512 -> 256 relu -> 128 -------------
__global__ void k_global(const float* __restrict__ gf,
                         const float* __restrict__ w1, const float* __restrict__ b1,
                         const float* __restrict__ w2, const float* __restrict__ b2) {
    __shared__ float s_in[512];
    __shared__ float s_h[256];
    int b = blockIdx.x, t = threadIdx.x;
    for (int i = t; i < 512; i += 256) s_in[i] = gf[b * 512 + i];
    __syncthreads();
    float a = b1[t];
    const float* wr = w1 + t * 512;
    for (int c = 0; c < 512; c++) a += wr[c] * s_in[c];
    s_h[t] = fmaxf(a, 0.f);
    __syncthreads();
    if (t < 128) {
        float a2 = b2[t];
        const float* w2r = w2 + t * 256;
        for (int c = 0; c < 256; c++) a2 += w2r[c] * s_h[c];
        g_gvec[b * 128 + t] = a2;
    }
}

// ---------------- c1 MLP: 3 -> 64 relu -> 128 ----------------------------
__global__ void __launch_bounds__(128) k_c1(const float* __restrict__ x,
                                            const float* __restrict__ w1, const float* __restrict__ b1,
                                            const float* __restrict__ w2, const float* __restrict__ b2) {
    __shared__ float sx[16 * 3];
    __shared__ float sh[16 * 64];
    int t = threadIdx.x;
    int base = blockIdx.x * 16;                 // global point id over B*N
    if (t < 48) sx[t] = x[(size_t)base * 3 + t];
    __syncthreads();
    for (int i = 0; i < 8; i++) {               // 16*64 hidden
        int task = t + 128 * i;
        int p = task >> 6, o = task & 63;
        float a = b1[o];
        a += w1[o * 3 + 0] * sx[p * 3 + 0];
        a += w1[o * 3 + 1] * sx[p * 3 + 1];
        a += w1[o * 3 + 2] * sx[p * 3 + 2];
        sh[p * 64 + o] = fmaxf(a, 0.f);
    }
    __syncthreads();
    for (int i = 0; i < 16; i++) {              // 16*128 outputs
        int task = t + 128 * i;
        int p = task >> 7, o = task & 127;
        float a = b2[o];
        const float* wr = w2 + o * 64;
        const float* hr = sh + p * 64;
#pragma unroll 16
        for (int c = 0; c < 64; c++) a += wr[c] * hr[c];
        g_f1[(size_t)(base + p) * 128 + o] = a;
    }
}

// ---------------- cs MLP: [f1|g] 256 -> 256 relu -> 128 ------------------
__global__ void __launch_bounds__(256) k_cs(const float* __restrict__ w1, const float* __restrict__ b1,
                                            const float* __restrict__ w2, const float* __restrict__ b2) {
    extern __shared__ float sm[];
    float* s_in = sm;                 // [32][256]
    float* s_h  = sm + 32 * 256;      // [32][256]
    int t = threadIdx.x;
    int base = blockIdx.x * 32;
    int b = base >> 13;
    for (int i = t; i < 32 * 128; i += 256) {
        int p = i >> 7, c = i & 127;
        s_in[p * 256 + c] = g_f1[(size_t)(base + p) * 128 + c];
        s_in[p * 256 + 128 + c] = g_gvec[b * 128 + c];
    }
    __syncthreads();
    // hidden: one output channel per thread, all 32 points
    {
        float acc[32];
#pragma unroll
        for (int p = 0; p < 32; p++) acc[p] = 0.f;
        const float4* wr = (const float4*)(w1 + t * 256);
        for (int c4 = 0; c4 < 64; c4++) {
            float4 w = __ldg(wr + c4);
#pragma unroll
            for (int p = 0; p < 32; p++) {
                float4 v = *(const float4*)(s_in + p * 256 + c4 * 4);
                acc[p] += w.x * v.x + w.y * v.y + w.z * v.z + w.w * v.w;
            }
        }
        float bo = b1[t];
        __syncthreads();   // ensure all reads of s_in done before we reuse? (s_h distinct) -- keep for safety ordering of s_h writes vs phase2 reads below
#pragma unroll
        for (int p = 0; p < 32; p++) s_h[p * 256 + t] = fmaxf(acc[p] + bo, 0.f);
    }
    __syncthreads();
    // out: 128 channels, threads split into two groups of 16 points
    {
        int o = t & 127, pg = t >> 7;
        float acc[16];
#pragma unroll
        for (int p = 0; p < 16; p++) acc[p] = 0.f;
        const float4* wr = (const float4*)(w2 + o * 256);
        for (int c4 = 0; c4 < 64; c4++) {
            float4 w = __ldg(wr + c4);
#pragma unroll
            for (int p = 0; p < 16; p++) {
                float4 v = *(const float4*)(s_h + (pg * 16 + p) * 256 + c4 * 4);
                acc[p] += w.x * v.x + w.y * v.y + w.z * v.z + w.w * v.w;
            }
        }
        float bo = b2[o];
#pragma unroll
        for (int p = 0; p < 16; p++)
            g_f2[(size_t)(base + pg * 16 + p) * 128 + o] = acc[p] + bo;
    }
}

// ---------------- FPS (exact JAX arithmetic replication) ------------------
__global__ void __launch_bounds__(1024, 1) k_fps(const float* __restrict__ x,
                                                 float* __restrict__ out_down) {
    int b = blockIdx.x, t = threadIdx.x;
    const float* xb = x + (size_t)b * NP * 3;
    float px[8], py[8], pz[8], md[8];
#pragma unroll
    for (int j = 0; j < 8; j++) {
        int n = j * 1024 + t;
        px[j] = xb[n * 3 + 0];
        py[j] = xb[n * 3 + 1];
        pz[j] = xb[n * 3 + 2];
        md[j] = 1e10f;
    }
    __shared__ float s_bv[32];
    __shared__ int   s_bi[32];
    __shared__ float s_piv[3];
    if (t == 0) {
        s_piv[0] = xb[0]; s_piv[1] = xb[1]; s_piv[2] = xb[2];
        g_down[(b * MP) * 3 + 0] = xb[0];
        g_down[(b * MP) * 3 + 1] = xb[1];
        g_down[(b * MP) * 3 + 2] = xb[2];
        out_down[(size_t)(b * MP) * 3 + 0] = xb[0];
        out_down[(size_t)(b * MP) * 3 + 1] = xb[1];
        out_down[(size_t)(b * MP) * 3 + 2] = xb[2];
    }
    __syncthreads();
    for (int it = 1; it < MP; it++) {
        float cx = s_piv[0], cy = s_piv[1], cz = s_piv[2];
        float bv = -1.f; int bi = 0;
#pragma unroll
        for (int j = 0; j < 8; j++) {
            float dx = __fsub_rn(px[j], cx);
            float dy = __fsub_rn(py[j], cy);
            float dz = __fsub_rn(pz[j], cz);
            float d = __fadd_rn(__fadd_rn(__fmul_rn(dx, dx), __fmul_rn(dy, dy)), __fmul_rn(dz, dz));
            float m = fminf(md[j], d);
            md[j] = m;
            if (m > bv) { bv = m; bi = j * 1024 + t; }
        }
#pragma unroll
        for (int off = 16; off; off >>= 1) {
            float ov = __shfl_down_sync(0xffffffffu, bv, off);
            int   oi = __shfl_down_sync(0xffffffffu, bi, off);
            if (ov > bv || (ov == bv && oi < bi)) { bv = ov; bi = oi; }
        }
        if ((t & 31) == 0) { s_bv[t >> 5] = bv; s_bi[t >> 5] = bi; }
        __syncthreads();
        if (t == 0) {
            float fv = s_bv[0]; int fi = s_bi[0];
            for (int w = 1; w < 32; w++) {
                if (s_bv[w] > fv || (s_bv[w] == fv && s_bi[w] < fi)) { fv = s_bv[w]; fi = s_bi[w]; }
            }
            float ax = xb[fi * 3], ay = xb[fi * 3 + 1], az = xb[fi * 3 + 2];
            s_piv[0] = ax; s_piv[1] = ay; s_piv[2] = az;
            g_down[(b * MP + it) * 3 + 0] = ax;
            g_down[(b * MP + it) * 3 + 1] = ay;
            g_down[(b * MP + it) * 3 + 2] = az;
            out_down[(size_t)(b * MP + it) * 3 + 0] = ax;
            out_down[(size_t)(b * MP + it) * 3 + 1] = ay;
            out_down[(size_t)(b * MP + it) * 3 + 2] = az;
        }
        __syncthreads();
    }
}

// ---------------- KNN top-17 (stable, JAX d2 formula) ---------------------
__global__ void __launch_bounds__(128) k_knn(const float* __restrict__ x) {
    extern __shared__ float sx[];     // NP*3
    int gid = blockIdx.x * 128 + threadIdx.x;   // over B*M
    int b = gid >> 10;
    const float* xb = x + (size_t)b * NP * 3;
    for (int i = threadIdx.x; i < NP * 3; i += 128) sx[i] = xb[i];
    __syncthreads();
    float qx = g_down[gid * 3 + 0], qy = g_down[gid * 3 + 1], qz = g_down[gid * 3 + 2];
    float sd = __fadd_rn(__fadd_rn(__fmul_rn(qx, qx), __fmul_rn(qy, qy)), __fmul_rn(qz, qz));
    float dist[17]; int ind[17];
#pragma unroll
    for (int i = 0; i < 17; i++) { dist[i] = 3.4e38f; ind[i] = 0; }
    for (int n = 0; n < NP; n++) {
        float ax = sx[n * 3 + 0], ay = sx[n * 3 + 1], az = sx[n * 3 + 2];
        float sn = __fadd_rn(__fadd_rn(__fmul_rn(ax, ax), __fmul_rn(ay, ay)), __fmul_rn(az, az));
        float dt = __fadd_rn(__fadd_rn(__fmul_rn(qx, ax), __fmul_rn(qy, ay)), __fmul_rn(qz, az));
        float d2 = __fsub_rn(__fadd_rn(sd, sn), __fmul_rn(2.f, dt));
        if (d2 < dist[16]) {
            int pos = 0;
#pragma unroll
            for (int s = 0; s < 17; s++) pos += (dist[s] <= d2) ? 1 : 0;
#pragma unroll
            for (int s = 16; s > 0; s--) {
                if (s > pos) { dist[s] = dist[s - 1]; ind[s] = ind[s - 1]; }
                else if (s == pos) { dist[s] = d2; ind[s] = n; }
            }
            if (pos == 0) { dist[0] = d2; ind[0] = n; }
        }
    }
#pragma unroll
    for (int s = 0; s < 17; s++) g_knn[(size_t)gid * 17 + s] = ind[s];
}

// ---------------- grouped convs + attention + output ----------------------
// block handles 4 m's; dynamic smem layout (floats):
//   feat   [0 .. 17408)        4*17*256
//   h1     [17408 .. 21760)    4*17*64      (aliased later by kv/qv)
//   h2     [21760 .. 26112)
//   knnx   [26112 .. 26316)
//   down   [26316 .. 26328)
//   lg     [26328 .. 26392)
//   idx    [26392 .. 26460)    (ints)
__global__ void __launch_bounds__(256) k_attn(
    const float* __restrict__ x,
    const float* __restrict__ w1, const float* __restrict__ b1,
    const float* __restrict__ gg1, const float* __restrict__ bb1,
    const float* __restrict__ w2, const float* __restrict__ b2,
    const float* __restrict__ gg2, const float* __restrict__ bb2,
    const float* __restrict__ w3, const float* __restrict__ b3,
    const float* __restrict__ qw, const float* __restrict__ qb,
    const float* __restrict__ kw, const float* __restrict__ kb,
    float* __restrict__ out_new)
{
    extern __shared__ float sm[];
    float* feat = sm;
    float* h1   = sm + 17408;
    float* h2   = sm + 21760;
    float* kv   = sm + 17408;            // alias (after h1/h2 dead)
    float* qv   = sm + 21504;            // alias
    float* knnx = sm + 26112;
    float* dwn  = sm + 26316;
    float* lg   = sm + 26328;
    int*   sidx = (int*)(sm + 26392);

    int t = threadIdx.x;
    int wid = t >> 5, lane = t & 31;
    int bm0 = blockIdx.x * 4;
    int b = bm0 >> 10;
    const float* xb = x + (size_t)b * NP * 3;

    if (t < 68) {
        int id = g_knn[(size_t)bm0 * 17 + t];
        sidx[t] = id;
        knnx[t * 3 + 0] = xb[id * 3 + 0];
        knnx[t * 3 + 1] = xb[id * 3 + 1];
        knnx[t * 3 + 2] = xb[id * 3 + 2];
    }
    if (t < 12) dwn[t] = g_down[(size_t)bm0 * 3 + t];
    __syncthreads();

    // gather knn_f -> feat[:,0..127]
    for (int r = wid; r < 68; r += 8) {
        const float* src = g_f2 + ((size_t)(b * NP) + sidx[r]) * 128;
        float* dst = feat + r * 256;
        for (int s = lane; s < 128; s += 32) dst[s] = src[s];
    }

    const float bnc = 1.f / sqrtf(1.0f + 1e-5f);

    // h1: 9 -> 64, bn, leaky
    for (int i = 0; i < 17; i++) {
        int task = t + 256 * i;         // < 4352
        int o = task & 63;
        int row = task >> 6;            // mi*17+kk
        int mi = row / 17;
        const float* kp = knnx + row * 3;
        const float* dp = dwn + mi * 3;
        float r0 = dp[0], r1 = dp[1], r2v = dp[2];
        float r3 = kp[0], r4 = kp[1], r5 = kp[2];
        const float* w = w1 + o * 9;
        float a = b1[o];
        a += w[0] * r0 + w[1] * r1 + w[2] * r2v;
        a += w[3] * r3 + w[4] * r4 + w[5] * r5;
        a += w[6] * (r0 - r3) + w[7] * (r1 - r4) + w[8] * (r2v - r5);
        a = a * (gg1[o] * bnc) + bb1[o];
        a = a > 0.f ? a : 0.01f * a;
        h1[row * 64 + o] = a;
    }
    __syncthreads();
    // h2: 64 -> 64, bn, leaky
    for (int i = 0; i < 17; i++) {
        int task = t + 256 * i;
        int o = task & 63;
        int row = task >> 6;
        const float* w = w2 + o * 64;
        const float* hr = h1 + row * 64;
        float a = b2[o];
#pragma unroll 16
        for (int c = 0; c < 64; c++) a += w[c] * hr[c];
        a = a * (gg2[o] * bnc) + bb2[o];
        a = a > 0.f ? a : 0.01f * a;
        h2[row * 64 + o] = a;
    }
    __syncthreads();
    // r2: 64 -> 128 -> feat[:,128..255]
    for (int i = 0; i < 34; i++) {
        int task = t + 256 * i;         // < 8704
        int o = task & 127;
        int row = task >> 7;
        const float* w = w3 + o * 64;
        const float* hr = h2 + row * 64;
        float a = b3[o];
#pragma unroll 16
        for (int c = 0; c < 64; c++) a += w[c] * hr[c];
        feat[row * 256 + 128 + o] = a;
    }
    __syncthreads();

    // q/k 256x256 convs + logits, one mi at a time (kv/qv alias h1/h2 space)
    const float4* kwr = (const float4*)(kw + t * 256);
    const float4* qwr = (const float4*)(qw + t * 256);
    for (int mi = 0; mi < 4; mi++) {
        float accq = 0.f;
        float accj[16];
#pragma unroll
        for (int j = 0; j < 16; j++) accj[j] = 0.f;
        const float4* f0 = (const float4*)(feat + (mi * 17) * 256);
#pragma unroll 2
        for (int c4 = 0; c4 < 64; c4++) {
            float4 wq = __ldg(qwr + c4);
            float4 v0 = f0[c4];
            accq += wq.x * v0.x + wq.y * v0.y + wq.z * v0.z + wq.w * v0.w;
            float4 wk = __ldg(kwr + c4);
#pragma unroll
            for (int j = 0; j < 16; j++) {
                float4 v = ((const float4*)(feat + (mi * 17 + 1 + j) * 256))[c4];
                accj[j] += wk.x * v.x + wk.y * v.y + wk.z * v.z + wk.w * v.w;
            }
        }
        qv[t] = accq + qb[t];
#pragma unroll
        for (int j = 0; j < 16; j++) kv[j * 256 + t] = accj[j] + kb[t];
        __syncthreads();
        for (int j = wid; j < 16; j += 8) {
            float s = 0.f;
#pragma unroll
            for (int s8 = 0; s8 < 8; s8++) {
                int o = lane + 32 * s8;
                s += qv[o] * kv[j * 256 + o];
            }
#pragma unroll
            for (int off = 16; off; off >>= 1) s += __shfl_down_sync(0xffffffffu, s, off);
            if (lane == 0) lg[mi * 16 + j] = s;
        }
        __syncthreads();
    }

    // softmax + weighted neighbor sum
    if (t < 4) {
        float l[16], mx = -3.4e38f;
#pragma unroll
        for (int j = 0; j < 16; j++) { l[j] = lg[t * 16 + j]; mx = fmaxf(mx, l[j]); }
        float sum = 0.f;
#pragma unroll
        for (int j = 0; j < 16; j++) { l[j] = expf(l[j] - mx); sum += l[j]; }
        float inv = 1.f / sum;
        float nx = 0.f, ny = 0.f, nz = 0.f;
#pragma unroll
        for (int j = 0; j < 16; j++) {
            float w = l[j] * inv;
            const float* kp = knnx + (t * 17 + 1 + j) * 3;
            nx += w * kp[0]; ny += w * kp[1]; nz += w * kp[2];
        }
        float* po = out_new + (size_t)(bm0 + t) * 3;
        po[0] = nx; po[1] = ny; po[2] = nz;
    }
}

// ---------------- launch ---------------------------------------------------
extern "C" void kernel_launch(void* const* d_in, const int* in_sizes, int n_in,
                              void* d_out, int out_size) {
    const float* x      = (const float*)d_in[0];
    const float* gf     = (const float*)d_in[1];
    const float* c1_w1  = (const float*)d_in[2];
    const float* c1_b1  = (const float*)d_in[3];
    const float* c1_w2  = (const float*)d_in[4];
    const float* c1_b2  = (const float*)d_in[5];
    const float* cf_w1  = (const float*)d_in[6];
    const float* cf_b1  = (const float*)d_in[7];
    const float* cf_w2  = (const float*)d_in[8];
    const float* cf_b2  = (const float*)d_in[9];
    const float* cs_w1  = (const float*)d_in[10];
    const float* cs_b1  = (const float*)d_in[11];
    const float* cs_w2  = (const float*)d_in[12];
    const float* cs_b2  = (const float*)d_in[13];
    const float* s2_w1  = (const float*)d_in[14];
    const float* s2_b1  = (const float*)d_in[15];
    const float* s2_g1  = (const float*)d_in[16];
    const float* s2_bb1 = (const float*)d_in[17];
    const float* s2_w2  = (const float*)d_in[18];
    const float* s2_b2  = (const float*)d_in[19];
    const float* s2_g2  = (const float*)d_in[20];
    const float* s2_bb2 = (const float*)d_in[21];
    const float* s2_w3  = (const float*)d_in[22];
    const float* s2_b3  = (const float*)d_in[23];
    const float* q_w    = (const float*)d_in[24];
    const float* q_b    = (const float*)d_in[25];
    const float* k_w    = (const float*)d_in[26];
    const float* k_b    = (const float*)d_in[27];
    float* out = (float*)d_out;

    cudaFuncSetAttribute(k_cs,   cudaFuncAttributeMaxDynamicSharedMemorySize, 65536);
    cudaFuncSetAttribute(k_knn,  cudaFuncAttributeMaxDynamicSharedMemorySize, NP * 3 * 4);
    cudaFuncSetAttribute(k_attn, cudaFuncAttributeMaxDynamicSharedMemorySize, 26460 * 4);

    // FPS first (longest sequential chain, independent of feature MLPs)
    k_fps<<<BN, 1024>>>(x, out);
    k_global<<<BN, 256>>>(gf, cf_w1, cf_b1, cf_w2, cf_b2);
    k_c1<<<(BN * NP) / 16, 128>>>(x, c1_w1, c1_b1, c1_w2, c1_b2);
    k_cs<<<(BN * NP) / 32, 256, 65536>>>(cs_w1, cs_b1, cs_w2, cs_b2);
    k_knn<<<(BN * MP) / 128, 128, NP * 3 * 4>>>(x);
    k_attn<<<(BN * MP) / 4, 256, 26460 * 4>>>(x,
        s2_w1, s2_b1, s2_g1, s2_bb1,
        s2_w2, s2_b2, s2_g2, s2_bb2,
        s2_w3, s2_b3, q_w, q_b, k_w, k_b,
        out + (size_t)BN * MP * 3);
}

// round 3
// speedup vs baseline: 4.5098x; 4.5098x over previous
#include <cuda_runtime.h>
#include <math.h>

#define BN 8
#define NP 8192
#define MP 1024
#define KNB 17

// ---------------- scratch (device globals; no allocation) ----------------
__device__ float g_gvec[BN * 128];
__device__ float g_f1[BN * NP * 128];
__device__ float g_f2[BN * NP * 128];
__device__ float g_down[BN * MP * 3];
__device__ int   g_knn[BN * MP * KNB];
// repacked weights: W[O][C] -> RP[((c>>2)*O + o)*4 + (c&3)]
__device__ float g_csw1p[256 * 256];
__device__ float g_csw2p[128 * 256];
__device__ float g_qwp[256 * 256];
__device__ float g_kwp[256 * 256];
__device__ float g_s2w2p[64 * 64];
__device__ float g_s2w3p[128 * 64];
__device__ float g_c1w2p[128 * 64];

typedef unsigned long long ull;
__device__ __forceinline__ ull f2pk(float lo, float hi) {
    ull r; asm("mov.b64 %0,{%1,%2};" : "=l"(r) : "f"(lo), "f"(hi)); return r;
}
__device__ __forceinline__ void f2up(ull v, float& lo, float& hi) {
    asm("mov.b64 {%0,%1},%2;" : "=f"(lo), "=f"(hi) : "l"(v));
}
__device__ __forceinline__ ull addx2(ull a, ull b) {
    ull r; asm("add.rn.f32x2 %0,%1,%2;" : "=l"(r) : "l"(a), "l"(b)); return r;
}
__device__ __forceinline__ ull mulx2(ull a, ull b) {
    ull r; asm("mul.rn.f32x2 %0,%1,%2;" : "=l"(r) : "l"(a), "l"(b)); return r;
}

// ---------------- weight repack ------------------------------------------
__global__ void k_repack(const float* __restrict__ w, float* __restrict__ o, int O, int C) {
    int g = blockIdx.x * 256 + threadIdx.x;
    if (g >= O * C) return;
    int oo = g / C, c = g - oo * C;
    o[((c >> 2) * O + oo) * 4 + (c & 3)] = w[g];
}

// ---------------- global-feature MLP: 512 -> 256 relu -> 128 -------------
__global__ void k_global(const float* __restrict__ gf,
                         const float* __restrict__ w1, const float* __restrict__ b1,
                         const float* __restrict__ w2, const float* __restrict__ b2) {
    __shared__ float s_in[512];
    __shared__ float s_h[256];
    int b = blockIdx.x, t = threadIdx.x;
    for (int i = t; i < 512; i += 256) s_in[i] = gf[b * 512 + i];
    __syncthreads();
    float a = b1[t];
    const float* wr = w1 + t * 512;
    for (int c = 0; c < 512; c++) a += wr[c] * s_in[c];
    s_h[t] = fmaxf(a, 0.f);
    __syncthreads();
    if (t < 128) {
        float a2 = b2[t];
        const float* w2r = w2 + t * 256;
        for (int c = 0; c < 256; c++) a2 += w2r[c] * s_h[c];
        g_gvec[b * 128 + t] = a2;
    }
}

// ---------------- c1 MLP: 3 -> 64 relu -> 128 ----------------------------
__global__ void __launch_bounds__(128) k_c1(const float* __restrict__ x,
                                            const float* __restrict__ w1, const float* __restrict__ b1,
                                            const float* __restrict__ b2) {
    __shared__ __align__(16) float sx[16 * 3];
    __shared__ __align__(16) float sh[16 * 64];
    int t = threadIdx.x;
    int base = blockIdx.x * 16;
    if (t < 48) sx[t] = x[(size_t)base * 3 + t];
    __syncthreads();
    for (int i = 0; i < 8; i++) {
        int task = t + 128 * i;
        int p = task >> 6, o = task & 63;
        float a = b1[o];
        a += w1[o * 3 + 0] * sx[p * 3 + 0];
        a += w1[o * 3 + 1] * sx[p * 3 + 1];
        a += w1[o * 3 + 2] * sx[p * 3 + 2];
        sh[p * 64 + o] = fmaxf(a, 0.f);
    }
    __syncthreads();
    const float4* wp = (const float4*)g_c1w2p;
    for (int i = 0; i < 16; i++) {
        int task = t + 128 * i;
        int p = task >> 7, o = task & 127;
        float a = b2[o];
        const float4* hr = (const float4*)(sh + p * 64);
#pragma unroll
        for (int c4 = 0; c4 < 16; c4++) {
            float4 w = wp[c4 * 128 + o];
            float4 v = hr[c4];
            a += w.x * v.x + w.y * v.y + w.z * v.z + w.w * v.w;
        }
        g_f1[(size_t)(base + p) * 128 + o] = a;
    }
}

// ---------------- cs MLP: [f1|g] 256 -> 256 relu -> 128 ------------------
__global__ void __launch_bounds__(256) k_cs(const float* __restrict__ b1v,
                                            const float* __restrict__ b2v) {
    extern __shared__ __align__(16) float sm_cs[];
    float* s_in = sm_cs;
    float* s_h  = sm_cs + 32 * 256;
    int t = threadIdx.x;
    int base = blockIdx.x * 32;
    int b = base >> 13;
    for (int i = t; i < 32 * 128; i += 256) {
        int p = i >> 7, c = i & 127;
        s_in[p * 256 + c] = g_f1[(size_t)(base + p) * 128 + c];
        s_in[p * 256 + 128 + c] = g_gvec[b * 128 + c];
    }
    __syncthreads();
    {
        float acc[32];
#pragma unroll
        for (int p = 0; p < 32; p++) acc[p] = 0.f;
        const float4* wp = (const float4*)g_csw1p;
        for (int c4 = 0; c4 < 64; c4++) {
            float4 w = wp[c4 * 256 + t];
#pragma unroll
            for (int p = 0; p < 32; p++) {
                float4 v = *(const float4*)(s_in + p * 256 + c4 * 4);
                acc[p] += w.x * v.x + w.y * v.y + w.z * v.z + w.w * v.w;
            }
        }
        float bo = b1v[t];
        __syncthreads();
#pragma unroll
        for (int p = 0; p < 32; p++) s_h[p * 256 + t] = fmaxf(acc[p] + bo, 0.f);
    }
    __syncthreads();
    {
        int o = t & 127, pg = t >> 7;
        float acc[16];
#pragma unroll
        for (int p = 0; p < 16; p++) acc[p] = 0.f;
        const float4* wp = (const float4*)g_csw2p;
        for (int c4 = 0; c4 < 64; c4++) {
            float4 w = wp[c4 * 128 + o];
#pragma unroll
            for (int p = 0; p < 16; p++) {
                float4 v = *(const float4*)(s_h + (pg * 16 + p) * 256 + c4 * 4);
                acc[p] += w.x * v.x + w.y * v.y + w.z * v.z + w.w * v.w;
            }
        }
        float bo = b2v[o];
#pragma unroll
        for (int p = 0; p < 16; p++)
            g_f2[(size_t)(base + pg * 16 + p) * 128 + o] = acc[p] + bo;
    }
}

// ---------------- FPS (bit-exact JAX arithmetic, f32x2 packed) ------------
__global__ void __launch_bounds__(1024, 1) k_fps(const float* __restrict__ x,
                                                 float* __restrict__ out_down) {
    extern __shared__ float sx[];     // NP*3 floats
    __shared__ float s_bv[32];
    __shared__ int   s_bi[32];
    __shared__ float s_piv[3];
    int b = blockIdx.x, t = threadIdx.x, lane = t & 31, wid = t >> 5;
    const float* xb = x + (size_t)b * NP * 3;
    for (int i = t; i < NP * 3; i += 1024) sx[i] = xb[i];
    __syncthreads();
    if (t == 0) {
        s_piv[0] = sx[0]; s_piv[1] = sx[1]; s_piv[2] = sx[2];
        int o3 = b * MP * 3;
        g_down[o3 + 0] = sx[0]; g_down[o3 + 1] = sx[1]; g_down[o3 + 2] = sx[2];
        out_down[o3 + 0] = sx[0]; out_down[o3 + 1] = sx[1]; out_down[o3 + 2] = sx[2];
    }
    // thread t owns points 8t..8t+7 (contiguous ascending -> first-index ties OK)
    ull pxp[4], pyp[4], pzp[4];
    float md[8];
    int base = t * 8;
#pragma unroll
    for (int j = 0; j < 4; j++) {
        int n = base + 2 * j;
        pxp[j] = f2pk(sx[n * 3 + 0], sx[n * 3 + 3]);
        pyp[j] = f2pk(sx[n * 3 + 1], sx[n * 3 + 4]);
        pzp[j] = f2pk(sx[n * 3 + 2], sx[n * 3 + 5]);
        md[2 * j] = 1e10f; md[2 * j + 1] = 1e10f;
    }
    __syncthreads();
    for (int it = 1; it < MP; it++) {
        float cx = s_piv[0], cy = s_piv[1], cz = s_piv[2];
        ull ncx = f2pk(-cx, -cx), ncy = f2pk(-cy, -cy), ncz = f2pk(-cz, -cz);
        float bv = -1.f; int bi = 0;
#pragma unroll
        for (int j = 0; j < 4; j++) {
            ull dx = addx2(pxp[j], ncx);
            ull dy = addx2(pyp[j], ncy);
            ull dz = addx2(pzp[j], ncz);
            ull s = addx2(addx2(mulx2(dx, dx), mulx2(dy, dy)), mulx2(dz, dz));
            float lo, hi; f2up(s, lo, hi);
            float m0 = fminf(md[2 * j], lo);     md[2 * j] = m0;
            float m1 = fminf(md[2 * j + 1], hi); md[2 * j + 1] = m1;
            if (m0 > bv) { bv = m0; bi = base + 2 * j; }
            if (m1 > bv) { bv = m1; bi = base + 2 * j + 1; }
        }
#pragma unroll
        for (int off = 16; off; off >>= 1) {
            float ov = __shfl_down_sync(0xffffffffu, bv, off);
            int   oi = __shfl_down_sync(0xffffffffu, bi, off);
            if (ov > bv || (ov == bv && oi < bi)) { bv = ov; bi = oi; }
        }
        if (lane == 0) { s_bv[wid] = bv; s_bi[wid] = bi; }
        __syncthreads();
        if (wid == 0) {
            float v = s_bv[lane]; int vi = s_bi[lane];
#pragma unroll
            for (int off = 16; off; off >>= 1) {
                float ov = __shfl_down_sync(0xffffffffu, v, off);
                int   oi = __shfl_down_sync(0xffffffffu, vi, off);
                if (ov > v || (ov == v && oi < vi)) { v = ov; vi = oi; }
            }
            if (lane == 0) {
                float ax = sx[vi * 3], ay = sx[vi * 3 + 1], az = sx[vi * 3 + 2];
                s_piv[0] = ax; s_piv[1] = ay; s_piv[2] = az;
                int o3 = (b * MP + it) * 3;
                g_down[o3 + 0] = ax; g_down[o3 + 1] = ay; g_down[o3 + 2] = az;
                out_down[o3 + 0] = ax; out_down[o3 + 1] = ay; out_down[o3 + 2] = az;
            }
        }
        __syncthreads();
    }
}

// ---------------- KNN top-17 (stable, JAX d2 formula) ---------------------
__global__ void __launch_bounds__(128) k_knn(const float* __restrict__ x) {
    extern __shared__ float skx[];
    int gid = blockIdx.x * 128 + threadIdx.x;
    int b = gid >> 10;
    const float* xb = x + (size_t)b * NP * 3;
    for (int i = threadIdx.x; i < NP * 3; i += 128) skx[i] = xb[i];
    __syncthreads();
    float qx = g_down[gid * 3 + 0], qy = g_down[gid * 3 + 1], qz = g_down[gid * 3 + 2];
    float sd = __fadd_rn(__fadd_rn(__fmul_rn(qx, qx), __fmul_rn(qy, qy)), __fmul_rn(qz, qz));
    float dist[17]; int ind[17];
#pragma unroll
    for (int i = 0; i < 17; i++) { dist[i] = 3.4e38f; ind[i] = 0; }
    for (int n = 0; n < NP; n++) {
        float ax = skx[n * 3 + 0], ay = skx[n * 3 + 1], az = skx[n * 3 + 2];
        float sn = __fadd_rn(__fadd_rn(__fmul_rn(ax, ax), __fmul_rn(ay, ay)), __fmul_rn(az, az));
        float dt = __fadd_rn(__fadd_rn(__fmul_rn(qx, ax), __fmul_rn(qy, ay)), __fmul_rn(qz, az));
        float d2 = __fsub_rn(__fadd_rn(sd, sn), __fmul_rn(2.f, dt));
        if (d2 < dist[16]) {
            int pos = 0;
#pragma unroll
            for (int s = 0; s < 17; s++) pos += (dist[s] <= d2) ? 1 : 0;
#pragma unroll
            for (int s = 16; s > 0; s--) {
                if (s > pos) { dist[s] = dist[s - 1]; ind[s] = ind[s - 1]; }
                else if (s == pos) { dist[s] = d2; ind[s] = n; }
            }
            if (pos == 0) { dist[0] = d2; ind[0] = n; }
        }
    }
#pragma unroll
    for (int s = 0; s < 17; s++) g_knn[(size_t)gid * 17 + s] = ind[s];
}

// ---------------- grouped convs + attention + output ----------------------
// smem floats: feat[0..17408) kv[17408..25600) qv[25600..26112)
//              knnx[26112..26316) dwn[26316..26328) lg[26328..26392) idx[26392..26460)
// h1 aliases [17408..21760), h2 aliases [21760..26112)
__global__ void __launch_bounds__(256) k_attn(
    const float* __restrict__ x,
    const float* __restrict__ w1, const float* __restrict__ b1,
    const float* __restrict__ gg1, const float* __restrict__ bb1,
    const float* __restrict__ b2, const float* __restrict__ gg2, const float* __restrict__ bb2,
    const float* __restrict__ b3,
    const float* __restrict__ qb, const float* __restrict__ kb,
    float* __restrict__ out_new)
{
    extern __shared__ __align__(16) float sm[];
    float* feat = sm;
    float* h1   = sm + 17408;
    float* h2   = sm + 21760;
    float* kv   = sm + 17408;
    float* qv   = sm + 25600;
    float* knnx = sm + 26112;
    float* dwn  = sm + 26316;
    float* lg   = sm + 26328;
    int*   sidx = (int*)(sm + 26392);

    int t = threadIdx.x;
    int wid = t >> 5, lane = t & 31;
    int bm0 = blockIdx.x * 4;
    int b = bm0 >> 10;
    const float* xb = x + (size_t)b * NP * 3;

    if (t < 68) {
        int id = g_knn[(size_t)bm0 * 17 + t];
        sidx[t] = id;
        knnx[t * 3 + 0] = xb[id * 3 + 0];
        knnx[t * 3 + 1] = xb[id * 3 + 1];
        knnx[t * 3 + 2] = xb[id * 3 + 2];
    }
    if (t < 12) dwn[t] = g_down[(size_t)bm0 * 3 + t];
    __syncthreads();

    // gather knn_f -> feat[:,0..127]
    for (int r = wid; r < 68; r += 8) {
        const float* src = g_f2 + ((size_t)(b * NP) + sidx[r]) * 128;
        float* dst = feat + r * 256;
        for (int s = lane; s < 128; s += 32) dst[s] = src[s];
    }

    const float bnc = 1.f / sqrtf(1.0f + 1e-5f);

    // h1: 9 -> 64, bn, leaky
    for (int i = 0; i < 17; i++) {
        int task = t + 256 * i;
        int o = task & 63;
        int row = task >> 6;
        int mi = row / 17;
        const float* kp = knnx + row * 3;
        const float* dp = dwn + mi * 3;
        float r0 = dp[0], r1 = dp[1], r2v = dp[2];
        float r3 = kp[0], r4 = kp[1], r5 = kp[2];
        const float* w = w1 + o * 9;
        float a = b1[o];
        a += w[0] * r0 + w[1] * r1 + w[2] * r2v;
        a += w[3] * r3 + w[4] * r4 + w[5] * r5;
        a += w[6] * (r0 - r3) + w[7] * (r1 - r4) + w[8] * (r2v - r5);
        a = a * (gg1[o] * bnc) + bb1[o];
        a = a > 0.f ? a : 0.01f * a;
        h1[row * 64 + o] = a;
    }
    __syncthreads();
    // h2: 64 -> 64, bn, leaky (coalesced repacked weights)
    {
        const float4* wp = (const float4*)g_s2w2p;
        for (int i = 0; i < 17; i++) {
            int task = t + 256 * i;
            int o = task & 63;
            int row = task >> 6;
            const float4* hr = (const float4*)(h1 + row * 64);
            float a = b2[o];
#pragma unroll
            for (int c4 = 0; c4 < 16; c4++) {
                float4 w = wp[c4 * 64 + o];
                float4 v = hr[c4];
                a += w.x * v.x + w.y * v.y + w.z * v.z + w.w * v.w;
            }
            a = a * (gg2[o] * bnc) + bb2[o];
            a = a > 0.f ? a : 0.01f * a;
            h2[row * 64 + o] = a;
        }
    }
    __syncthreads();
    // r2: 64 -> 128 -> feat[:,128..255]
    {
        const float4* wp = (const float4*)g_s2w3p;
        for (int i = 0; i < 34; i++) {
            int task = t + 256 * i;
            int o = task & 127;
            int row = task >> 7;
            const float4* hr = (const float4*)(h2 + row * 64);
            float a = b3[o];
#pragma unroll
            for (int c4 = 0; c4 < 16; c4++) {
                float4 w = wp[c4 * 128 + o];
                float4 v = hr[c4];
                a += w.x * v.x + w.y * v.y + w.z * v.z + w.w * v.w;
            }
            feat[row * 256 + 128 + o] = a;
        }
    }
    __syncthreads();

    // q/k 256x256 convs + logits, two m's per pass (weight loads reused)
    const float4* qwp4 = (const float4*)g_qwp;
    const float4* kwp4 = (const float4*)g_kwp;
    const float4* f4 = (const float4*)feat;
    for (int mp = 0; mp < 2; mp++) {
        float accq0 = 0.f, accq1 = 0.f;
        float a0[16], a1[16];
#pragma unroll
        for (int j = 0; j < 16; j++) { a0[j] = 0.f; a1[j] = 0.f; }
        int r0b = (2 * mp) * 17 * 64;
        int r1b = (2 * mp + 1) * 17 * 64;
        for (int c4 = 0; c4 < 64; c4++) {
            float4 wq = qwp4[c4 * 256 + t];
            float4 wk = kwp4[c4 * 256 + t];
            float4 v;
            v = f4[r0b + c4];
            accq0 += wq.x * v.x + wq.y * v.y + wq.z * v.z + wq.w * v.w;
            v = f4[r1b + c4];
            accq1 += wq.x * v.x + wq.y * v.y + wq.z * v.z + wq.w * v.w;
#pragma unroll
            for (int j = 0; j < 16; j++) {
                v = f4[r0b + (1 + j) * 64 + c4];
                a0[j] += wk.x * v.x + wk.y * v.y + wk.z * v.z + wk.w * v.w;
            }
#pragma unroll
            for (int j = 0; j < 16; j++) {
                v = f4[r1b + (1 + j) * 64 + c4];
                a1[j] += wk.x * v.x + wk.y * v.y + wk.z * v.z + wk.w * v.w;
            }
        }
        qv[t] = accq0 + qb[t];
        qv[256 + t] = accq1 + qb[t];
#pragma unroll
        for (int j = 0; j < 16; j++) {
            kv[j * 256 + t] = a0[j] + kb[t];
            kv[(16 + j) * 256 + t] = a1[j] + kb[t];
        }
        __syncthreads();
        for (int hj = wid; hj < 32; hj += 8) {       // hj = h*16 + j
            float s = 0.f;
#pragma unroll
            for (int s8 = 0; s8 < 8; s8++) {
                int o = lane + 32 * s8;
                s += qv[(hj >> 4) * 256 + o] * kv[hj * 256 + o];
            }
#pragma unroll
            for (int off = 16; off; off >>= 1) s += __shfl_down_sync(0xffffffffu, s, off);
            if (lane == 0) lg[mp * 32 + hj] = s;
        }
        __syncthreads();
    }

    // softmax + weighted neighbor sum
    if (t < 4) {
        float l[16], mx = -3.4e38f;
#pragma unroll
        for (int j = 0; j < 16; j++) { l[j] = lg[t * 16 + j]; mx = fmaxf(mx, l[j]); }
        float sum = 0.f;
#pragma unroll
        for (int j = 0; j < 16; j++) { l[j] = expf(l[j] - mx); sum += l[j]; }
        float inv = 1.f / sum;
        float nx = 0.f, ny = 0.f, nz = 0.f;
#pragma unroll
        for (int j = 0; j < 16; j++) {
            float w = l[j] * inv;
            const float* kp = knnx + (t * 17 + 1 + j) * 3;
            nx += w * kp[0]; ny += w * kp[1]; nz += w * kp[2];
        }
        float* po = out_new + (size_t)(bm0 + t) * 3;
        po[0] = nx; po[1] = ny; po[2] = nz;
    }
}

// ---------------- launch ---------------------------------------------------
extern "C" void kernel_launch(void* const* d_in, const int* in_sizes, int n_in,
                              void* d_out, int out_size) {
    const float* x      = (const float*)d_in[0];
    const float* gf     = (const float*)d_in[1];
    const float* c1_w1  = (const float*)d_in[2];
    const float* c1_b1  = (const float*)d_in[3];
    const float* c1_w2  = (const float*)d_in[4];
    const float* c1_b2  = (const float*)d_in[5];
    const float* cf_w1  = (const float*)d_in[6];
    const float* cf_b1  = (const float*)d_in[7];
    const float* cf_w2  = (const float*)d_in[8];
    const float* cf_b2  = (const float*)d_in[9];
    const float* cs_w1  = (const float*)d_in[10];
    const float* cs_b1  = (const float*)d_in[11];
    const float* cs_w2  = (const float*)d_in[12];
    const float* cs_b2  = (const float*)d_in[13];
    const float* s2_w1  = (const float*)d_in[14];
    const float* s2_b1  = (const float*)d_in[15];
    const float* s2_g1  = (const float*)d_in[16];
    const float* s2_bb1 = (const float*)d_in[17];
    const float* s2_w2  = (const float*)d_in[18];
    const float* s2_b2  = (const float*)d_in[19];
    const float* s2_g2  = (const float*)d_in[20];
    const float* s2_bb2 = (const float*)d_in[21];
    const float* s2_w3  = (const float*)d_in[22];
    const float* s2_b3  = (const float*)d_in[23];
    const float* q_w    = (const float*)d_in[24];
    const float* q_b    = (const float*)d_in[25];
    const float* k_w    = (const float*)d_in[26];
    const float* k_b    = (const float*)d_in[27];
    float* out = (float*)d_out;

    static bool s_init = false;
    static cudaStream_t st;
    static cudaEvent_t evF, evD;
    static float *rp_csw1, *rp_csw2, *rp_qw, *rp_kw, *rp_s2w2, *rp_s2w3, *rp_c1w2;
    if (!s_init) {
        cudaStreamCreateWithFlags(&st, cudaStreamNonBlocking);
        cudaEventCreateWithFlags(&evF, cudaEventDisableTiming);
        cudaEventCreateWithFlags(&evD, cudaEventDisableTiming);
        cudaGetSymbolAddress((void**)&rp_csw1, g_csw1p);
        cudaGetSymbolAddress((void**)&rp_csw2, g_csw2p);
        cudaGetSymbolAddress((void**)&rp_qw,   g_qwp);
        cudaGetSymbolAddress((void**)&rp_kw,   g_kwp);
        cudaGetSymbolAddress((void**)&rp_s2w2, g_s2w2p);
        cudaGetSymbolAddress((void**)&rp_s2w3, g_s2w3p);
        cudaGetSymbolAddress((void**)&rp_c1w2, g_c1w2p);
        cudaFuncSetAttribute(k_cs,   cudaFuncAttributeMaxDynamicSharedMemorySize, 65536);
        cudaFuncSetAttribute(k_knn,  cudaFuncAttributeMaxDynamicSharedMemorySize, NP * 3 * 4);
        cudaFuncSetAttribute(k_fps,  cudaFuncAttributeMaxDynamicSharedMemorySize, NP * 3 * 4);
        cudaFuncSetAttribute(k_attn, cudaFuncAttributeMaxDynamicSharedMemorySize, 26460 * 4);
        s_init = true;
    }

    // fork: FPS -> KNN chain runs concurrently with repacks + MLP chain
    cudaEventRecord(evF, 0);
    cudaStreamWaitEvent(st, evF, 0);
    k_fps<<<BN, 1024, NP * 3 * 4, st>>>(x, out);
    k_knn<<<(BN * MP) / 128, 128, NP * 3 * 4, st>>>(x);
    cudaEventRecord(evD, st);

    // main stream: repacks + feature MLPs
    k_repack<<<(256 * 256 + 255) / 256, 256>>>(cs_w1, rp_csw1, 256, 256);
    k_repack<<<(128 * 256 + 255) / 256, 256>>>(cs_w2, rp_csw2, 128, 256);
    k_repack<<<(256 * 256 + 255) / 256, 256>>>(q_w, rp_qw, 256, 256);
    k_repack<<<(256 * 256 + 255) / 256, 256>>>(k_w, rp_kw, 256, 256);
    k_repack<<<(64 * 64 + 255) / 256, 256>>>(s2_w2, rp_s2w2, 64, 64);
    k_repack<<<(128 * 64 + 255) / 256, 256>>>(s2_w3, rp_s2w3, 128, 64);
    k_repack<<<(128 * 64 + 255) / 256, 256>>>(c1_w2, rp_c1w2, 128, 64);
    k_global<<<BN, 256>>>(gf, cf_w1, cf_b1, cf_w2, cf_b2);
    k_c1<<<(BN * NP) / 16, 128>>>(x, c1_w1, c1_b1, c1_b2);
    k_cs<<<(BN * NP) / 32, 256, 65536>>>(cs_b1, cs_b2);

    // join and run attention
    cudaStreamWaitEvent(0, evD, 0);
    k_attn<<<(BN * MP) / 4, 256, 26460 * 4>>>(x,
        s2_w1, s2_b1, s2_g1, s2_bb1,
        s2_b2, s2_g2, s2_bb2,
        s2_b3, q_b, k_b,
        out + (size_t)BN * MP * 3);
}

// round 4
// speedup vs baseline: 5.3333x; 1.1826x over previous
#include <cuda_runtime.h>
#include <math.h>

#define BN 8
#define NP 8192
#define MP 1024
#define KNB 17

// ---------------- scratch (device globals; no allocation) ----------------
__device__ float g_gvec[BN * 128];
__device__ float g_f1[BN * NP * 128];
__device__ float g_f2[BN * NP * 128];
__device__ float g_down[BN * MP * 3];
__device__ int   g_knn[BN * MP * KNB];
// repacked weights: W[O][C] -> RP[((c>>2)*O + o)*4 + (c&3)]
__device__ float g_csw1p[256 * 256];
__device__ float g_csw2p[128 * 256];
__device__ float g_qwp[256 * 256];
__device__ float g_s2w2p[64 * 64];
__device__ float g_s2w3p[128 * 64];
__device__ float g_c1w2p[128 * 64];

typedef unsigned long long ull;
__device__ __forceinline__ ull f2pk(float lo, float hi) {
    ull r; asm("mov.b64 %0,{%1,%2};" : "=l"(r) : "f"(lo), "f"(hi)); return r;
}
__device__ __forceinline__ void f2up(ull v, float& lo, float& hi) {
    asm("mov.b64 {%0,%1},%2;" : "=f"(lo), "=f"(hi) : "l"(v));
}
__device__ __forceinline__ ull addx2(ull a, ull b) {
    ull r; asm("add.rn.f32x2 %0,%1,%2;" : "=l"(r) : "l"(a), "l"(b)); return r;
}
__device__ __forceinline__ ull mulx2(ull a, ull b) {
    ull r; asm("mul.rn.f32x2 %0,%1,%2;" : "=l"(r) : "l"(a), "l"(b)); return r;
}

// ---------------- prep: all weight repacks + global MLP in one kernel ----
__device__ __forceinline__ void rp_one(const float* __restrict__ w, float* __restrict__ o,
                                       int O, int C, int blk) {
    int g = blk * 256 + threadIdx.x;
    if (g >= O * C) return;
    int oo = g / C, c = g - oo * C;
    o[((c >> 2) * O + oo) * 4 + (c & 3)] = w[g];
}

__global__ void k_prep(const float* __restrict__ cs_w1, const float* __restrict__ cs_w2,
                       const float* __restrict__ q_w,
                       const float* __restrict__ s2_w2, const float* __restrict__ s2_w3,
                       const float* __restrict__ c1_w2,
                       const float* __restrict__ gf,
                       const float* __restrict__ w1, const float* __restrict__ b1,
                       const float* __restrict__ w2, const float* __restrict__ b2) {
    int blk = blockIdx.x;
    if (blk < 256)       { rp_one(cs_w1, g_csw1p, 256, 256, blk); return; }
    else if (blk < 384)  { rp_one(cs_w2, g_csw2p, 128, 256, blk - 256); return; }
    else if (blk < 640)  { rp_one(q_w,   g_qwp,   256, 256, blk - 384); return; }
    else if (blk < 656)  { rp_one(s2_w2, g_s2w2p,  64,  64, blk - 640); return; }
    else if (blk < 688)  { rp_one(s2_w3, g_s2w3p, 128,  64, blk - 656); return; }
    else if (blk < 720)  { rp_one(c1_w2, g_c1w2p, 128,  64, blk - 688); return; }
    // global-feature MLP: 512 -> 256 relu -> 128
    __shared__ float s_in[512];
    __shared__ float s_h[256];
    int b = blk - 720, t = threadIdx.x;
    for (int i = t; i < 512; i += 256) s_in[i] = gf[b * 512 + i];
    __syncthreads();
    float a = b1[t];
    const float* wr = w1 + t * 512;
    for (int c = 0; c < 512; c++) a += wr[c] * s_in[c];
    s_h[t] = fmaxf(a, 0.f);
    __syncthreads();
    if (t < 128) {
        float a2 = b2[t];
        const float* w2r = w2 + t * 256;
        for (int c = 0; c < 256; c++) a2 += w2r[c] * s_h[c];
        g_gvec[b * 128 + t] = a2;
    }
}

// ---------------- c1 MLP: 3 -> 64 relu -> 128 ----------------------------
__global__ void __launch_bounds__(128) k_c1(const float* __restrict__ x,
                                            const float* __restrict__ w1, const float* __restrict__ b1,
                                            const float* __restrict__ b2) {
    __shared__ __align__(16) float sx[16 * 3];
    __shared__ __align__(16) float sh[16 * 64];
    int t = threadIdx.x;
    int base = blockIdx.x * 16;
    if (t < 48) sx[t] = x[(size_t)base * 3 + t];
    __syncthreads();
    for (int i = 0; i < 8; i++) {
        int task = t + 128 * i;
        int p = task >> 6, o = task & 63;
        float a = b1[o];
        a += w1[o * 3 + 0] * sx[p * 3 + 0];
        a += w1[o * 3 + 1] * sx[p * 3 + 1];
        a += w1[o * 3 + 2] * sx[p * 3 + 2];
        sh[p * 64 + o] = fmaxf(a, 0.f);
    }
    __syncthreads();
    const float4* wp = (const float4*)g_c1w2p;
    for (int i = 0; i < 16; i++) {
        int task = t + 128 * i;
        int p = task >> 7, o = task & 127;
        float a = b2[o];
        const float4* hr = (const float4*)(sh + p * 64);
#pragma unroll
        for (int c4 = 0; c4 < 16; c4++) {
            float4 w = wp[c4 * 128 + o];
            float4 v = hr[c4];
            a += w.x * v.x + w.y * v.y + w.z * v.z + w.w * v.w;
        }
        g_f1[(size_t)(base + p) * 128 + o] = a;
    }
}

// ---------------- cs MLP: [f1|g] 256 -> 256 relu -> 128 ------------------
__global__ void __launch_bounds__(256) k_cs(const float* __restrict__ b1v,
                                            const float* __restrict__ b2v) {
    extern __shared__ __align__(16) float sm_cs[];
    float* s_in = sm_cs;
    float* s_h  = sm_cs + 32 * 256;
    int t = threadIdx.x;
    int base = blockIdx.x * 32;
    int b = base >> 13;
    for (int i = t; i < 32 * 128; i += 256) {
        int p = i >> 7, c = i & 127;
        s_in[p * 256 + c] = g_f1[(size_t)(base + p) * 128 + c];
        s_in[p * 256 + 128 + c] = g_gvec[b * 128 + c];
    }
    __syncthreads();
    {
        float acc[32];
#pragma unroll
        for (int p = 0; p < 32; p++) acc[p] = 0.f;
        const float4* wp = (const float4*)g_csw1p;
        for (int c4 = 0; c4 < 64; c4++) {
            float4 w = wp[c4 * 256 + t];
#pragma unroll
            for (int p = 0; p < 32; p++) {
                float4 v = *(const float4*)(s_in + p * 256 + c4 * 4);
                acc[p] += w.x * v.x + w.y * v.y + w.z * v.z + w.w * v.w;
            }
        }
        float bo = b1v[t];
        __syncthreads();
#pragma unroll
        for (int p = 0; p < 32; p++) s_h[p * 256 + t] = fmaxf(acc[p] + bo, 0.f);
    }
    __syncthreads();
    {
        int o = t & 127, pg = t >> 7;
        float acc[16];
#pragma unroll
        for (int p = 0; p < 16; p++) acc[p] = 0.f;
        const float4* wp = (const float4*)g_csw2p;
        for (int c4 = 0; c4 < 64; c4++) {
            float4 w = wp[c4 * 128 + o];
#pragma unroll
            for (int p = 0; p < 16; p++) {
                float4 v = *(const float4*)(s_h + (pg * 16 + p) * 256 + c4 * 4);
                acc[p] += w.x * v.x + w.y * v.y + w.z * v.z + w.w * v.w;
            }
        }
        float bo = b2v[o];
#pragma unroll
        for (int p = 0; p < 16; p++)
            g_f2[(size_t)(base + pg * 16 + p) * 128 + o] = acc[p] + bo;
    }
}

// ---------------- FPS (bit-exact, 1 barrier/iter, xor-bfly reduces) -------
__global__ void __launch_bounds__(1024, 1) k_fps(const float* __restrict__ x,
                                                 float* __restrict__ out_down) {
    extern __shared__ float sx[];     // NP*3 floats
    __shared__ float s_bv[2][32];
    __shared__ int   s_bi[2][32];
    int b = blockIdx.x, t = threadIdx.x, lane = t & 31, wid = t >> 5;
    const float* xb = x + (size_t)b * NP * 3;
    for (int i = t; i < NP * 3; i += 1024) sx[i] = xb[i];
    __syncthreads();
    float cx = sx[0], cy = sx[1], cz = sx[2];
    if (t == 0) {
        int o3 = b * MP * 3;
        g_down[o3 + 0] = cx; g_down[o3 + 1] = cy; g_down[o3 + 2] = cz;
        out_down[o3 + 0] = cx; out_down[o3 + 1] = cy; out_down[o3 + 2] = cz;
    }
    ull pxp[4], pyp[4], pzp[4];
    float md[8];
    int base = t * 8;
#pragma unroll
    for (int j = 0; j < 4; j++) {
        int n = base + 2 * j;
        pxp[j] = f2pk(sx[n * 3 + 0], sx[n * 3 + 3]);
        pyp[j] = f2pk(sx[n * 3 + 1], sx[n * 3 + 4]);
        pzp[j] = f2pk(sx[n * 3 + 2], sx[n * 3 + 5]);
        md[2 * j] = 1e10f; md[2 * j + 1] = 1e10f;
    }
    int buf = 0;
    for (int it = 1; it < MP; it++) {
        ull ncx = f2pk(-cx, -cx), ncy = f2pk(-cy, -cy), ncz = f2pk(-cz, -cz);
        float bv = -1.f; int bi = 0;
#pragma unroll
        for (int j = 0; j < 4; j++) {
            ull dx = addx2(pxp[j], ncx);
            ull dy = addx2(pyp[j], ncy);
            ull dz = addx2(pzp[j], ncz);
            ull s = addx2(addx2(mulx2(dx, dx), mulx2(dy, dy)), mulx2(dz, dz));
            float lo, hi; f2up(s, lo, hi);
            float m0 = fminf(md[2 * j], lo);     md[2 * j] = m0;
            float m1 = fminf(md[2 * j + 1], hi); md[2 * j + 1] = m1;
            if (m0 > bv) { bv = m0; bi = base + 2 * j; }
            if (m1 > bv) { bv = m1; bi = base + 2 * j + 1; }
        }
        // warp argmax (xor-bfly: max w/ min-index tie is order-independent)
#pragma unroll
        for (int off = 16; off; off >>= 1) {
            float ov = __shfl_xor_sync(0xffffffffu, bv, off);
            int   oi = __shfl_xor_sync(0xffffffffu, bi, off);
            if (ov > bv || (ov == bv && oi < bi)) { bv = ov; bi = oi; }
        }
        if (lane == 0) { s_bv[buf][wid] = bv; s_bi[buf][wid] = bi; }
        __syncthreads();
        // every warp redundantly reduces the 32 warp candidates
        float v = s_bv[buf][lane]; int vi = s_bi[buf][lane];
#pragma unroll
        for (int off = 16; off; off >>= 1) {
            float ov = __shfl_xor_sync(0xffffffffu, v, off);
            int   oi = __shfl_xor_sync(0xffffffffu, vi, off);
            if (ov > v || (ov == v && oi < vi)) { v = ov; vi = oi; }
        }
        cx = sx[vi * 3]; cy = sx[vi * 3 + 1]; cz = sx[vi * 3 + 2];
        if (t == 0) {
            int o3 = (b * MP + it) * 3;
            g_down[o3 + 0] = cx; g_down[o3 + 1] = cy; g_down[o3 + 2] = cz;
            out_down[o3 + 0] = cx; out_down[o3 + 1] = cy; out_down[o3 + 2] = cz;
        }
        buf ^= 1;
    }
}

// ---------------- KNN top-17 (stable, JAX d2 formula) ---------------------
__global__ void __launch_bounds__(128) k_knn(const float* __restrict__ x) {
    extern __shared__ float skx[];
    int gid = blockIdx.x * 128 + threadIdx.x;
    int b = gid >> 10;
    const float* xb = x + (size_t)b * NP * 3;
    for (int i = threadIdx.x; i < NP * 3; i += 128) skx[i] = xb[i];
    __syncthreads();
    float qx = g_down[gid * 3 + 0], qy = g_down[gid * 3 + 1], qz = g_down[gid * 3 + 2];
    float sd = __fadd_rn(__fadd_rn(__fmul_rn(qx, qx), __fmul_rn(qy, qy)), __fmul_rn(qz, qz));
    float dist[17]; int ind[17];
#pragma unroll
    for (int i = 0; i < 17; i++) { dist[i] = 3.4e38f; ind[i] = 0; }
    for (int n = 0; n < NP; n++) {
        float ax = skx[n * 3 + 0], ay = skx[n * 3 + 1], az = skx[n * 3 + 2];
        float sn = __fadd_rn(__fadd_rn(__fmul_rn(ax, ax), __fmul_rn(ay, ay)), __fmul_rn(az, az));
        float dt = __fadd_rn(__fadd_rn(__fmul_rn(qx, ax), __fmul_rn(qy, ay)), __fmul_rn(qz, az));
        float d2 = __fsub_rn(__fadd_rn(sd, sn), __fmul_rn(2.f, dt));
        if (d2 < dist[16]) {
            int pos = 0;
#pragma unroll
            for (int s = 0; s < 17; s++) pos += (dist[s] <= d2) ? 1 : 0;
#pragma unroll
            for (int s = 16; s > 0; s--) {
                if (s > pos) { dist[s] = dist[s - 1]; ind[s] = ind[s - 1]; }
                else if (s == pos) { dist[s] = d2; ind[s] = n; }
            }
            if (pos == 0) { dist[0] = d2; ind[0] = n; }
        }
    }
#pragma unroll
    for (int s = 0; s < 17; s++) g_knn[(size_t)gid * 17 + s] = ind[s];
}

// ---------------- grouped convs + attention + output ----------------------
// logits via u = Wk^T q :  logit_mj = u_m . f_j + q_m . bk  (k-conv eliminated)
// smem floats: feat[0..17408)  h1[17408..21760)  h2[21760..26112)
//              qs aliases [17408..18432), us aliases [18432..19456)
//              knnx[26112..26316) dwn[26316..26328) lg[26328..26396) idx[26396..26464)
__global__ void __launch_bounds__(256) k_attn(
    const float* __restrict__ x,
    const float* __restrict__ w1, const float* __restrict__ b1,
    const float* __restrict__ gg1, const float* __restrict__ bb1,
    const float* __restrict__ b2, const float* __restrict__ gg2, const float* __restrict__ bb2,
    const float* __restrict__ b3,
    const float* __restrict__ qb,
    const float* __restrict__ kw, const float* __restrict__ kb,
    float* __restrict__ out_new)
{
    extern __shared__ __align__(16) float sm[];
    float* feat = sm;
    float* h1   = sm + 17408;
    float* h2   = sm + 21760;
    float* qs   = sm + 17408;      // alias (h1 dead by then)
    float* us   = sm + 18432;      // alias
    float* knnx = sm + 26112;
    float* dwn  = sm + 26316;
    float* lg   = sm + 26328;      // 68 floats: 64 logit dots + 4 q.bk
    int*   sidx = (int*)(sm + 26396);

    int t = threadIdx.x;
    int wid = t >> 5, lane = t & 31;
    int bm0 = blockIdx.x * 4;
    int b = bm0 >> 10;
    const float* xb = x + (size_t)b * NP * 3;

    if (t < 68) {
        int id = g_knn[(size_t)bm0 * 17 + t];
        sidx[t] = id;
        knnx[t * 3 + 0] = xb[id * 3 + 0];
        knnx[t * 3 + 1] = xb[id * 3 + 1];
        knnx[t * 3 + 2] = xb[id * 3 + 2];
    }
    if (t < 12) dwn[t] = g_down[(size_t)bm0 * 3 + t];
    __syncthreads();

    // gather knn_f -> feat[:,0..127]
    for (int r = wid; r < 68; r += 8) {
        const float* src = g_f2 + ((size_t)(b * NP) + sidx[r]) * 128;
        float* dst = feat + r * 256;
        for (int s = lane; s < 128; s += 32) dst[s] = src[s];
    }

    const float bnc = 1.f / sqrtf(1.0f + 1e-5f);

    // h1: 9 -> 64, bn, leaky
    for (int i = 0; i < 17; i++) {
        int task = t + 256 * i;
        int o = task & 63;
        int row = task >> 6;
        int mi = row / 17;
        const float* kp = knnx + row * 3;
        const float* dp = dwn + mi * 3;
        float r0 = dp[0], r1 = dp[1], r2v = dp[2];
        float r3 = kp[0], r4 = kp[1], r5 = kp[2];
        const float* w = w1 + o * 9;
        float a = b1[o];
        a += w[0] * r0 + w[1] * r1 + w[2] * r2v;
        a += w[3] * r3 + w[4] * r4 + w[5] * r5;
        a += w[6] * (r0 - r3) + w[7] * (r1 - r4) + w[8] * (r2v - r5);
        a = a * (gg1[o] * bnc) + bb1[o];
        a = a > 0.f ? a : 0.01f * a;
        h1[row * 64 + o] = a;
    }
    __syncthreads();
    // h2: 64 -> 64, bn, leaky
    {
        const float4* wp = (const float4*)g_s2w2p;
        for (int i = 0; i < 17; i++) {
            int task = t + 256 * i;
            int o = task & 63;
            int row = task >> 6;
            const float4* hr = (const float4*)(h1 + row * 64);
            float a = b2[o];
#pragma unroll
            for (int c4 = 0; c4 < 16; c4++) {
                float4 w = wp[c4 * 64 + o];
                float4 v = hr[c4];
                a += w.x * v.x + w.y * v.y + w.z * v.z + w.w * v.w;
            }
            a = a * (gg2[o] * bnc) + bb2[o];
            a = a > 0.f ? a : 0.01f * a;
            h2[row * 64 + o] = a;
        }
    }
    __syncthreads();
    // r2: 64 -> 128 -> feat[:,128..255]
    {
        const float4* wp = (const float4*)g_s2w3p;
        for (int i = 0; i < 34; i++) {
            int task = t + 256 * i;
            int o = task & 127;
            int row = task >> 7;
            const float4* hr = (const float4*)(h2 + row * 64);
            float a = b3[o];
#pragma unroll
            for (int c4 = 0; c4 < 16; c4++) {
                float4 w = wp[c4 * 128 + o];
                float4 v = hr[c4];
                a += w.x * v.x + w.y * v.y + w.z * v.z + w.w * v.w;
            }
            feat[row * 256 + 128 + o] = a;
        }
    }
    __syncthreads();

    // q_m = Wq . feat_row(mi*17) + bq   (thread t = output channel)
    {
        const float4* qwp4 = (const float4*)g_qwp;
        float acc[4];
#pragma unroll
        for (int mi = 0; mi < 4; mi++) acc[mi] = 0.f;
        for (int c4 = 0; c4 < 64; c4++) {
            float4 w = qwp4[c4 * 256 + t];
#pragma unroll
            for (int mi = 0; mi < 4; mi++) {
                float4 v = *(const float4*)(feat + (mi * 17) * 256 + c4 * 4);
                acc[mi] += w.x * v.x + w.y * v.y + w.z * v.z + w.w * v.w;
            }
        }
        float bo = qb[t];
        __syncthreads();                  // h1/h2 region dead after r2 sync; protect qs alias vs h1 readers (already synced) — this orders acc writes
#pragma unroll
        for (int mi = 0; mi < 4; mi++) qs[mi * 256 + t] = acc[mi] + bo;
    }
    __syncthreads();

    // u_m[c] = sum_o kw[o*256+c] * q_m[o]   (raw kw layout is coalesced here)
    {
        float u0 = 0.f, u1 = 0.f, u2 = 0.f, u3 = 0.f;
        for (int o = 0; o < 256; o++) {
            float w = __ldg(kw + o * 256 + t);
            float q0 = qs[o], q1 = qs[256 + o], q2 = qs[512 + o], q3 = qs[768 + o];
            u0 += w * q0; u1 += w * q1; u2 += w * q2; u3 += w * q3;
        }
        us[t] = u0; us[256 + t] = u1; us[512 + t] = u2; us[768 + t] = u3;
    }
    __syncthreads();

    // logits: tasks 0..63 = u_m . f_j ; tasks 64..67 = q_m . bk
    for (int task = wid; task < 68; task += 8) {
        float s = 0.f;
        if (task < 64) {
            int mi = task >> 4, j = task & 15;
            const float* uf = us + mi * 256;
            const float* fr = feat + (mi * 17 + 1 + j) * 256;
#pragma unroll
            for (int s8 = 0; s8 < 8; s8++) { int o = lane + 32 * s8; s += uf[o] * fr[o]; }
        } else {
            int mi = task - 64;
            const float* qr = qs + mi * 256;
#pragma unroll
            for (int s8 = 0; s8 < 8; s8++) { int o = lane + 32 * s8; s += qr[o] * kb[o]; }
        }
#pragma unroll
        for (int off = 16; off; off >>= 1) s += __shfl_down_sync(0xffffffffu, s, off);
        if (lane == 0) lg[task] = s;
    }
    __syncthreads();

    // softmax + weighted neighbor sum
    if (t < 4) {
        float qbk = lg[64 + t];
        float l[16], mx = -3.4e38f;
#pragma unroll
        for (int j = 0; j < 16; j++) { l[j] = lg[t * 16 + j] + qbk; mx = fmaxf(mx, l[j]); }
        float sum = 0.f;
#pragma unroll
        for (int j = 0; j < 16; j++) { l[j] = expf(l[j] - mx); sum += l[j]; }
        float inv = 1.f / sum;
        float nx = 0.f, ny = 0.f, nz = 0.f;
#pragma unroll
        for (int j = 0; j < 16; j++) {
            float w = l[j] * inv;
            const float* kp = knnx + (t * 17 + 1 + j) * 3;
            nx += w * kp[0]; ny += w * kp[1]; nz += w * kp[2];
        }
        float* po = out_new + (size_t)(bm0 + t) * 3;
        po[0] = nx; po[1] = ny; po[2] = nz;
    }
}

// ---------------- launch ---------------------------------------------------
extern "C" void kernel_launch(void* const* d_in, const int* in_sizes, int n_in,
                              void* d_out, int out_size) {
    const float* x      = (const float*)d_in[0];
    const float* gf     = (const float*)d_in[1];
    const float* c1_w1  = (const float*)d_in[2];
    const float* c1_b1  = (const float*)d_in[3];
    const float* c1_w2  = (const float*)d_in[4];
    const float* c1_b2  = (const float*)d_in[5];
    const float* cf_w1  = (const float*)d_in[6];
    const float* cf_b1  = (const float*)d_in[7];
    const float* cf_w2  = (const float*)d_in[8];
    const float* cf_b2  = (const float*)d_in[9];
    const float* cs_w1  = (const float*)d_in[10];
    const float* cs_b1  = (const float*)d_in[11];
    const float* cs_w2  = (const float*)d_in[12];
    const float* cs_b2  = (const float*)d_in[13];
    const float* s2_w1  = (const float*)d_in[14];
    const float* s2_b1  = (const float*)d_in[15];
    const float* s2_g1  = (const float*)d_in[16];
    const float* s2_bb1 = (const float*)d_in[17];
    const float* s2_w2  = (const float*)d_in[18];
    const float* s2_b2  = (const float*)d_in[19];
    const float* s2_g2  = (const float*)d_in[20];
    const float* s2_bb2 = (const float*)d_in[21];
    const float* s2_w3  = (const float*)d_in[22];
    const float* s2_b3  = (const float*)d_in[23];
    const float* q_w    = (const float*)d_in[24];
    const float* q_b    = (const float*)d_in[25];
    const float* k_w    = (const float*)d_in[26];
    const float* k_b    = (const float*)d_in[27];
    float* out = (float*)d_out;

    static bool s_init = false;
    static cudaStream_t st;
    static cudaEvent_t evF, evD;
    if (!s_init) {
        cudaStreamCreateWithFlags(&st, cudaStreamNonBlocking);
        cudaEventCreateWithFlags(&evF, cudaEventDisableTiming);
        cudaEventCreateWithFlags(&evD, cudaEventDisableTiming);
        cudaFuncSetAttribute(k_cs,   cudaFuncAttributeMaxDynamicSharedMemorySize, 65536);
        cudaFuncSetAttribute(k_knn,  cudaFuncAttributeMaxDynamicSharedMemorySize, NP * 3 * 4);
        cudaFuncSetAttribute(k_fps,  cudaFuncAttributeMaxDynamicSharedMemorySize, NP * 3 * 4);
        cudaFuncSetAttribute(k_attn, cudaFuncAttributeMaxDynamicSharedMemorySize, 26464 * 4);
        s_init = true;
    }

    // fork point for side stream
    cudaEventRecord(evF, 0);
    cudaStreamWaitEvent(st, evF, 0);

    // submission order chosen so ncu's profiled launch (#4) = k_fps
    k_prep<<<728, 256>>>(cs_w1, cs_w2, q_w, s2_w2, s2_w3, c1_w2,      // #1
                         gf, cf_w1, cf_b1, cf_w2, cf_b2);
    k_c1<<<(BN * NP) / 16, 128>>>(x, c1_w1, c1_b1, c1_b2);            // #2
    k_cs<<<(BN * NP) / 32, 256, 65536>>>(cs_b1, cs_b2);               // #3
    k_fps<<<BN, 1024, NP * 3 * 4, st>>>(x, out);                      // #4  <- profiled
    k_knn<<<(BN * MP) / 128, 128, NP * 3 * 4, st>>>(x);               // #5
    cudaEventRecord(evD, st);
    cudaStreamWaitEvent(0, evD, 0);
    k_attn<<<(BN * MP) / 4, 256, 26464 * 4>>>(x,                      // #6
        s2_w1, s2_b1, s2_g1, s2_bb1,
        s2_b2, s2_g2, s2_bb2,
        s2_b3, q_b, k_w, k_b,
        out + (size_t)BN * MP * 3);
}

// round 5
// speedup vs baseline: 6.7036x; 1.2569x over previous
#include <cuda_runtime.h>
#include <math.h>

#define BN 8
#define NP 8192
#define MP 1024
#define KNB 17
#define FS 36   // padded transposed-row stride (floats): 144B, 16B-aligned, 4-way-max store conflicts

// ---------------- scratch (device globals; no allocation) ----------------
__device__ float g_gvec[BN * 128];
__device__ float g_f2[BN * NP * 128];
__device__ float g_down[BN * MP * 3];
__device__ int   g_knn[BN * MP * KNB];
// packed weights: W[O][C] -> P[((c>>2)*O + o)*4 + (c&3)]
__device__ float g_csw1p[256 * 256];
__device__ float g_csw2p[128 * 256];
__device__ float g_s2w2p[64 * 64];
__device__ float g_s2w3p[128 * 64];
__device__ float g_c1w2p[128 * 64];
// fused attention mats: A = Wk^T Wq (packed like above), c = Wk^T bq, vb = Wq^T bk, s0 = bq.bk
__device__ float g_Ap[256 * 256];
__device__ float g_cvec[256];
__device__ float g_vb[256];
__device__ float g_s0[1];

typedef unsigned long long ull;
__device__ __forceinline__ ull f2pk(float lo, float hi) {
    ull r; asm("mov.b64 %0,{%1,%2};" : "=l"(r) : "f"(lo), "f"(hi)); return r;
}
__device__ __forceinline__ void f2up(ull v, float& lo, float& hi) {
    asm("mov.b64 {%0,%1},%2;" : "=f"(lo), "=f"(hi) : "l"(v));
}
__device__ __forceinline__ ull addx2(ull a, ull b) {
    ull r; asm("add.rn.f32x2 %0,%1,%2;" : "=l"(r) : "l"(a), "l"(b)); return r;
}
__device__ __forceinline__ ull mulx2(ull a, ull b) {
    ull r; asm("mul.rn.f32x2 %0,%1,%2;" : "=l"(r) : "l"(a), "l"(b)); return r;
}
__device__ __forceinline__ ull fma2(ull a, ull b, ull c) {
    ull r; asm("fma.rn.f32x2 %0,%1,%2,%3;" : "=l"(r) : "l"(a), "l"(b), "l"(c)); return r;
}

// ---------------- prep: repacks + global MLP + fused q/k mats -------------
__device__ __forceinline__ void rp_one(const float* __restrict__ w, float* __restrict__ o,
                                       int O, int C, int blk) {
    int g = blk * 256 + threadIdx.x;
    if (g >= O * C) return;
    int oo = g / C, c = g - oo * C;
    o[((c >> 2) * O + oo) * 4 + (c & 3)] = w[g];
}

__global__ void k_prep(const float* __restrict__ cs_w1, const float* __restrict__ cs_w2,
                       const float* __restrict__ s2_w2, const float* __restrict__ s2_w3,
                       const float* __restrict__ c1_w2,
                       const float* __restrict__ q_w, const float* __restrict__ k_w,
                       const float* __restrict__ q_b, const float* __restrict__ k_b,
                       const float* __restrict__ gf,
                       const float* __restrict__ cf_w1, const float* __restrict__ cf_b1,
                       const float* __restrict__ cf_w2, const float* __restrict__ cf_b2) {
    __shared__ float s_buf[512];
    __shared__ float s_h[256];
    __shared__ float s_red[8];
    int blk = blockIdx.x, t = threadIdx.x;
    if (blk < 256)      { rp_one(cs_w1, g_csw1p, 256, 256, blk); return; }
    if (blk < 384)      { rp_one(cs_w2, g_csw2p, 128, 256, blk - 256); return; }
    if (blk < 400)      { rp_one(s2_w2, g_s2w2p,  64,  64, blk - 384); return; }
    if (blk < 432)      { rp_one(s2_w3, g_s2w3p, 128,  64, blk - 400); return; }
    if (blk < 464)      { rp_one(c1_w2, g_c1w2p, 128,  64, blk - 432); return; }
    if (blk < 720) {
        // row i of A = Wk^T Wq, plus c[i] = (Wk^T bq)[i]
        int i = blk - 464;
        s_buf[t] = k_w[t * 256 + i];          // kcol[o] = kw[o][i]
        __syncthreads();
        float acc = 0.f;
        for (int o = 0; o < 256; o++) acc += s_buf[o] * __ldg(q_w + o * 256 + t);
        g_Ap[((t >> 2) * 256 + i) * 4 + (t & 3)] = acc;
        float part = s_buf[t] * q_b[t];
#pragma unroll
        for (int off = 16; off; off >>= 1) part += __shfl_down_sync(0xffffffffu, part, off);
        if ((t & 31) == 0) s_red[t >> 5] = part;
        __syncthreads();
        if (t == 0) { float s = 0.f; for (int w = 0; w < 8; w++) s += s_red[w]; g_cvec[i] = s; }
        return;
    }
    if (blk < 728) {
        // global-feature MLP: 512 -> 256 relu -> 128
        int b = blk - 720;
        for (int i = t; i < 512; i += 256) s_buf[i] = gf[b * 512 + i];
        __syncthreads();
        float a = cf_b1[t];
        const float* wr = cf_w1 + t * 512;
        for (int c = 0; c < 512; c++) a += wr[c] * s_buf[c];
        s_h[t] = fmaxf(a, 0.f);
        __syncthreads();
        if (t < 128) {
            float a2 = cf_b2[t];
            const float* w2r = cf_w2 + t * 256;
            for (int c = 0; c < 256; c++) a2 += w2r[c] * s_h[c];
            g_gvec[b * 128 + t] = a2;
        }
        return;
    }
    // blk == 728: vb[j] = sum_o qw[o][j]*bk[o] ; s0 = bq.bk
    {
        float acc = 0.f;
        for (int o = 0; o < 256; o++) acc += __ldg(q_w + o * 256 + t) * k_b[o];
        g_vb[t] = acc;
        if (t == 0) {
            float s = 0.f;
            for (int o = 0; o < 256; o++) s += q_b[o] * k_b[o];
            g_s0[0] = s;
        }
    }
}

// ---------------- fused c1 + cs MLP (packed f32x2 FMA) --------------------
// 32 points per block. Transposed (channel-major) smem, stride FS.
__global__ void __launch_bounds__(256) k_feat(const float* __restrict__ x,
                                              const float* __restrict__ c1w1,
                                              const float* __restrict__ c1b1,
                                              const float* __restrict__ c1b2,
                                              const float* __restrict__ csb1,
                                              const float* __restrict__ csb2) {
    extern __shared__ __align__(16) float fm[];
    float* s_int = fm;                 // [256][FS]  inputs to cs (f1 | gvec)
    float* s_ht  = fm + 256 * FS;      // [256][FS]  cs hidden (also aliases c1 hidden rows 0..63)
    float* s_h64 = s_ht;               // alias [64][FS]
    float* s_xyz = fm + 512 * FS;      // 96
    int t = threadIdx.x;
    int base = blockIdx.x * 32;
    int b = base >> 13;
    if (t < 96) s_xyz[t] = x[(size_t)base * 3 + t];
    __syncthreads();
    // c1 layer1: 3 -> 64, relu (transposed write)
    for (int i = 0; i < 8; i++) {
        int task = t + 256 * i;
        int p = task & 31, o = task >> 5;
        float a = c1b1[o];
        a += c1w1[o * 3 + 0] * s_xyz[p * 3 + 0];
        a += c1w1[o * 3 + 1] * s_xyz[p * 3 + 1];
        a += c1w1[o * 3 + 2] * s_xyz[p * 3 + 2];
        s_h64[o * FS + p] = fmaxf(a, 0.f);
    }
    __syncthreads();
    // c1 layer2: 64 -> 128 -> s_int rows 0..127
    {
        int o = t & 127, half = t >> 7;
        ull acc[8];
#pragma unroll
        for (int pp = 0; pp < 8; pp++) acc[pp] = 0ull;
        const float4* wp = (const float4*)g_c1w2p;
        for (int c4 = 0; c4 < 16; c4++) {
            float4 w = wp[c4 * 128 + o];
            ull ww[4] = { f2pk(w.x, w.x), f2pk(w.y, w.y), f2pk(w.z, w.z), f2pk(w.w, w.w) };
#pragma unroll
            for (int c = 0; c < 4; c++) {
                const ulonglong2* vp = (const ulonglong2*)(s_h64 + (c4 * 4 + c) * FS + half * 16);
#pragma unroll
                for (int g = 0; g < 4; g++) {
                    ulonglong2 v = vp[g];
                    acc[g * 2]     = fma2(ww[c], v.x, acc[g * 2]);
                    acc[g * 2 + 1] = fma2(ww[c], v.y, acc[g * 2 + 1]);
                }
            }
        }
        ull bb = f2pk(c1b2[o], c1b2[o]);
#pragma unroll
        for (int pp = 0; pp < 8; pp++)
            *(ull*)(s_int + o * FS + half * 16 + pp * 2) = addx2(acc[pp], bb);
    }
    // gvec rows 128..255 (broadcast per channel)
    for (int i = t; i < 128 * 32; i += 256) {
        int c = i >> 5, p = i & 31;
        s_int[(128 + c) * FS + p] = __ldg(&g_gvec[b * 128 + c]);
    }
    __syncthreads();
    // cs layer1: 256 -> 256, relu
    {
        ull acc[16];
#pragma unroll
        for (int pp = 0; pp < 16; pp++) acc[pp] = 0ull;
        const float4* wp = (const float4*)g_csw1p;
        for (int c4 = 0; c4 < 64; c4++) {
            float4 w = wp[c4 * 256 + t];
            ull ww[4] = { f2pk(w.x, w.x), f2pk(w.y, w.y), f2pk(w.z, w.z), f2pk(w.w, w.w) };
#pragma unroll
            for (int c = 0; c < 4; c++) {
                const ulonglong2* vp = (const ulonglong2*)(s_int + (c4 * 4 + c) * FS);
#pragma unroll
                for (int g = 0; g < 8; g++) {
                    ulonglong2 v = vp[g];
                    acc[g * 2]     = fma2(ww[c], v.x, acc[g * 2]);
                    acc[g * 2 + 1] = fma2(ww[c], v.y, acc[g * 2 + 1]);
                }
            }
        }
        float bo = csb1[t];
#pragma unroll
        for (int pp = 0; pp < 16; pp++) {
            float lo, hi; f2up(acc[pp], lo, hi);
            lo = fmaxf(lo + bo, 0.f); hi = fmaxf(hi + bo, 0.f);
            *(ull*)(s_ht + t * FS + pp * 2) = f2pk(lo, hi);
        }
    }
    __syncthreads();
    // cs layer2: 256 -> 128 -> g_f2 (point-major)
    {
        int o = t & 127, half = t >> 7;
        ull acc[8];
#pragma unroll
        for (int pp = 0; pp < 8; pp++) acc[pp] = 0ull;
        const float4* wp = (const float4*)g_csw2p;
        for (int c4 = 0; c4 < 64; c4++) {
            float4 w = wp[c4 * 128 + o];
            ull ww[4] = { f2pk(w.x, w.x), f2pk(w.y, w.y), f2pk(w.z, w.z), f2pk(w.w, w.w) };
#pragma unroll
            for (int c = 0; c < 4; c++) {
                const ulonglong2* vp = (const ulonglong2*)(s_ht + (c4 * 4 + c) * FS + half * 16);
#pragma unroll
                for (int g = 0; g < 4; g++) {
                    ulonglong2 v = vp[g];
                    acc[g * 2]     = fma2(ww[c], v.x, acc[g * 2]);
                    acc[g * 2 + 1] = fma2(ww[c], v.y, acc[g * 2 + 1]);
                }
            }
        }
        float bo = csb2[o];
#pragma unroll
        for (int pp = 0; pp < 8; pp++) {
            float lo, hi; f2up(acc[pp], lo, hi);
            int p0 = base + half * 16 + pp * 2;
            g_f2[(size_t)p0 * 128 + o]       = lo + bo;
            g_f2[(size_t)(p0 + 1) * 128 + o] = hi + bo;
        }
    }
}

// ---------------- FPS (bit-exact; REDUX value+index reduction) ------------
__global__ void __launch_bounds__(1024, 1) k_fps(const float* __restrict__ x,
                                                 float* __restrict__ out_down) {
    extern __shared__ float sx[];     // NP*3
    __shared__ unsigned s_bv[32];
    __shared__ unsigned s_bi[32];
    int b = blockIdx.x, t = threadIdx.x, lane = t & 31, wid = t >> 5;
    const float* xb = x + (size_t)b * NP * 3;
    for (int i = t; i < NP * 3; i += 1024) sx[i] = xb[i];
    __syncthreads();
    float cx = sx[0], cy = sx[1], cz = sx[2];
    if (t == 0) {
        int o3 = b * MP * 3;
        g_down[o3 + 0] = cx; g_down[o3 + 1] = cy; g_down[o3 + 2] = cz;
        out_down[o3 + 0] = cx; out_down[o3 + 1] = cy; out_down[o3 + 2] = cz;
    }
    ull pxp[4], pyp[4], pzp[4];
    float md[8];
    int base = t * 8;
#pragma unroll
    for (int j = 0; j < 4; j++) {
        int n = base + 2 * j;
        pxp[j] = f2pk(sx[n * 3 + 0], sx[n * 3 + 3]);
        pyp[j] = f2pk(sx[n * 3 + 1], sx[n * 3 + 4]);
        pzp[j] = f2pk(sx[n * 3 + 2], sx[n * 3 + 5]);
        md[2 * j] = 1e10f; md[2 * j + 1] = 1e10f;
    }
    for (int it = 1; it < MP; it++) {
        ull ncx = f2pk(-cx, -cx), ncy = f2pk(-cy, -cy), ncz = f2pk(-cz, -cz);
#pragma unroll
        for (int j = 0; j < 4; j++) {
            ull dx = addx2(pxp[j], ncx);
            ull dy = addx2(pyp[j], ncy);
            ull dz = addx2(pzp[j], ncz);
            ull s = addx2(addx2(mulx2(dx, dx), mulx2(dy, dy)), mulx2(dz, dz));
            float lo, hi; f2up(s, lo, hi);
            md[2 * j]     = fminf(md[2 * j], lo);
            md[2 * j + 1] = fminf(md[2 * j + 1], hi);
        }
        // value max (distances are >= 0: float bits monotone as uint)
        float m01 = fmaxf(md[0], md[1]), m23 = fmaxf(md[2], md[3]);
        float m45 = fmaxf(md[4], md[5]), m67 = fmaxf(md[6], md[7]);
        float m = fmaxf(fmaxf(m01, m23), fmaxf(m45, m67));
        unsigned wm = __reduce_max_sync(0xffffffffu, __float_as_uint(m));
        if (lane == 0) s_bv[wid] = wm;
        __syncthreads();
        unsigned gm = __reduce_max_sync(0xffffffffu, s_bv[lane]);
        // index recovery: first (min) index whose value bit-equals gm
        unsigned li = 0xffffffffu;
#pragma unroll
        for (int j = 7; j >= 0; j--)
            li = (__float_as_uint(md[j]) == gm) ? (unsigned)(base + j) : li;
        unsigned wi = __reduce_min_sync(0xffffffffu, li);
        if (lane == 0) s_bi[wid] = wi;
        __syncthreads();
        unsigned gi = __reduce_min_sync(0xffffffffu, s_bi[lane]);
        cx = sx[gi * 3]; cy = sx[gi * 3 + 1]; cz = sx[gi * 3 + 2];
        if (t == 0) {
            int o3 = (b * MP + it) * 3;
            g_down[o3 + 0] = cx; g_down[o3 + 1] = cy; g_down[o3 + 2] = cz;
            out_down[o3 + 0] = cx; out_down[o3 + 1] = cy; out_down[o3 + 2] = cz;
        }
    }
}

// ---------------- KNN top-17 (stable, JAX d2 formula) ---------------------
__global__ void __launch_bounds__(64) k_knn(const float* __restrict__ x) {
    extern __shared__ float skx[];
    int gid = blockIdx.x * 64 + threadIdx.x;
    int b = gid >> 10;
    const float* xb = x + (size_t)b * NP * 3;
    for (int i = threadIdx.x; i < NP * 3; i += 64) skx[i] = xb[i];
    __syncthreads();
    float qx = g_down[gid * 3 + 0], qy = g_down[gid * 3 + 1], qz = g_down[gid * 3 + 2];
    float sd = __fadd_rn(__fadd_rn(__fmul_rn(qx, qx), __fmul_rn(qy, qy)), __fmul_rn(qz, qz));
    float dist[17]; int ind[17];
#pragma unroll
    for (int i = 0; i < 17; i++) { dist[i] = 3.4e38f; ind[i] = 0; }
    for (int n = 0; n < NP; n++) {
        float ax = skx[n * 3 + 0], ay = skx[n * 3 + 1], az = skx[n * 3 + 2];
        float sn = __fadd_rn(__fadd_rn(__fmul_rn(ax, ax), __fmul_rn(ay, ay)), __fmul_rn(az, az));
        float dt = __fadd_rn(__fadd_rn(__fmul_rn(qx, ax), __fmul_rn(qy, ay)), __fmul_rn(qz, az));
        float d2 = __fsub_rn(__fadd_rn(sd, sn), __fmul_rn(2.f, dt));
        if (d2 < dist[16]) {
            int pos = 0;
#pragma unroll
            for (int s = 0; s < 17; s++) pos += (dist[s] <= d2) ? 1 : 0;
#pragma unroll
            for (int s = 16; s > 0; s--) {
                if (s > pos) { dist[s] = dist[s - 1]; ind[s] = ind[s - 1]; }
                else if (s == pos) { dist[s] = d2; ind[s] = n; }
            }
            if (pos == 0) { dist[0] = d2; ind[0] = n; }
        }
    }
#pragma unroll
    for (int s = 0; s < 17; s++) g_knn[(size_t)gid * 17 + s] = ind[s];
}

// ---------------- grouped convs + attention (G=2 m's per block) -----------
// logit_mj = u_m . f_j + vb . f_m0 + s0, with u_m = A f_m0 + c
// smem floats: feat[0..8704) h1[8704..10880) h2[10880..13056)
//              us alias [8704..9216)
//              knnx[13056..13158) dwn[13158..13164) lg[13164..13198) sidx[13200..13234)
__global__ void __launch_bounds__(256) k_attn(
    const float* __restrict__ x,
    const float* __restrict__ w1, const float* __restrict__ b1,
    const float* __restrict__ gg1, const float* __restrict__ bb1,
    const float* __restrict__ b2, const float* __restrict__ gg2, const float* __restrict__ bb2,
    const float* __restrict__ b3,
    float* __restrict__ out_new)
{
    extern __shared__ __align__(16) float sm[];
    float* feat = sm;
    float* h1   = sm + 8704;
    float* us   = sm + 8704;       // alias (h1 dead)
    float* h2   = sm + 10880;
    float* knnx = sm + 13056;
    float* dwn  = sm + 13158;
    float* lg   = sm + 13164;
    int*   sidx = (int*)(sm + 13200);

    int t = threadIdx.x;
    int wid = t >> 5, lane = t & 31;
    int bm0 = blockIdx.x * 2;
    int b = bm0 >> 10;
    const float* xb = x + (size_t)b * NP * 3;

    if (t < 34) {
        int id = g_knn[(size_t)bm0 * 17 + t];
        sidx[t] = id;
        knnx[t * 3 + 0] = xb[id * 3 + 0];
        knnx[t * 3 + 1] = xb[id * 3 + 1];
        knnx[t * 3 + 2] = xb[id * 3 + 2];
    }
    if (t < 6) dwn[t] = g_down[(size_t)bm0 * 3 + t];
    __syncthreads();

    // gather knn_f -> feat[:,0..127]   (one LDG.128 + STS.128 per lane per row)
    for (int r = wid; r < 34; r += 8) {
        const float4* src = (const float4*)(g_f2 + ((size_t)(b * NP) + sidx[r]) * 128);
        ((float4*)(feat + r * 256))[lane] = src[lane];
    }

    const float bnc = 1.f / sqrtf(1.0f + 1e-5f);

    // h1: 9 -> 64, bn, leaky
    for (int i = 0; i < 9; i++) {
        int task = t + 256 * i;
        if (task < 2176) {
            int o = task & 63, row = task >> 6;
            int mi = (row >= 17) ? 1 : 0;
            const float* kp = knnx + row * 3;
            const float* dp = dwn + mi * 3;
            float r0 = dp[0], r1 = dp[1], r2v = dp[2];
            float r3 = kp[0], r4 = kp[1], r5 = kp[2];
            const float* w = w1 + o * 9;
            float a = b1[o];
            a += w[0] * r0 + w[1] * r1 + w[2] * r2v;
            a += w[3] * r3 + w[4] * r4 + w[5] * r5;
            a += w[6] * (r0 - r3) + w[7] * (r1 - r4) + w[8] * (r2v - r5);
            a = a * (gg1[o] * bnc) + bb1[o];
            a = a > 0.f ? a : 0.01f * a;
            h1[row * 64 + o] = a;
        }
    }
    __syncthreads();
    // h2: 64 -> 64, bn, leaky
    {
        const float4* wp = (const float4*)g_s2w2p;
        for (int i = 0; i < 9; i++) {
            int task = t + 256 * i;
            if (task < 2176) {
                int o = task & 63, row = task >> 6;
                const float4* hr = (const float4*)(h1 + row * 64);
                float a = b2[o];
#pragma unroll
                for (int c4 = 0; c4 < 16; c4++) {
                    float4 w = wp[c4 * 64 + o];
                    float4 v = hr[c4];
                    a += w.x * v.x + w.y * v.y + w.z * v.z + w.w * v.w;
                }
                a = a * (gg2[o] * bnc) + bb2[o];
                a = a > 0.f ? a : 0.01f * a;
                h2[row * 64 + o] = a;
            }
        }
    }
    __syncthreads();
    // r2: 64 -> 128 -> feat[:,128..255]   (4352 tasks = 17*256 exactly)
    {
        const float4* wp = (const float4*)g_s2w3p;
        for (int i = 0; i < 17; i++) {
            int task = t + 256 * i;
            int o = task & 127, row = task >> 7;
            const float4* hr = (const float4*)(h2 + row * 64);
            float a = b3[o];
#pragma unroll
            for (int c4 = 0; c4 < 16; c4++) {
                float4 w = wp[c4 * 128 + o];
                float4 v = hr[c4];
                a += w.x * v.x + w.y * v.y + w.z * v.z + w.w * v.w;
            }
            feat[row * 256 + 128 + o] = a;
        }
    }
    __syncthreads();

    // u_m = A f_m0 + c   (thread t = output channel)
    {
        const float4* ap = (const float4*)g_Ap;
        float a0 = 0.f, a1 = 0.f;
        for (int c4 = 0; c4 < 64; c4++) {
            float4 w = ap[c4 * 256 + t];
            float4 v0 = *(const float4*)(feat + c4 * 4);              // row 0
            float4 v1 = *(const float4*)(feat + 17 * 256 + c4 * 4);   // row 17
            a0 += w.x * v0.x + w.y * v0.y + w.z * v0.z + w.w * v0.w;
            a1 += w.x * v1.x + w.y * v1.y + w.z * v1.z + w.w * v1.w;
        }
        float cv = g_cvec[t];
        us[t] = a0 + cv;
        us[256 + t] = a1 + cv;
    }
    __syncthreads();

    // logits: tasks 0..31 = u_m . f_j ; tasks 32..33 = vb . f_m0
    for (int task = wid; task < 34; task += 8) {
        float s = 0.f;
        if (task < 32) {
            int mi = task >> 4, j = task & 15;
            const float* uf = us + mi * 256;
            const float* fr = feat + (mi * 17 + 1 + j) * 256;
#pragma unroll
            for (int s8 = 0; s8 < 8; s8++) { int o = lane + 32 * s8; s += uf[o] * fr[o]; }
        } else {
            int mi = task - 32;
            const float* fr = feat + mi * 17 * 256;
#pragma unroll
            for (int s8 = 0; s8 < 8; s8++) { int o = lane + 32 * s8; s += __ldg(&g_vb[o]) * fr[o]; }
        }
#pragma unroll
        for (int off = 16; off; off >>= 1) s += __shfl_down_sync(0xffffffffu, s, off);
        if (lane == 0) lg[task] = s;
    }
    __syncthreads();

    // softmax + weighted neighbor sum
    if (t < 2) {
        float ex = lg[32 + t] + g_s0[0];
        float l[16], mx = -3.4e38f;
#pragma unroll
        for (int j = 0; j < 16; j++) { l[j] = lg[t * 16 + j] + ex; mx = fmaxf(mx, l[j]); }
        float sum = 0.f;
#pragma unroll
        for (int j = 0; j < 16; j++) { l[j] = expf(l[j] - mx); sum += l[j]; }
        float inv = 1.f / sum;
        float nx = 0.f, ny = 0.f, nz = 0.f;
#pragma unroll
        for (int j = 0; j < 16; j++) {
            float w = l[j] * inv;
            const float* kp = knnx + (t * 17 + 1 + j) * 3;
            nx += w * kp[0]; ny += w * kp[1]; nz += w * kp[2];
        }
        float* po = out_new + (size_t)(bm0 + t) * 3;
        po[0] = nx; po[1] = ny; po[2] = nz;
    }
}

// ---------------- launch ---------------------------------------------------
extern "C" void kernel_launch(void* const* d_in, const int* in_sizes, int n_in,
                              void* d_out, int out_size) {
    const float* x      = (const float*)d_in[0];
    const float* gf     = (const float*)d_in[1];
    const float* c1_w1  = (const float*)d_in[2];
    const float* c1_b1  = (const float*)d_in[3];
    const float* c1_w2  = (const float*)d_in[4];
    const float* c1_b2  = (const float*)d_in[5];
    const float* cf_w1  = (const float*)d_in[6];
    const float* cf_b1  = (const float*)d_in[7];
    const float* cf_w2  = (const float*)d_in[8];
    const float* cf_b2  = (const float*)d_in[9];
    const float* cs_w1  = (const float*)d_in[10];
    const float* cs_b1  = (const float*)d_in[11];
    const float* cs_w2  = (const float*)d_in[12];
    const float* cs_b2  = (const float*)d_in[13];
    const float* s2_w1  = (const float*)d_in[14];
    const float* s2_b1  = (const float*)d_in[15];
    const float* s2_g1  = (const float*)d_in[16];
    const float* s2_bb1 = (const float*)d_in[17];
    const float* s2_w2  = (const float*)d_in[18];
    const float* s2_b2  = (const float*)d_in[19];
    const float* s2_g2  = (const float*)d_in[20];
    const float* s2_bb2 = (const float*)d_in[21];
    const float* s2_w3  = (const float*)d_in[22];
    const float* s2_b3  = (const float*)d_in[23];
    const float* q_w    = (const float*)d_in[24];
    const float* q_b    = (const float*)d_in[25];
    const float* k_w    = (const float*)d_in[26];
    const float* k_b    = (const float*)d_in[27];
    float* out = (float*)d_out;

    static bool s_init = false;
    static cudaStream_t st;
    static cudaEvent_t evF, evD;
    if (!s_init) {
        cudaStreamCreateWithFlags(&st, cudaStreamNonBlocking);
        cudaEventCreateWithFlags(&evF, cudaEventDisableTiming);
        cudaEventCreateWithFlags(&evD, cudaEventDisableTiming);
        cudaFuncSetAttribute(k_feat, cudaFuncAttributeMaxDynamicSharedMemorySize, (512 * FS + 96) * 4);
        cudaFuncSetAttribute(k_knn,  cudaFuncAttributeMaxDynamicSharedMemorySize, NP * 3 * 4);
        cudaFuncSetAttribute(k_fps,  cudaFuncAttributeMaxDynamicSharedMemorySize, NP * 3 * 4);
        cudaFuncSetAttribute(k_attn, cudaFuncAttributeMaxDynamicSharedMemorySize, 13236 * 4);
        s_init = true;
    }

    // fork for the geometric chain
    cudaEventRecord(evF, 0);
    cudaStreamWaitEvent(st, evF, 0);
    k_fps<<<BN, 1024, NP * 3 * 4, st>>>(x, out);                      // #1
    k_knn<<<(BN * MP) / 64, 64, NP * 3 * 4, st>>>(x);                 // #2
    cudaEventRecord(evD, st);

    // main stream
    k_prep<<<729, 256>>>(cs_w1, cs_w2, s2_w2, s2_w3, c1_w2,           // #3
                         q_w, k_w, q_b, k_b,
                         gf, cf_w1, cf_b1, cf_w2, cf_b2);
    k_feat<<<(BN * NP) / 32, 256, (512 * FS + 96) * 4>>>(x,           // #4 <- profiled
        c1_w1, c1_b1, c1_b2, cs_b1, cs_b2);

    cudaStreamWaitEvent(0, evD, 0);
    k_attn<<<(BN * MP) / 2, 256, 13236 * 4>>>(x,                      // #5
        s2_w1, s2_b1, s2_g1, s2_bb1,
        s2_b2, s2_g2, s2_bb2,
        s2_b3,
        out + (size_t)BN * MP * 3);
}

// round 6
// speedup vs baseline: 7.1556x; 1.0674x over previous
#include <cuda_runtime.h>
#include <math.h>

#define BN 8
#define NP 8192
#define MP 1024
#define KNB 17
#define FS 36   // transposed-row stride (floats), 16B-aligned

typedef unsigned long long ull;

// ---------------- scratch (device globals; no allocation) ----------------
__device__ float g_gvec[BN * 128];
__device__ float g_f2[BN * NP * 128];
__device__ float g_down[BN * MP * 3];
__device__ int   g_knn[BN * MP * KNB];
// dup-packed weights for feat: D[c*O + o] = (w[o][c], w[o][c]) as ull
__device__ ull   g_csw1d[256 * 256];
__device__ ull   g_csw2d[256 * 128];
__device__ ull   g_c1w2d[64 * 128];
// packed (4c x o x 4) weights for attn convs (s2w2 prefolded with bn)
__device__ float g_s2w2p[64 * 64];
__device__ float g_s2w3p[128 * 64];
// prefolded h1 weights/biases
__device__ float g_w1f[64 * 9];
__device__ float g_b1f[64];
__device__ float g_b2f[64];
// fused attention mats: A = Wk^T Wq (packed), c = Wk^T bq, vb = Wq^T bk, s0 = bq.bk
__device__ float g_Ap[256 * 256];
__device__ float g_cvec[256];
__device__ float g_vb[256];
__device__ float g_s0[1];

__device__ __forceinline__ ull f2pk(float lo, float hi) {
    ull r; asm("mov.b64 %0,{%1,%2};" : "=l"(r) : "f"(lo), "f"(hi)); return r;
}
__device__ __forceinline__ void f2up(ull v, float& lo, float& hi) {
    asm("mov.b64 {%0,%1},%2;" : "=f"(lo), "=f"(hi) : "l"(v));
}
__device__ __forceinline__ ull addx2(ull a, ull b) {
    ull r; asm("add.rn.f32x2 %0,%1,%2;" : "=l"(r) : "l"(a), "l"(b)); return r;
}
__device__ __forceinline__ ull mulx2(ull a, ull b) {
    ull r; asm("mul.rn.f32x2 %0,%1,%2;" : "=l"(r) : "l"(a), "l"(b)); return r;
}
__device__ __forceinline__ ull fma2(ull a, ull b, ull c) {
    ull r; asm("fma.rn.f32x2 %0,%1,%2,%3;" : "=l"(r) : "l"(a), "l"(b), "l"(c)); return r;
}

// ---------------- prep ----------------------------------------------------
__device__ __forceinline__ void rp_dup(const float* __restrict__ w, ull* __restrict__ o,
                                       int O, int C, int blk) {
    int g = blk * 256 + threadIdx.x;
    if (g >= O * C) return;
    int c = g / O, oo = g - c * O;
    float v = w[oo * C + c];
    o[c * O + oo] = f2pk(v, v);
}

__global__ void k_prep(const float* __restrict__ cs_w1, const float* __restrict__ cs_w2,
                       const float* __restrict__ c1_w2,
                       const float* __restrict__ s2_w1, const float* __restrict__ s2_b1,
                       const float* __restrict__ s2_g1, const float* __restrict__ s2_bb1,
                       const float* __restrict__ s2_w2, const float* __restrict__ s2_b2,
                       const float* __restrict__ s2_g2, const float* __restrict__ s2_bb2,
                       const float* __restrict__ s2_w3,
                       const float* __restrict__ q_w, const float* __restrict__ k_w,
                       const float* __restrict__ q_b, const float* __restrict__ k_b,
                       const float* __restrict__ gf,
                       const float* __restrict__ cf_w1, const float* __restrict__ cf_b1,
                       const float* __restrict__ cf_w2, const float* __restrict__ cf_b2) {
    __shared__ float s_buf[512];
    __shared__ float s_h[256];
    __shared__ float s_red[8];
    const float bnc = 1.f / sqrtf(1.0f + 1e-5f);
    int blk = blockIdx.x, t = threadIdx.x;
    if (blk < 256)  { rp_dup(cs_w1, g_csw1d, 256, 256, blk); return; }
    if (blk < 384)  { rp_dup(cs_w2, g_csw2d, 128, 256, blk - 256); return; }
    if (blk < 416)  { rp_dup(c1_w2, g_c1w2d, 128, 64, blk - 384); return; }
    if (blk < 432) {
        int g = (blk - 416) * 256 + t;   // 4096 = 64x64, prefold bn
        int o = g >> 6, c = g & 63;
        g_s2w2p[((c >> 2) * 64 + o) * 4 + (c & 3)] = s2_w2[o * 64 + c] * (s2_g2[o] * bnc);
        return;
    }
    if (blk < 464) {
        int g = (blk - 432) * 256 + t;   // 8192 = 128x64
        int o = g >> 6, c = g & 63;
        g_s2w3p[((c >> 2) * 128 + o) * 4 + (c & 3)] = s2_w3[o * 64 + c];
        return;
    }
    if (blk < 720) {
        // row i of A = Wk^T Wq, plus c[i]
        int i = blk - 464;
        s_buf[t] = k_w[t * 256 + i];
        __syncthreads();
        float acc = 0.f;
        for (int o = 0; o < 256; o++) acc += s_buf[o] * __ldg(q_w + o * 256 + t);
        g_Ap[((t >> 2) * 256 + i) * 4 + (t & 3)] = acc;
        float part = s_buf[t] * q_b[t];
#pragma unroll
        for (int off = 16; off; off >>= 1) part += __shfl_down_sync(0xffffffffu, part, off);
        if ((t & 31) == 0) s_red[t >> 5] = part;
        __syncthreads();
        if (t == 0) { float s = 0.f; for (int w = 0; w < 8; w++) s += s_red[w]; g_cvec[i] = s; }
        return;
    }
    if (blk < 728) {
        // global-feature MLP: 512 -> 256 relu -> 128
        int b = blk - 720;
        for (int i = t; i < 512; i += 256) s_buf[i] = gf[b * 512 + i];
        __syncthreads();
        float a = cf_b1[t];
        const float* wr = cf_w1 + t * 512;
        for (int c = 0; c < 512; c++) a += wr[c] * s_buf[c];
        s_h[t] = fmaxf(a, 0.f);
        __syncthreads();
        if (t < 128) {
            float a2 = cf_b2[t];
            const float* w2r = cf_w2 + t * 256;
            for (int c = 0; c < 256; c++) a2 += w2r[c] * s_h[c];
            g_gvec[b * 128 + t] = a2;
        }
        return;
    }
    if (blk == 728) {
        float acc = 0.f;
        for (int o = 0; o < 256; o++) acc += __ldg(q_w + o * 256 + t) * k_b[o];
        g_vb[t] = acc;
        if (t == 0) {
            float s = 0.f;
            for (int o = 0; o < 256; o++) s += q_b[o] * k_b[o];
            g_s0[0] = s;
        }
        return;
    }
    // blk == 729: h1 prefold
    for (int i = t; i < 576; i += 256) {
        int o = i / 9;
        g_w1f[i] = s2_w1[i] * (s2_g1[o] * bnc);
    }
    if (t < 64) {
        g_b1f[t] = s2_b1[t] * (s2_g1[t] * bnc) + s2_bb1[t];
        g_b2f[t] = s2_b2[t] * (s2_g2[t] * bnc) + s2_bb2[t];
    }
}

// ---------------- fused c1 + cs MLP (register-blocked f32x2) --------------
// 32 points per block; transposed channel-major smem [C][FS].
__global__ void __launch_bounds__(256) k_feat(const float* __restrict__ x,
                                              const float* __restrict__ c1w1,
                                              const float* __restrict__ c1b1,
                                              const float* __restrict__ c1b2,
                                              const float* __restrict__ csb1,
                                              const float* __restrict__ csb2) {
    extern __shared__ __align__(16) float fm[];
    float* s_int = fm;                 // [256][FS]
    float* s_ht  = fm + 256 * FS;      // [256][FS] (rows 0..63 alias c1 hidden)
    float* s_h64 = s_ht;
    float* s_xyz = fm + 512 * FS;
    int t = threadIdx.x;
    int base = blockIdx.x * 32;
    int b = base >> 13;
    if (t < 96) s_xyz[t] = x[(size_t)base * 3 + t];
    __syncthreads();
    // c1 layer1: 3 -> 64, relu
    for (int i = 0; i < 8; i++) {
        int task = t + 256 * i;
        int p = task & 31, o = task >> 5;
        float a = c1b1[o];
        a += c1w1[o * 3 + 0] * s_xyz[p * 3 + 0];
        a += c1w1[o * 3 + 1] * s_xyz[p * 3 + 1];
        a += c1w1[o * 3 + 2] * s_xyz[p * 3 + 2];
        s_h64[o * FS + p] = fmaxf(a, 0.f);
    }
    __syncthreads();
    // c1 layer2: 64 -> 128 -> s_int rows 0..127   (tile 4 outs x 4 pts)
    {
        int o0 = (t & 31) * 4, pg = t >> 5;
        ull acc[8];
#pragma unroll
        for (int i = 0; i < 8; i++) acc[i] = 0ull;
#pragma unroll 4
        for (int c = 0; c < 64; c++) {
            ulonglong2 w01 = *(const ulonglong2*)(g_c1w2d + c * 128 + o0);
            ulonglong2 w23 = *(const ulonglong2*)(g_c1w2d + c * 128 + o0 + 2);
            ulonglong2 v = *(const ulonglong2*)(s_h64 + c * FS + pg * 4);
            acc[0] = fma2(w01.x, v.x, acc[0]); acc[1] = fma2(w01.x, v.y, acc[1]);
            acc[2] = fma2(w01.y, v.x, acc[2]); acc[3] = fma2(w01.y, v.y, acc[3]);
            acc[4] = fma2(w23.x, v.x, acc[4]); acc[5] = fma2(w23.x, v.y, acc[5]);
            acc[6] = fma2(w23.y, v.x, acc[6]); acc[7] = fma2(w23.y, v.y, acc[7]);
        }
        float4 bq = *(const float4*)(c1b2 + o0);
        float bb[4] = { bq.x, bq.y, bq.z, bq.w };
        __syncthreads();   // all s_h64 reads done before s_int writes overlap?? (s_int distinct region) - ordering vs next phase reads
#pragma unroll
        for (int oi = 0; oi < 4; oi++) {
            ull bp = f2pk(bb[oi], bb[oi]);
            *(ull*)(s_int + (o0 + oi) * FS + pg * 4)     = addx2(acc[oi * 2], bp);
            *(ull*)(s_int + (o0 + oi) * FS + pg * 4 + 2) = addx2(acc[oi * 2 + 1], bp);
        }
    }
    // gvec rows 128..255
    for (int i = t; i < 128 * 32; i += 256) {
        int c = i >> 5, p = i & 31;
        s_int[(128 + c) * FS + p] = __ldg(&g_gvec[b * 128 + c]);
    }
    __syncthreads();
    // cs layer1: 256 -> 256, relu   (tile 4 outs x 8 pts)
    {
        int o0 = (t & 63) * 4, pg = t >> 6;
        ull acc[16];
#pragma unroll
        for (int i = 0; i < 16; i++) acc[i] = 0ull;
#pragma unroll 2
        for (int c = 0; c < 256; c++) {
            ulonglong2 w01 = *(const ulonglong2*)(g_csw1d + c * 256 + o0);
            ulonglong2 w23 = *(const ulonglong2*)(g_csw1d + c * 256 + o0 + 2);
            ulonglong2 v01 = *(const ulonglong2*)(s_int + c * FS + pg * 8);
            ulonglong2 v23 = *(const ulonglong2*)(s_int + c * FS + pg * 8 + 4);
            acc[0]  = fma2(w01.x, v01.x, acc[0]);  acc[1]  = fma2(w01.x, v01.y, acc[1]);
            acc[2]  = fma2(w01.x, v23.x, acc[2]);  acc[3]  = fma2(w01.x, v23.y, acc[3]);
            acc[4]  = fma2(w01.y, v01.x, acc[4]);  acc[5]  = fma2(w01.y, v01.y, acc[5]);
            acc[6]  = fma2(w01.y, v23.x, acc[6]);  acc[7]  = fma2(w01.y, v23.y, acc[7]);
            acc[8]  = fma2(w23.x, v01.x, acc[8]);  acc[9]  = fma2(w23.x, v01.y, acc[9]);
            acc[10] = fma2(w23.x, v23.x, acc[10]); acc[11] = fma2(w23.x, v23.y, acc[11]);
            acc[12] = fma2(w23.y, v01.x, acc[12]); acc[13] = fma2(w23.y, v01.y, acc[13]);
            acc[14] = fma2(w23.y, v23.x, acc[14]); acc[15] = fma2(w23.y, v23.y, acc[15]);
        }
        float4 bq = *(const float4*)(csb1 + o0);
        float bb[4] = { bq.x, bq.y, bq.z, bq.w };
        __syncthreads();
#pragma unroll
        for (int oi = 0; oi < 4; oi++) {
#pragma unroll
            for (int g = 0; g < 4; g++) {
                float lo, hi; f2up(acc[oi * 4 + g], lo, hi);
                lo = fmaxf(lo + bb[oi], 0.f); hi = fmaxf(hi + bb[oi], 0.f);
                *(ull*)(s_ht + (o0 + oi) * FS + pg * 8 + g * 2) = f2pk(lo, hi);
            }
        }
    }
    __syncthreads();
    // cs layer2: 256 -> 128 -> g_f2 point-major   (tile 4 outs x 4 pts)
    {
        int o0 = (t & 31) * 4, pg = t >> 5;
        ull acc[8];
#pragma unroll
        for (int i = 0; i < 8; i++) acc[i] = 0ull;
#pragma unroll 2
        for (int c = 0; c < 256; c++) {
            ulonglong2 w01 = *(const ulonglong2*)(g_csw2d + c * 128 + o0);
            ulonglong2 w23 = *(const ulonglong2*)(g_csw2d + c * 128 + o0 + 2);
            ulonglong2 v = *(const ulonglong2*)(s_ht + c * FS + pg * 4);
            acc[0] = fma2(w01.x, v.x, acc[0]); acc[1] = fma2(w01.x, v.y, acc[1]);
            acc[2] = fma2(w01.y, v.x, acc[2]); acc[3] = fma2(w01.y, v.y, acc[3]);
            acc[4] = fma2(w23.x, v.x, acc[4]); acc[5] = fma2(w23.x, v.y, acc[5]);
            acc[6] = fma2(w23.y, v.x, acc[6]); acc[7] = fma2(w23.y, v.y, acc[7]);
        }
        float4 bq = *(const float4*)(csb2 + o0);
        float bb[4] = { bq.x, bq.y, bq.z, bq.w };
#pragma unroll
        for (int pp = 0; pp < 4; pp++) {
            float4 val;
            float lo, hi;
            f2up(acc[0 + (pp >> 1)], lo, hi); val.x = ((pp & 1) ? hi : lo) + bb[0];
            f2up(acc[2 + (pp >> 1)], lo, hi); val.y = ((pp & 1) ? hi : lo) + bb[1];
            f2up(acc[4 + (pp >> 1)], lo, hi); val.z = ((pp & 1) ? hi : lo) + bb[2];
            f2up(acc[6 + (pp >> 1)], lo, hi); val.w = ((pp & 1) ? hi : lo) + bb[3];
            *(float4*)(g_f2 + (size_t)(base + pg * 4 + pp) * 128 + o0) = val;
        }
    }
}

// ---------------- FPS (bit-exact; SoA; ONE barrier per iteration) ---------
__global__ void __launch_bounds__(1024, 1) k_fps(const float* __restrict__ x,
                                                 float* __restrict__ out_down) {
    extern __shared__ float sp[];     // sxx[NP] syy[NP] szz[NP]
    float* sxx = sp;
    float* syy = sp + NP;
    float* szz = sp + 2 * NP;
    __shared__ unsigned s_bv[2][32];
    __shared__ unsigned s_bi[2][32];
    int b = blockIdx.x, t = threadIdx.x, lane = t & 31, wid = t >> 5;
    const float* xb = x + (size_t)b * NP * 3;
    for (int i = t; i < NP; i += 1024) {
        sxx[i] = xb[3 * i]; syy[i] = xb[3 * i + 1]; szz[i] = xb[3 * i + 2];
    }
    __syncthreads();
    float cx = sxx[0], cy = syy[0], cz = szz[0];
    if (t == 0) {
        int o3 = b * MP * 3;
        g_down[o3 + 0] = cx; g_down[o3 + 1] = cy; g_down[o3 + 2] = cz;
        out_down[o3 + 0] = cx; out_down[o3 + 1] = cy; out_down[o3 + 2] = cz;
    }
    int base = t * 8;
    ull pxp[4], pyp[4], pzp[4];
    float md[8];
#pragma unroll
    for (int j = 0; j < 4; j++) {
        pxp[j] = *(const ull*)(sxx + base + 2 * j);
        pyp[j] = *(const ull*)(syy + base + 2 * j);
        pzp[j] = *(const ull*)(szz + base + 2 * j);
        md[2 * j] = 1e10f; md[2 * j + 1] = 1e10f;
    }
    int buf = 0;
    for (int it = 1; it < MP; it++) {
        ull ncx = f2pk(-cx, -cx), ncy = f2pk(-cy, -cy), ncz = f2pk(-cz, -cz);
#pragma unroll
        for (int j = 0; j < 4; j++) {
            ull dx = addx2(pxp[j], ncx);
            ull dy = addx2(pyp[j], ncy);
            ull dz = addx2(pzp[j], ncz);
            ull s = addx2(addx2(mulx2(dx, dx), mulx2(dy, dy)), mulx2(dz, dz));
            float lo, hi; f2up(s, lo, hi);
            md[2 * j]     = fminf(md[2 * j], lo);
            md[2 * j + 1] = fminf(md[2 * j + 1], hi);
        }
        float m01 = fmaxf(md[0], md[1]), m23 = fmaxf(md[2], md[3]);
        float m45 = fmaxf(md[4], md[5]), m67 = fmaxf(md[6], md[7]);
        float m = fmaxf(fmaxf(m01, m23), fmaxf(m45, m67));
        unsigned wm = __reduce_max_sync(0xffffffffu, __float_as_uint(m));
        unsigned li = 0xffffffffu;
#pragma unroll
        for (int j = 7; j >= 0; j--)
            li = (__float_as_uint(md[j]) == wm) ? (unsigned)(base + j) : li;
        unsigned wi = __reduce_min_sync(0xffffffffu, li);
        if (lane == 0) { s_bv[buf][wid] = wm; s_bi[buf][wid] = wi; }
        __syncthreads();
        unsigned v = s_bv[buf][lane];
        unsigned gm = __reduce_max_sync(0xffffffffu, v);
        unsigned cand = (v == gm) ? s_bi[buf][lane] : 0xffffffffu;
        unsigned gi = __reduce_min_sync(0xffffffffu, cand);
        cx = sxx[gi]; cy = syy[gi]; cz = szz[gi];
        if (t == 0) {
            int o3 = (b * MP + it) * 3;
            g_down[o3 + 0] = cx; g_down[o3 + 1] = cy; g_down[o3 + 2] = cz;
            out_down[o3 + 0] = cx; out_down[o3 + 1] = cy; out_down[o3 + 2] = cz;
        }
        buf ^= 1;
    }
}

// ---------------- KNN top-17 (stable; SoA; f32x2 pair per iter) -----------
__global__ void __launch_bounds__(64) k_knn(const float* __restrict__ x) {
    extern __shared__ float kp[];
    float* sxx = kp;
    float* syy = kp + NP;
    float* szz = kp + 2 * NP;
    int gid = blockIdx.x * 64 + threadIdx.x;
    int b = gid >> 10;
    const float* xb = x + (size_t)b * NP * 3;
    for (int i = threadIdx.x; i < NP; i += 64) {
        sxx[i] = xb[3 * i]; syy[i] = xb[3 * i + 1]; szz[i] = xb[3 * i + 2];
    }
    __syncthreads();
    float qx = g_down[gid * 3 + 0], qy = g_down[gid * 3 + 1], qz = g_down[gid * 3 + 2];
    float sd = __fadd_rn(__fadd_rn(__fmul_rn(qx, qx), __fmul_rn(qy, qy)), __fmul_rn(qz, qz));
    ull qxp = f2pk(qx, qx), qyp = f2pk(qy, qy), qzp = f2pk(qz, qz);
    ull sdp = f2pk(sd, sd), n2p = f2pk(-2.f, -2.f);
    float dist[17]; int ind[17];
#pragma unroll
    for (int i = 0; i < 17; i++) { dist[i] = 3.4e38f; ind[i] = 0; }
    for (int n = 0; n < NP; n += 2) {
        ull axp = *(const ull*)(sxx + n);
        ull ayp = *(const ull*)(syy + n);
        ull azp = *(const ull*)(szz + n);
        ull sn = addx2(addx2(mulx2(axp, axp), mulx2(ayp, ayp)), mulx2(azp, azp));
        ull dt = addx2(addx2(mulx2(qxp, axp), mulx2(qyp, ayp)), mulx2(qzp, azp));
        ull d2p = addx2(addx2(sdp, sn), mulx2(n2p, dt));
        float dlo, dhi; f2up(d2p, dlo, dhi);
#pragma unroll
        for (int h = 0; h < 2; h++) {
            float d2 = h ? dhi : dlo;
            int ni = n + h;
            if (d2 < dist[16]) {
                int pos = 0;
#pragma unroll
                for (int s = 0; s < 17; s++) pos += (dist[s] <= d2) ? 1 : 0;
#pragma unroll
                for (int s = 16; s > 0; s--) {
                    if (s > pos) { dist[s] = dist[s - 1]; ind[s] = ind[s - 1]; }
                    else if (s == pos) { dist[s] = d2; ind[s] = ni; }
                }
                if (pos == 0) { dist[0] = d2; ind[0] = ni; }
            }
        }
    }
#pragma unroll
    for (int s = 0; s < 17; s++) g_knn[(size_t)gid * 17 + s] = ind[s];
}

// ---------------- grouped convs + attention (G=2 m's per block) -----------
__global__ void __launch_bounds__(256) k_attn(
    const float* __restrict__ x,
    const float* __restrict__ b3,
    float* __restrict__ out_new)
{
    extern __shared__ __align__(16) float sm[];
    float* feat = sm;                  // [34][256]
    float* h1   = sm + 8704;           // [34][64]
    float* us   = sm + 8704;           // alias (h1 dead)
    float* h2   = sm + 10880;          // [34][64]
    float* knnx = sm + 13056;          // [34][3]
    float* dwn  = sm + 13158;          // [2][3]
    float* lg   = sm + 13164;          // 34
    int*   sidx = (int*)(sm + 13200);  // 34

    int t = threadIdx.x;
    int wid = t >> 5, lane = t & 31;
    int bm0 = blockIdx.x * 2;
    int b = bm0 >> 10;
    const float* xb = x + (size_t)b * NP * 3;

    if (t < 34) {
        int id = g_knn[(size_t)bm0 * 17 + t];
        sidx[t] = id;
        knnx[t * 3 + 0] = xb[id * 3 + 0];
        knnx[t * 3 + 1] = xb[id * 3 + 1];
        knnx[t * 3 + 2] = xb[id * 3 + 2];
    }
    if (t < 6) dwn[t] = g_down[(size_t)bm0 * 3 + t];
    __syncthreads();

    // gather knn_f -> feat[:,0..127]
    for (int r = wid; r < 34; r += 8) {
        const float4* src = (const float4*)(g_f2 + ((size_t)(b * NP) + sidx[r]) * 128);
        ((float4*)(feat + r * 256))[lane] = src[lane];
    }

    // h1: 9 -> 64 (prefolded bn), leaky
    for (int i = 0; i < 9; i++) {
        int task = t + 256 * i;
        if (task < 2176) {
            int o = task & 63, row = task >> 6;
            int mi = (row >= 17) ? 1 : 0;
            const float* kpp = knnx + row * 3;
            const float* dp = dwn + mi * 3;
            float r0 = dp[0], r1 = dp[1], r2v = dp[2];
            float r3 = kpp[0], r4 = kpp[1], r5 = kpp[2];
            const float* w = g_w1f + o * 9;
            float a = g_b1f[o];
            a += w[0] * r0 + w[1] * r1 + w[2] * r2v;
            a += w[3] * r3 + w[4] * r4 + w[5] * r5;
            a += w[6] * (r0 - r3) + w[7] * (r1 - r4) + w[8] * (r2v - r5);
            a = a > 0.f ? a : 0.01f * a;
            h1[row * 64 + o] = a;
        }
    }
    __syncthreads();
    // h2: 64 -> 64 (prefolded), leaky; row-pairs (row, row+17)
    {
        const float4* wp = (const float4*)g_s2w2p;
        for (int i = 0; i < 5; i++) {
            int task = t + 256 * i;
            if (task < 1088) {
                int o = task & 63, row = task >> 6;
                const float4* hA = (const float4*)(h1 + row * 64);
                const float4* hB = (const float4*)(h1 + (row + 17) * 64);
                float a0 = g_b2f[o], a1 = g_b2f[o];
#pragma unroll
                for (int c4 = 0; c4 < 16; c4++) {
                    float4 w = wp[c4 * 64 + o];
                    float4 v0 = hA[c4], v1 = hB[c4];
                    a0 += w.x * v0.x + w.y * v0.y + w.z * v0.z + w.w * v0.w;
                    a1 += w.x * v1.x + w.y * v1.y + w.z * v1.z + w.w * v1.w;
                }
                a0 = a0 > 0.f ? a0 : 0.01f * a0;
                a1 = a1 > 0.f ? a1 : 0.01f * a1;
                h2[row * 64 + o] = a0;
                h2[(row + 17) * 64 + o] = a1;
            }
        }
    }
    __syncthreads();
    // r2: 64 -> 128 -> feat[:,128..255]; row-pairs
    {
        const float4* wp = (const float4*)g_s2w3p;
        for (int i = 0; i < 9; i++) {
            int task = t + 256 * i;
            if (task < 2176) {
                int o = task & 127, row = task >> 7;
                const float4* hA = (const float4*)(h2 + row * 64);
                const float4* hB = (const float4*)(h2 + (row + 17) * 64);
                float a0 = b3[o], a1 = b3[o];
#pragma unroll
                for (int c4 = 0; c4 < 16; c4++) {
                    float4 w = wp[c4 * 128 + o];
                    float4 v0 = hA[c4], v1 = hB[c4];
                    a0 += w.x * v0.x + w.y * v0.y + w.z * v0.z + w.w * v0.w;
                    a1 += w.x * v1.x + w.y * v1.y + w.z * v1.z + w.w * v1.w;
                }
                feat[row * 256 + 128 + o] = a0;
                feat[(row + 17) * 256 + 128 + o] = a1;
            }
        }
    }
    __syncthreads();

    // u_m = A f_m0 + c
    {
        const float4* ap = (const float4*)g_Ap;
        float a0 = 0.f, a1 = 0.f;
        for (int c4 = 0; c4 < 64; c4++) {
            float4 w = ap[c4 * 256 + t];
            float4 v0 = *(const float4*)(feat + c4 * 4);
            float4 v1 = *(const float4*)(feat + 17 * 256 + c4 * 4);
            a0 += w.x * v0.x + w.y * v0.y + w.z * v0.z + w.w * v0.w;
            a1 += w.x * v1.x + w.y * v1.y + w.z * v1.z + w.w * v1.w;
        }
        float cv = g_cvec[t];
        us[t] = a0 + cv;
        us[256 + t] = a1 + cv;
    }
    __syncthreads();

    // logits
    for (int task = wid; task < 34; task += 8) {
        float s = 0.f;
        if (task < 32) {
            int mi = task >> 4, j = task & 15;
            const float* uf = us + mi * 256;
            const float* fr = feat + (mi * 17 + 1 + j) * 256;
#pragma unroll
            for (int s8 = 0; s8 < 8; s8++) { int o = lane + 32 * s8; s += uf[o] * fr[o]; }
        } else {
            int mi = task - 32;
            const float* fr = feat + mi * 17 * 256;
#pragma unroll
            for (int s8 = 0; s8 < 8; s8++) { int o = lane + 32 * s8; s += __ldg(&g_vb[o]) * fr[o]; }
        }
#pragma unroll
        for (int off = 16; off; off >>= 1) s += __shfl_down_sync(0xffffffffu, s, off);
        if (lane == 0) lg[task] = s;
    }
    __syncthreads();

    // softmax + weighted neighbor sum
    if (t < 2) {
        float ex = lg[32 + t] + g_s0[0];
        float l[16], mx = -3.4e38f;
#pragma unroll
        for (int j = 0; j < 16; j++) { l[j] = lg[t * 16 + j] + ex; mx = fmaxf(mx, l[j]); }
        float sum = 0.f;
#pragma unroll
        for (int j = 0; j < 16; j++) { l[j] = expf(l[j] - mx); sum += l[j]; }
        float inv = 1.f / sum;
        float nx = 0.f, ny = 0.f, nz = 0.f;
#pragma unroll
        for (int j = 0; j < 16; j++) {
            float w = l[j] * inv;
            const float* kpp = knnx + (t * 17 + 1 + j) * 3;
            nx += w * kpp[0]; ny += w * kpp[1]; nz += w * kpp[2];
        }
        float* po = out_new + (size_t)(bm0 + t) * 3;
        po[0] = nx; po[1] = ny; po[2] = nz;
    }
}

// ---------------- launch ---------------------------------------------------
extern "C" void kernel_launch(void* const* d_in, const int* in_sizes, int n_in,
                              void* d_out, int out_size) {
    const float* x      = (const float*)d_in[0];
    const float* gf     = (const float*)d_in[1];
    const float* c1_w1  = (const float*)d_in[2];
    const float* c1_b1  = (const float*)d_in[3];
    const float* c1_w2  = (const float*)d_in[4];
    const float* c1_b2  = (const float*)d_in[5];
    const float* cf_w1  = (const float*)d_in[6];
    const float* cf_b1  = (const float*)d_in[7];
    const float* cf_w2  = (const float*)d_in[8];
    const float* cf_b2  = (const float*)d_in[9];
    const float* cs_w1  = (const float*)d_in[10];
    const float* cs_b1  = (const float*)d_in[11];
    const float* cs_w2  = (const float*)d_in[12];
    const float* cs_b2  = (const float*)d_in[13];
    const float* s2_w1  = (const float*)d_in[14];
    const float* s2_b1  = (const float*)d_in[15];
    const float* s2_g1  = (const float*)d_in[16];
    const float* s2_bb1 = (const float*)d_in[17];
    const float* s2_w2  = (const float*)d_in[18];
    const float* s2_b2  = (const float*)d_in[19];
    const float* s2_g2  = (const float*)d_in[20];
    const float* s2_bb2 = (const float*)d_in[21];
    const float* s2_w3  = (const float*)d_in[22];
    const float* s2_b3  = (const float*)d_in[23];
    const float* q_w    = (const float*)d_in[24];
    const float* q_b    = (const float*)d_in[25];
    const float* k_w    = (const float*)d_in[26];
    const float* k_b    = (const float*)d_in[27];
    float* out = (float*)d_out;

    static bool s_init = false;
    static cudaStream_t st;
    static cudaEvent_t evF, evD;
    if (!s_init) {
        cudaStreamCreateWithFlags(&st, cudaStreamNonBlocking);
        cudaEventCreateWithFlags(&evF, cudaEventDisableTiming);
        cudaEventCreateWithFlags(&evD, cudaEventDisableTiming);
        cudaFuncSetAttribute(k_feat, cudaFuncAttributeMaxDynamicSharedMemorySize, (512 * FS + 96) * 4);
        cudaFuncSetAttribute(k_knn,  cudaFuncAttributeMaxDynamicSharedMemorySize, NP * 3 * 4);
        cudaFuncSetAttribute(k_fps,  cudaFuncAttributeMaxDynamicSharedMemorySize, NP * 3 * 4);
        cudaFuncSetAttribute(k_attn, cudaFuncAttributeMaxDynamicSharedMemorySize, 13236 * 4);
        s_init = true;
    }

    // fork for the geometric chain
    cudaEventRecord(evF, 0);
    cudaStreamWaitEvent(st, evF, 0);
    k_fps<<<BN, 1024, NP * 3 * 4, st>>>(x, out);                      // #1
    k_knn<<<(BN * MP) / 64, 64, NP * 3 * 4, st>>>(x);                 // #2
    cudaEventRecord(evD, st);

    // main stream
    k_prep<<<730, 256>>>(cs_w1, cs_w2, c1_w2,                         // #3
                         s2_w1, s2_b1, s2_g1, s2_bb1,
                         s2_w2, s2_b2, s2_g2, s2_bb2, s2_w3,
                         q_w, k_w, q_b, k_b,
                         gf, cf_w1, cf_b1, cf_w2, cf_b2);
    k_feat<<<(BN * NP) / 32, 256, (512 * FS + 96) * 4>>>(x,           // #4 <- profiled
        c1_w1, c1_b1, c1_b2, cs_b1, cs_b2);

    cudaStreamWaitEvent(0, evD, 0);
    k_attn<<<(BN * MP) / 2, 256, 13236 * 4>>>(x, s2_b3,               // #5
        out + (size_t)BN * MP * 3);
}

// round 7
// speedup vs baseline: 8.0742x; 1.1284x over previous
#include <cuda_runtime.h>
#include <math.h>

#define BN 8
#define NP 8192
#define MP 1024
#define KNB 17
#define FS 36   // transposed-row stride (floats), 16B-aligned

typedef unsigned long long ull;

// ---------------- scratch (device globals; no allocation) ----------------
__device__ float g_gvec[BN * 128];
__device__ float g_f2[BN * NP * 128];
__device__ float g_down[BN * MP * 3];
__device__ int   g_knn[BN * MP * KNB];
// transposed weights for feat: T[c*O + o] = W[o][c]  (coalesced float4 loads)
__device__ float g_csw1t[256 * 256];
__device__ float g_csw2t[256 * 128];
__device__ float g_c1w2t[64 * 128];
// packed (4c x o x 4) weights for attn convs (s2w2 prefolded with bn)
__device__ float g_s2w2p[64 * 64];
__device__ float g_s2w3p[128 * 64];
// prefolded h1 weights/biases
__device__ float g_w1f[64 * 9];
__device__ float g_b1f[64];
__device__ float g_b2f[64];
// fused attention mats: A = Wk^T Wq (packed), c = Wk^T bq, vb = Wq^T bk, s0 = bq.bk
__device__ float g_Ap[256 * 256];
__device__ float g_cvec[256];
__device__ float g_vb[256];
__device__ float g_s0[1];

__device__ __forceinline__ ull f2pk(float lo, float hi) {
    ull r; asm("mov.b64 %0,{%1,%2};" : "=l"(r) : "f"(lo), "f"(hi)); return r;
}
__device__ __forceinline__ void f2up(ull v, float& lo, float& hi) {
    asm("mov.b64 {%0,%1},%2;" : "=f"(lo), "=f"(hi) : "l"(v));
}
__device__ __forceinline__ ull addx2(ull a, ull b) {
    ull r; asm("add.rn.f32x2 %0,%1,%2;" : "=l"(r) : "l"(a), "l"(b)); return r;
}
__device__ __forceinline__ ull mulx2(ull a, ull b) {
    ull r; asm("mul.rn.f32x2 %0,%1,%2;" : "=l"(r) : "l"(a), "l"(b)); return r;
}
__device__ __forceinline__ ull fma2(ull a, ull b, ull c) {
    ull r; asm("fma.rn.f32x2 %0,%1,%2,%3;" : "=l"(r) : "l"(a), "l"(b), "l"(c)); return r;
}

// ---------------- prep ----------------------------------------------------
__device__ __forceinline__ void rp_t(const float* __restrict__ w, float* __restrict__ o,
                                     int O, int C, int blk) {
    int g = blk * 256 + threadIdx.x;
    if (g >= O * C) return;
    int c = g / O, oo = g - c * O;
    o[c * O + oo] = w[oo * C + c];
}

__global__ void k_prep(const float* __restrict__ cs_w1, const float* __restrict__ cs_w2,
                       const float* __restrict__ c1_w2,
                       const float* __restrict__ s2_w1, const float* __restrict__ s2_b1,
                       const float* __restrict__ s2_g1, const float* __restrict__ s2_bb1,
                       const float* __restrict__ s2_w2, const float* __restrict__ s2_b2,
                       const float* __restrict__ s2_g2, const float* __restrict__ s2_bb2,
                       const float* __restrict__ s2_w3,
                       const float* __restrict__ q_w, const float* __restrict__ k_w,
                       const float* __restrict__ q_b, const float* __restrict__ k_b,
                       const float* __restrict__ gf,
                       const float* __restrict__ cf_w1, const float* __restrict__ cf_b1,
                       const float* __restrict__ cf_w2, const float* __restrict__ cf_b2) {
    __shared__ float s_buf[512];
    __shared__ float s_h[256];
    __shared__ float s_red[8];
    const float bnc = 1.f / sqrtf(1.0f + 1e-5f);
    int blk = blockIdx.x, t = threadIdx.x;
    if (blk < 256)  { rp_t(cs_w1, g_csw1t, 256, 256, blk); return; }
    if (blk < 384)  { rp_t(cs_w2, g_csw2t, 128, 256, blk - 256); return; }
    if (blk < 416)  { rp_t(c1_w2, g_c1w2t, 128, 64, blk - 384); return; }
    if (blk < 432) {
        int g = (blk - 416) * 256 + t;   // 4096 = 64x64, prefold bn
        int o = g >> 6, c = g & 63;
        g_s2w2p[((c >> 2) * 64 + o) * 4 + (c & 3)] = s2_w2[o * 64 + c] * (s2_g2[o] * bnc);
        return;
    }
    if (blk < 464) {
        int g = (blk - 432) * 256 + t;   // 8192 = 128x64
        int o = g >> 6, c = g & 63;
        g_s2w3p[((c >> 2) * 128 + o) * 4 + (c & 3)] = s2_w3[o * 64 + c];
        return;
    }
    if (blk < 720) {
        // row i of A = Wk^T Wq, plus c[i]
        int i = blk - 464;
        s_buf[t] = k_w[t * 256 + i];
        __syncthreads();
        float acc = 0.f;
        for (int o = 0; o < 256; o++) acc += s_buf[o] * __ldg(q_w + o * 256 + t);
        g_Ap[((t >> 2) * 256 + i) * 4 + (t & 3)] = acc;
        float part = s_buf[t] * q_b[t];
#pragma unroll
        for (int off = 16; off; off >>= 1) part += __shfl_down_sync(0xffffffffu, part, off);
        if ((t & 31) == 0) s_red[t >> 5] = part;
        __syncthreads();
        if (t == 0) { float s = 0.f; for (int w = 0; w < 8; w++) s += s_red[w]; g_cvec[i] = s; }
        return;
    }
    if (blk < 728) {
        // global-feature MLP: 512 -> 256 relu -> 128
        int b = blk - 720;
        for (int i = t; i < 512; i += 256) s_buf[i] = gf[b * 512 + i];
        __syncthreads();
        float a = cf_b1[t];
        const float* wr = cf_w1 + t * 512;
        for (int c = 0; c < 512; c++) a += wr[c] * s_buf[c];
        s_h[t] = fmaxf(a, 0.f);
        __syncthreads();
        if (t < 128) {
            float a2 = cf_b2[t];
            const float* w2r = cf_w2 + t * 256;
            for (int c = 0; c < 256; c++) a2 += w2r[c] * s_h[c];
            g_gvec[b * 128 + t] = a2;
        }
        return;
    }
    if (blk == 728) {
        float acc = 0.f;
        for (int o = 0; o < 256; o++) acc += __ldg(q_w + o * 256 + t) * k_b[o];
        g_vb[t] = acc;
        if (t == 0) {
            float s = 0.f;
            for (int o = 0; o < 256; o++) s += q_b[o] * k_b[o];
            g_s0[0] = s;
        }
        return;
    }
    // blk == 729: h1 prefold
    for (int i = t; i < 576; i += 256) {
        int o = i / 9;
        g_w1f[i] = s2_w1[i] * (s2_g1[o] * bnc);
    }
    if (t < 64) {
        g_b1f[t] = s2_b1[t] * (s2_g1[t] * bnc) + s2_bb1[t];
        g_b2f[t] = s2_b2[t] * (s2_g2[t] * bnc) + s2_bb2[t];
    }
}

// ---------------- fused c1 + cs MLP (coalesced W^T + in-reg dup) ----------
// 32 points per block; transposed channel-major smem [C][FS].
__global__ void __launch_bounds__(256) k_feat(const float* __restrict__ x,
                                              const float* __restrict__ c1w1,
                                              const float* __restrict__ c1b1,
                                              const float* __restrict__ c1b2,
                                              const float* __restrict__ csb1,
                                              const float* __restrict__ csb2) {
    extern __shared__ __align__(16) float fm[];
    float* s_int = fm;                 // [256][FS]
    float* s_ht  = fm + 256 * FS;      // [256][FS] (rows 0..63 alias c1 hidden)
    float* s_h64 = s_ht;
    float* s_xyz = fm + 512 * FS;
    int t = threadIdx.x;
    int base = blockIdx.x * 32;
    int b = base >> 13;
    if (t < 96) s_xyz[t] = x[(size_t)base * 3 + t];
    __syncthreads();
    // c1 layer1: 3 -> 64, relu
    for (int i = 0; i < 8; i++) {
        int task = t + 256 * i;
        int p = task & 31, o = task >> 5;
        float a = c1b1[o];
        a += c1w1[o * 3 + 0] * s_xyz[p * 3 + 0];
        a += c1w1[o * 3 + 1] * s_xyz[p * 3 + 1];
        a += c1w1[o * 3 + 2] * s_xyz[p * 3 + 2];
        s_h64[o * FS + p] = fmaxf(a, 0.f);
    }
    __syncthreads();
    // c1 layer2: 64 -> 128 -> s_int rows 0..127   (tile 4 outs x 4 pts)
    {
        int o0 = (t & 31) * 4, pg = t >> 5;
        ull acc[8];
#pragma unroll
        for (int i = 0; i < 8; i++) acc[i] = 0ull;
#pragma unroll 4
        for (int c = 0; c < 64; c++) {
            float4 w = *(const float4*)(g_c1w2t + c * 128 + o0);
            ull w0 = f2pk(w.x, w.x), w1 = f2pk(w.y, w.y);
            ull w2 = f2pk(w.z, w.z), w3 = f2pk(w.w, w.w);
            ulonglong2 v = *(const ulonglong2*)(s_h64 + c * FS + pg * 4);
            acc[0] = fma2(w0, v.x, acc[0]); acc[1] = fma2(w0, v.y, acc[1]);
            acc[2] = fma2(w1, v.x, acc[2]); acc[3] = fma2(w1, v.y, acc[3]);
            acc[4] = fma2(w2, v.x, acc[4]); acc[5] = fma2(w2, v.y, acc[5]);
            acc[6] = fma2(w3, v.x, acc[6]); acc[7] = fma2(w3, v.y, acc[7]);
        }
        float4 bq = *(const float4*)(c1b2 + o0);
        float bb[4] = { bq.x, bq.y, bq.z, bq.w };
        __syncthreads();
#pragma unroll
        for (int oi = 0; oi < 4; oi++) {
            ull bp = f2pk(bb[oi], bb[oi]);
            *(ull*)(s_int + (o0 + oi) * FS + pg * 4)     = addx2(acc[oi * 2], bp);
            *(ull*)(s_int + (o0 + oi) * FS + pg * 4 + 2) = addx2(acc[oi * 2 + 1], bp);
        }
    }
    // gvec rows 128..255
    for (int i = t; i < 128 * 32; i += 256) {
        int c = i >> 5, p = i & 31;
        s_int[(128 + c) * FS + p] = __ldg(&g_gvec[b * 128 + c]);
    }
    __syncthreads();
    // cs layer1: 256 -> 256, relu   (tile 4 outs x 8 pts)
    {
        int o0 = (t & 63) * 4, pg = t >> 6;
        ull acc[16];
#pragma unroll
        for (int i = 0; i < 16; i++) acc[i] = 0ull;
#pragma unroll 2
        for (int c = 0; c < 256; c++) {
            float4 w = *(const float4*)(g_csw1t + c * 256 + o0);
            ull w0 = f2pk(w.x, w.x), w1 = f2pk(w.y, w.y);
            ull w2 = f2pk(w.z, w.z), w3 = f2pk(w.w, w.w);
            ulonglong2 v01 = *(const ulonglong2*)(s_int + c * FS + pg * 8);
            ulonglong2 v23 = *(const ulonglong2*)(s_int + c * FS + pg * 8 + 4);
            acc[0]  = fma2(w0, v01.x, acc[0]);  acc[1]  = fma2(w0, v01.y, acc[1]);
            acc[2]  = fma2(w0, v23.x, acc[2]);  acc[3]  = fma2(w0, v23.y, acc[3]);
            acc[4]  = fma2(w1, v01.x, acc[4]);  acc[5]  = fma2(w1, v01.y, acc[5]);
            acc[6]  = fma2(w1, v23.x, acc[6]);  acc[7]  = fma2(w1, v23.y, acc[7]);
            acc[8]  = fma2(w2, v01.x, acc[8]);  acc[9]  = fma2(w2, v01.y, acc[9]);
            acc[10] = fma2(w2, v23.x, acc[10]); acc[11] = fma2(w2, v23.y, acc[11]);
            acc[12] = fma2(w3, v01.x, acc[12]); acc[13] = fma2(w3, v01.y, acc[13]);
            acc[14] = fma2(w3, v23.x, acc[14]); acc[15] = fma2(w3, v23.y, acc[15]);
        }
        float4 bq = *(const float4*)(csb1 + o0);
        float bb[4] = { bq.x, bq.y, bq.z, bq.w };
        __syncthreads();
#pragma unroll
        for (int oi = 0; oi < 4; oi++) {
#pragma unroll
            for (int g = 0; g < 4; g++) {
                float lo, hi; f2up(acc[oi * 4 + g], lo, hi);
                lo = fmaxf(lo + bb[oi], 0.f); hi = fmaxf(hi + bb[oi], 0.f);
                *(ull*)(s_ht + (o0 + oi) * FS + pg * 8 + g * 2) = f2pk(lo, hi);
            }
        }
    }
    __syncthreads();
    // cs layer2: 256 -> 128 -> g_f2 point-major   (tile 4 outs x 4 pts)
    {
        int o0 = (t & 31) * 4, pg = t >> 5;
        ull acc[8];
#pragma unroll
        for (int i = 0; i < 8; i++) acc[i] = 0ull;
#pragma unroll 2
        for (int c = 0; c < 256; c++) {
            float4 w = *(const float4*)(g_csw2t + c * 128 + o0);
            ull w0 = f2pk(w.x, w.x), w1 = f2pk(w.y, w.y);
            ull w2 = f2pk(w.z, w.z), w3 = f2pk(w.w, w.w);
            ulonglong2 v = *(const ulonglong2*)(s_ht + c * FS + pg * 4);
            acc[0] = fma2(w0, v.x, acc[0]); acc[1] = fma2(w0, v.y, acc[1]);
            acc[2] = fma2(w1, v.x, acc[2]); acc[3] = fma2(w1, v.y, acc[3]);
            acc[4] = fma2(w2, v.x, acc[4]); acc[5] = fma2(w2, v.y, acc[5]);
            acc[6] = fma2(w3, v.x, acc[6]); acc[7] = fma2(w3, v.y, acc[7]);
        }
        float4 bq = *(const float4*)(csb2 + o0);
        float bb[4] = { bq.x, bq.y, bq.z, bq.w };
#pragma unroll
        for (int pp = 0; pp < 4; pp++) {
            float4 val;
            float lo, hi;
            f2up(acc[0 + (pp >> 1)], lo, hi); val.x = ((pp & 1) ? hi : lo) + bb[0];
            f2up(acc[2 + (pp >> 1)], lo, hi); val.y = ((pp & 1) ? hi : lo) + bb[1];
            f2up(acc[4 + (pp >> 1)], lo, hi); val.z = ((pp & 1) ? hi : lo) + bb[2];
            f2up(acc[6 + (pp >> 1)], lo, hi); val.w = ((pp & 1) ? hi : lo) + bb[3];
            *(float4*)(g_f2 + (size_t)(base + pg * 4 + pp) * 128 + o0) = val;
        }
    }
}

// ---------------- FPS (bit-exact; SoA; ONE barrier per iteration) ---------
__global__ void __launch_bounds__(1024, 1) k_fps(const float* __restrict__ x,
                                                 float* __restrict__ out_down) {
    extern __shared__ float sp[];     // sxx[NP] syy[NP] szz[NP]
    float* sxx = sp;
    float* syy = sp + NP;
    float* szz = sp + 2 * NP;
    __shared__ unsigned s_bv[2][32];
    __shared__ unsigned s_bi[2][32];
    int b = blockIdx.x, t = threadIdx.x, lane = t & 31, wid = t >> 5;
    const float* xb = x + (size_t)b * NP * 3;
    for (int i = t; i < NP; i += 1024) {
        sxx[i] = xb[3 * i]; syy[i] = xb[3 * i + 1]; szz[i] = xb[3 * i + 2];
    }
    __syncthreads();
    float cx = sxx[0], cy = syy[0], cz = szz[0];
    if (t == 0) {
        int o3 = b * MP * 3;
        g_down[o3 + 0] = cx; g_down[o3 + 1] = cy; g_down[o3 + 2] = cz;
        out_down[o3 + 0] = cx; out_down[o3 + 1] = cy; out_down[o3 + 2] = cz;
    }
    int base = t * 8;
    ull pxp[4], pyp[4], pzp[4];
    float md[8];
#pragma unroll
    for (int j = 0; j < 4; j++) {
        pxp[j] = *(const ull*)(sxx + base + 2 * j);
        pyp[j] = *(const ull*)(syy + base + 2 * j);
        pzp[j] = *(const ull*)(szz + base + 2 * j);
        md[2 * j] = 1e10f; md[2 * j + 1] = 1e10f;
    }
    int buf = 0;
    for (int it = 1; it < MP; it++) {
        ull ncx = f2pk(-cx, -cx), ncy = f2pk(-cy, -cy), ncz = f2pk(-cz, -cz);
#pragma unroll
        for (int j = 0; j < 4; j++) {
            ull dx = addx2(pxp[j], ncx);
            ull dy = addx2(pyp[j], ncy);
            ull dz = addx2(pzp[j], ncz);
            ull s = addx2(addx2(mulx2(dx, dx), mulx2(dy, dy)), mulx2(dz, dz));
            float lo, hi; f2up(s, lo, hi);
            md[2 * j]     = fminf(md[2 * j], lo);
            md[2 * j + 1] = fminf(md[2 * j + 1], hi);
        }
        float m01 = fmaxf(md[0], md[1]), m23 = fmaxf(md[2], md[3]);
        float m45 = fmaxf(md[4], md[5]), m67 = fmaxf(md[6], md[7]);
        float m = fmaxf(fmaxf(m01, m23), fmaxf(m45, m67));
        unsigned wm = __reduce_max_sync(0xffffffffu, __float_as_uint(m));
        unsigned li = 0xffffffffu;
#pragma unroll
        for (int j = 7; j >= 0; j--)
            li = (__float_as_uint(md[j]) == wm) ? (unsigned)(base + j) : li;
        unsigned wi = __reduce_min_sync(0xffffffffu, li);
        if (lane == 0) { s_bv[buf][wid] = wm; s_bi[buf][wid] = wi; }
        __syncthreads();
        unsigned v = s_bv[buf][lane];
        unsigned gm = __reduce_max_sync(0xffffffffu, v);
        unsigned cand = (v == gm) ? s_bi[buf][lane] : 0xffffffffu;
        unsigned gi = __reduce_min_sync(0xffffffffu, cand);
        cx = sxx[gi]; cy = syy[gi]; cz = szz[gi];
        if (t == 0) {
            int o3 = (b * MP + it) * 3;
            g_down[o3 + 0] = cx; g_down[o3 + 1] = cy; g_down[o3 + 2] = cz;
            out_down[o3 + 0] = cx; out_down[o3 + 1] = cy; out_down[o3 + 2] = cz;
        }
        buf ^= 1;
    }
}

// ---------------- KNN top-17 (stable; SoA; f32x2 pair per iter) -----------
__global__ void __launch_bounds__(64) k_knn(const float* __restrict__ x) {
    extern __shared__ float kp[];
    float* sxx = kp;
    float* syy = kp + NP;
    float* szz = kp + 2 * NP;
    int gid = blockIdx.x * 64 + threadIdx.x;
    int b = gid >> 10;
    const float* xb = x + (size_t)b * NP * 3;
    for (int i = threadIdx.x; i < NP; i += 64) {
        sxx[i] = xb[3 * i]; syy[i] = xb[3 * i + 1]; szz[i] = xb[3 * i + 2];
    }
    __syncthreads();
    float qx = g_down[gid * 3 + 0], qy = g_down[gid * 3 + 1], qz = g_down[gid * 3 + 2];
    float sd = __fadd_rn(__fadd_rn(__fmul_rn(qx, qx), __fmul_rn(qy, qy)), __fmul_rn(qz, qz));
    ull qxp = f2pk(qx, qx), qyp = f2pk(qy, qy), qzp = f2pk(qz, qz);
    ull sdp = f2pk(sd, sd), n2p = f2pk(-2.f, -2.f);
    float dist[17]; int ind[17];
#pragma unroll
    for (int i = 0; i < 17; i++) { dist[i] = 3.4e38f; ind[i] = 0; }
    for (int n = 0; n < NP; n += 2) {
        ull axp = *(const ull*)(sxx + n);
        ull ayp = *(const ull*)(syy + n);
        ull azp = *(const ull*)(szz + n);
        ull sn = addx2(addx2(mulx2(axp, axp), mulx2(ayp, ayp)), mulx2(azp, azp));
        ull dt = addx2(addx2(mulx2(qxp, axp), mulx2(qyp, ayp)), mulx2(qzp, azp));
        ull d2p = addx2(addx2(sdp, sn), mulx2(n2p, dt));
        float dlo, dhi; f2up(d2p, dlo, dhi);
#pragma unroll
        for (int h = 0; h < 2; h++) {
            float d2 = h ? dhi : dlo;
            int ni = n + h;
            if (d2 < dist[16]) {
                int pos = 0;
#pragma unroll
                for (int s = 0; s < 17; s++) pos += (dist[s] <= d2) ? 1 : 0;
#pragma unroll
                for (int s = 16; s > 0; s--) {
                    if (s > pos) { dist[s] = dist[s - 1]; ind[s] = ind[s - 1]; }
                    else if (s == pos) { dist[s] = d2; ind[s] = ni; }
                }
                if (pos == 0) { dist[0] = d2; ind[0] = ni; }
            }
        }
    }
#pragma unroll
    for (int s = 0; s < 17; s++) g_knn[(size_t)gid * 17 + s] = ind[s];
}

// ---------------- grouped convs + attention (G=2 m's per block) -----------
__global__ void __launch_bounds__(256) k_attn(
    const float* __restrict__ x,
    const float* __restrict__ b3,
    float* __restrict__ out_new)
{
    extern __shared__ __align__(16) float sm[];
    float* feat = sm;                  // [34][256]
    float* h1   = sm + 8704;           // [34][64]
    float* us   = sm + 8704;           // alias (h1 dead)
    float* h2   = sm + 10880;          // [34][64]
    float* knnx = sm + 13056;          // [34][3]
    float* dwn  = sm + 13158;          // [2][3]
    float* lg   = sm + 13164;          // 34
    int*   sidx = (int*)(sm + 13200);  // 34

    int t = threadIdx.x;
    int wid = t >> 5, lane = t & 31;
    int bm0 = blockIdx.x * 2;
    int b = bm0 >> 10;
    const float* xb = x + (size_t)b * NP * 3;

    if (t < 34) {
        int id = g_knn[(size_t)bm0 * 17 + t];
        sidx[t] = id;
        knnx[t * 3 + 0] = xb[id * 3 + 0];
        knnx[t * 3 + 1] = xb[id * 3 + 1];
        knnx[t * 3 + 2] = xb[id * 3 + 2];
    }
    if (t < 6) dwn[t] = g_down[(size_t)bm0 * 3 + t];
    __syncthreads();

    // gather knn_f -> feat[:,0..127]
    for (int r = wid; r < 34; r += 8) {
        const float4* src = (const float4*)(g_f2 + ((size_t)(b * NP) + sidx[r]) * 128);
        ((float4*)(feat + r * 256))[lane] = src[lane];
    }

    // h1: 9 -> 64 (prefolded bn), leaky
    for (int i = 0; i < 9; i++) {
        int task = t + 256 * i;
        if (task < 2176) {
            int o = task & 63, row = task >> 6;
            int mi = (row >= 17) ? 1 : 0;
            const float* kpp = knnx + row * 3;
            const float* dp = dwn + mi * 3;
            float r0 = dp[0], r1 = dp[1], r2v = dp[2];
            float r3 = kpp[0], r4 = kpp[1], r5 = kpp[2];
            const float* w = g_w1f + o * 9;
            float a = g_b1f[o];
            a += w[0] * r0 + w[1] * r1 + w[2] * r2v;
            a += w[3] * r3 + w[4] * r4 + w[5] * r5;
            a += w[6] * (r0 - r3) + w[7] * (r1 - r4) + w[8] * (r2v - r5);
            a = a > 0.f ? a : 0.01f * a;
            h1[row * 64 + o] = a;
        }
    }
    __syncthreads();
    // h2: 64 -> 64 (prefolded), leaky; row-pairs (row, row+17)
    {
        const float4* wp = (const float4*)g_s2w2p;
        for (int i = 0; i < 5; i++) {
            int task = t + 256 * i;
            if (task < 1088) {
                int o = task & 63, row = task >> 6;
                const float4* hA = (const float4*)(h1 + row * 64);
                const float4* hB = (const float4*)(h1 + (row + 17) * 64);
                float a0 = g_b2f[o], a1 = g_b2f[o];
#pragma unroll
                for (int c4 = 0; c4 < 16; c4++) {
                    float4 w = wp[c4 * 64 + o];
                    float4 v0 = hA[c4], v1 = hB[c4];
                    a0 += w.x * v0.x + w.y * v0.y + w.z * v0.z + w.w * v0.w;
                    a1 += w.x * v1.x + w.y * v1.y + w.z * v1.z + w.w * v1.w;
                }
                a0 = a0 > 0.f ? a0 : 0.01f * a0;
                a1 = a1 > 0.f ? a1 : 0.01f * a1;
                h2[row * 64 + o] = a0;
                h2[(row + 17) * 64 + o] = a1;
            }
        }
    }
    __syncthreads();
    // r2: 64 -> 128 -> feat[:,128..255]; row-pairs
    {
        const float4* wp = (const float4*)g_s2w3p;
        for (int i = 0; i < 9; i++) {
            int task = t + 256 * i;
            if (task < 2176) {
                int o = task & 127, row = task >> 7;
                const float4* hA = (const float4*)(h2 + row * 64);
                const float4* hB = (const float4*)(h2 + (row + 17) * 64);
                float a0 = b3[o], a1 = b3[o];
#pragma unroll
                for (int c4 = 0; c4 < 16; c4++) {
                    float4 w = wp[c4 * 128 + o];
                    float4 v0 = hA[c4], v1 = hB[c4];
                    a0 += w.x * v0.x + w.y * v0.y + w.z * v0.z + w.w * v0.w;
                    a1 += w.x * v1.x + w.y * v1.y + w.z * v1.z + w.w * v1.w;
                }
                feat[row * 256 + 128 + o] = a0;
                feat[(row + 17) * 256 + 128 + o] = a1;
            }
        }
    }
    __syncthreads();

    // u_m = A f_m0 + c
    {
        const float4* ap = (const float4*)g_Ap;
        float a0 = 0.f, a1 = 0.f;
        for (int c4 = 0; c4 < 64; c4++) {
            float4 w = ap[c4 * 256 + t];
            float4 v0 = *(const float4*)(feat + c4 * 4);
            float4 v1 = *(const float4*)(feat + 17 * 256 + c4 * 4);
            a0 += w.x * v0.x + w.y * v0.y + w.z * v0.z + w.w * v0.w;
            a1 += w.x * v1.x + w.y * v1.y + w.z * v1.z + w.w * v1.w;
        }
        float cv = g_cvec[t];
        us[t] = a0 + cv;
        us[256 + t] = a1 + cv;
    }
    __syncthreads();

    // logits
    for (int task = wid; task < 34; task += 8) {
        float s = 0.f;
        if (task < 32) {
            int mi = task >> 4, j = task & 15;
            const float* uf = us + mi * 256;
            const float* fr = feat + (mi * 17 + 1 + j) * 256;
#pragma unroll
            for (int s8 = 0; s8 < 8; s8++) { int o = lane + 32 * s8; s += uf[o] * fr[o]; }
        } else {
            int mi = task - 32;
            const float* fr = feat + mi * 17 * 256;
#pragma unroll
            for (int s8 = 0; s8 < 8; s8++) { int o = lane + 32 * s8; s += __ldg(&g_vb[o]) * fr[o]; }
        }
#pragma unroll
        for (int off = 16; off; off >>= 1) s += __shfl_down_sync(0xffffffffu, s, off);
        if (lane == 0) lg[task] = s;
    }
    __syncthreads();

    // softmax + weighted neighbor sum
    if (t < 2) {
        float ex = lg[32 + t] + g_s0[0];
        float l[16], mx = -3.4e38f;
#pragma unroll
        for (int j = 0; j < 16; j++) { l[j] = lg[t * 16 + j] + ex; mx = fmaxf(mx, l[j]); }
        float sum = 0.f;
#pragma unroll
        for (int j = 0; j < 16; j++) { l[j] = expf(l[j] - mx); sum += l[j]; }
        float inv = 1.f / sum;
        float nx = 0.f, ny = 0.f, nz = 0.f;
#pragma unroll
        for (int j = 0; j < 16; j++) {
            float w = l[j] * inv;
            const float* kpp = knnx + (t * 17 + 1 + j) * 3;
            nx += w * kpp[0]; ny += w * kpp[1]; nz += w * kpp[2];
        }
        float* po = out_new + (size_t)(bm0 + t) * 3;
        po[0] = nx; po[1] = ny; po[2] = nz;
    }
}

// ---------------- launch ---------------------------------------------------
extern "C" void kernel_launch(void* const* d_in, const int* in_sizes, int n_in,
                              void* d_out, int out_size) {
    const float* x      = (const float*)d_in[0];
    const float* gf     = (const float*)d_in[1];
    const float* c1_w1  = (const float*)d_in[2];
    const float* c1_b1  = (const float*)d_in[3];
    const float* c1_w2  = (const float*)d_in[4];
    const float* c1_b2  = (const float*)d_in[5];
    const float* cf_w1  = (const float*)d_in[6];
    const float* cf_b1  = (const float*)d_in[7];
    const float* cf_w2  = (const float*)d_in[8];
    const float* cf_b2  = (const float*)d_in[9];
    const float* cs_w1  = (const float*)d_in[10];
    const float* cs_b1  = (const float*)d_in[11];
    const float* cs_w2  = (const float*)d_in[12];
    const float* cs_b2  = (const float*)d_in[13];
    const float* s2_w1  = (const float*)d_in[14];
    const float* s2_b1  = (const float*)d_in[15];
    const float* s2_g1  = (const float*)d_in[16];
    const float* s2_bb1 = (const float*)d_in[17];
    const float* s2_w2  = (const float*)d_in[18];
    const float* s2_b2  = (const float*)d_in[19];
    const float* s2_g2  = (const float*)d_in[20];
    const float* s2_bb2 = (const float*)d_in[21];
    const float* s2_w3  = (const float*)d_in[22];
    const float* s2_b3  = (const float*)d_in[23];
    const float* q_w    = (const float*)d_in[24];
    const float* q_b    = (const float*)d_in[25];
    const float* k_w    = (const float*)d_in[26];
    const float* k_b    = (const float*)d_in[27];
    float* out = (float*)d_out;

    static bool s_init = false;
    static cudaStream_t st;
    static cudaEvent_t evF, evD;
    if (!s_init) {
        cudaStreamCreateWithFlags(&st, cudaStreamNonBlocking);
        cudaEventCreateWithFlags(&evF, cudaEventDisableTiming);
        cudaEventCreateWithFlags(&evD, cudaEventDisableTiming);
        cudaFuncSetAttribute(k_feat, cudaFuncAttributeMaxDynamicSharedMemorySize, (512 * FS + 96) * 4);
        cudaFuncSetAttribute(k_knn,  cudaFuncAttributeMaxDynamicSharedMemorySize, NP * 3 * 4);
        cudaFuncSetAttribute(k_fps,  cudaFuncAttributeMaxDynamicSharedMemorySize, NP * 3 * 4);
        cudaFuncSetAttribute(k_attn, cudaFuncAttributeMaxDynamicSharedMemorySize, 13236 * 4);
        s_init = true;
    }

    // fork for the geometric chain
    cudaEventRecord(evF, 0);
    cudaStreamWaitEvent(st, evF, 0);
    k_fps<<<BN, 1024, NP * 3 * 4, st>>>(x, out);                      // #1
    k_knn<<<(BN * MP) / 64, 64, NP * 3 * 4, st>>>(x);                 // #2
    cudaEventRecord(evD, st);

    // main stream
    k_prep<<<730, 256>>>(cs_w1, cs_w2, c1_w2,                         // #3
                         s2_w1, s2_b1, s2_g1, s2_bb1,
                         s2_w2, s2_b2, s2_g2, s2_bb2, s2_w3,
                         q_w, k_w, q_b, k_b,
                         gf, cf_w1, cf_b1, cf_w2, cf_b2);
    k_feat<<<(BN * NP) / 32, 256, (512 * FS + 96) * 4>>>(x,           // #4 <- profiled
        c1_w1, c1_b1, c1_b2, cs_b1, cs_b2);

    cudaStreamWaitEvent(0, evD, 0);
    k_attn<<<(BN * MP) / 2, 256, 13236 * 4>>>(x, s2_b3,               // #5
        out + (size_t)BN * MP * 3);
}

// round 8
// speedup vs baseline: 8.4236x; 1.0433x over previous
#include <cuda_runtime.h>
#include <math.h>

#define BN 8
#define NP 8192
#define MP 1024
#define KNB 17
#define FS 36   // transposed-row stride (floats), 16B-aligned

typedef unsigned long long ull;

// ---------------- scratch (device globals; no allocation) ----------------
__device__ float g_gvec[BN * 128];
__device__ float g_f2[BN * NP * 128];
__device__ float g_down[BN * MP * 3];
__device__ int   g_knn[BN * MP * KNB];
// transposed weights for feat: T[c*O + o] = W[o][c]
__device__ float g_csw1t[256 * 256];
__device__ float g_csw2t[256 * 128];
__device__ float g_c1w2t[64 * 128];
// per-batch folded cs1 bias: g_hg[b][o] = csb1[o] + sum_{c>=128} w[o][c]*gvec[b][c-128]
__device__ float g_hg[BN * 256];
// h2 dup-packed weights (bn prefolded): D[c2*128 + o*2 + j] = dup(w2f[o][2c2+j])
__device__ ull   g_s2w2d[64 * 64];
// r2 packed weights: P[(c4*128+o)*4+k] = w3[o][4c4+k]
__device__ float g_s2w3p[128 * 64];
// prefolded h1 weights/biases
__device__ float g_w1f[64 * 9];
__device__ float g_b1f[64];
__device__ float g_b2f[64];
// fused attention mats
__device__ float g_Ap[256 * 256];
__device__ float g_cvec[256];
__device__ float g_vb[256];
__device__ float g_s0[1];

__device__ __forceinline__ ull f2pk(float lo, float hi) {
    ull r; asm("mov.b64 %0,{%1,%2};" : "=l"(r) : "f"(lo), "f"(hi)); return r;
}
__device__ __forceinline__ void f2up(ull v, float& lo, float& hi) {
    asm("mov.b64 {%0,%1},%2;" : "=f"(lo), "=f"(hi) : "l"(v));
}
__device__ __forceinline__ ull addx2(ull a, ull b) {
    ull r; asm("add.rn.f32x2 %0,%1,%2;" : "=l"(r) : "l"(a), "l"(b)); return r;
}
__device__ __forceinline__ ull mulx2(ull a, ull b) {
    ull r; asm("mul.rn.f32x2 %0,%1,%2;" : "=l"(r) : "l"(a), "l"(b)); return r;
}
__device__ __forceinline__ ull fma2(ull a, ull b, ull c) {
    ull r; asm("fma.rn.f32x2 %0,%1,%2,%3;" : "=l"(r) : "l"(a), "l"(b), "l"(c)); return r;
}

// ---------------- prep ----------------------------------------------------
__device__ __forceinline__ void rp_t(const float* __restrict__ w, float* __restrict__ o,
                                     int O, int C, int blk) {
    int g = blk * 256 + threadIdx.x;
    if (g >= O * C) return;
    int c = g / O, oo = g - c * O;
    o[c * O + oo] = w[oo * C + c];
}

__global__ void k_prep(const float* __restrict__ cs_w1, const float* __restrict__ cs_w2,
                       const float* __restrict__ c1_w2,
                       const float* __restrict__ s2_w1, const float* __restrict__ s2_b1,
                       const float* __restrict__ s2_g1, const float* __restrict__ s2_bb1,
                       const float* __restrict__ s2_w2, const float* __restrict__ s2_b2,
                       const float* __restrict__ s2_g2, const float* __restrict__ s2_bb2,
                       const float* __restrict__ s2_w3,
                       const float* __restrict__ q_w, const float* __restrict__ k_w,
                       const float* __restrict__ q_b, const float* __restrict__ k_b,
                       const float* __restrict__ gf,
                       const float* __restrict__ cf_w1, const float* __restrict__ cf_b1,
                       const float* __restrict__ cf_w2, const float* __restrict__ cf_b2) {
    __shared__ float s_buf[512];
    __shared__ float s_h[256];
    __shared__ float s_red[8];
    const float bnc = 1.f / sqrtf(1.0f + 1e-5f);
    int blk = blockIdx.x, t = threadIdx.x;
    if (blk < 256)  { rp_t(cs_w1, g_csw1t, 256, 256, blk); return; }
    if (blk < 384)  { rp_t(cs_w2, g_csw2t, 128, 256, blk - 256); return; }
    if (blk < 416)  { rp_t(c1_w2, g_c1w2t, 128, 64, blk - 384); return; }
    if (blk < 432) {
        int g = (blk - 416) * 256 + t;   // 4096 elems: j=g&1, o=(g>>1)&63, c2=g>>7
        int j = g & 1, o = (g >> 1) & 63, c2 = g >> 7;
        float v = s2_w2[o * 64 + 2 * c2 + j] * (s2_g2[o] * bnc);
        g_s2w2d[g] = f2pk(v, v);
        return;
    }
    if (blk < 464) {
        int g = (blk - 432) * 256 + t;   // 8192 = 128x64
        int o = g >> 6, c = g & 63;
        g_s2w3p[((c >> 2) * 128 + o) * 4 + (c & 3)] = s2_w3[o * 64 + c];
        return;
    }
    if (blk < 720) {
        // row i of A = Wk^T Wq, plus c[i]
        int i = blk - 464;
        s_buf[t] = k_w[t * 256 + i];
        __syncthreads();
        float acc = 0.f;
        for (int o = 0; o < 256; o++) acc += s_buf[o] * __ldg(q_w + o * 256 + t);
        g_Ap[((t >> 2) * 256 + i) * 4 + (t & 3)] = acc;
        float part = s_buf[t] * q_b[t];
#pragma unroll
        for (int off = 16; off; off >>= 1) part += __shfl_down_sync(0xffffffffu, part, off);
        if ((t & 31) == 0) s_red[t >> 5] = part;
        __syncthreads();
        if (t == 0) { float s = 0.f; for (int w = 0; w < 8; w++) s += s_red[w]; g_cvec[i] = s; }
        return;
    }
    if (blk < 728) {
        // global-feature MLP: 512 -> 256 relu -> 128
        int b = blk - 720;
        for (int i = t; i < 512; i += 256) s_buf[i] = gf[b * 512 + i];
        __syncthreads();
        float a = cf_b1[t];
        const float* wr = cf_w1 + t * 512;
        for (int c = 0; c < 512; c++) a += wr[c] * s_buf[c];
        s_h[t] = fmaxf(a, 0.f);
        __syncthreads();
        if (t < 128) {
            float a2 = cf_b2[t];
            const float* w2r = cf_w2 + t * 256;
            for (int c = 0; c < 256; c++) a2 += w2r[c] * s_h[c];
            g_gvec[b * 128 + t] = a2;
        }
        return;
    }
    if (blk == 728) {
        float acc = 0.f;
        for (int o = 0; o < 256; o++) acc += __ldg(q_w + o * 256 + t) * k_b[o];
        g_vb[t] = acc;
        if (t == 0) {
            float s = 0.f;
            for (int o = 0; o < 256; o++) s += q_b[o] * k_b[o];
            g_s0[0] = s;
        }
        return;
    }
    // blk == 729: h1 prefold
    for (int i = t; i < 576; i += 256) {
        int o = i / 9;
        g_w1f[i] = s2_w1[i] * (s2_g1[o] * bnc);
    }
    if (t < 64) {
        g_b1f[t] = s2_b1[t] * (s2_g1[t] * bnc) + s2_bb1[t];
        g_b2f[t] = s2_b2[t] * (s2_g2[t] * bnc) + s2_bb2[t];
    }
}

// prep2: fold gvec through cs_w1 upper half into per-batch bias g_hg
__global__ void k_prep2(const float* __restrict__ csb1) {
    __shared__ float gv[128];
    int b = blockIdx.x, t = threadIdx.x;
    if (t < 128) gv[t] = g_gvec[b * 128 + t];
    __syncthreads();
    float acc = csb1[t];
    for (int c = 0; c < 128; c++) acc += g_csw1t[(128 + c) * 256 + t] * gv[c];
    g_hg[b * 256 + t] = acc;
}

// ---------------- fused c1 + cs MLP (cs1 halved via g_hg) -----------------
// 32 points per block; transposed channel-major smem [C][FS].
__global__ void __launch_bounds__(256) k_feat(const float* __restrict__ x,
                                              const float* __restrict__ c1w1,
                                              const float* __restrict__ c1b1,
                                              const float* __restrict__ c1b2,
                                              const float* __restrict__ csb2) {
    extern __shared__ __align__(16) float fm[];
    float* s_int = fm;                 // [128][FS]  c1 output
    float* s_ht  = fm + 128 * FS;      // [256][FS]  cs hidden (rows 0..63 alias c1 hidden)
    float* s_h64 = s_ht;
    float* s_xyz = fm + 384 * FS;
    int t = threadIdx.x;
    int base = blockIdx.x * 32;
    int b = base >> 13;
    if (t < 96) s_xyz[t] = x[(size_t)base * 3 + t];
    __syncthreads();
    // c1 layer1: 3 -> 64, relu
    for (int i = 0; i < 8; i++) {
        int task = t + 256 * i;
        int p = task & 31, o = task >> 5;
        float a = c1b1[o];
        a += c1w1[o * 3 + 0] * s_xyz[p * 3 + 0];
        a += c1w1[o * 3 + 1] * s_xyz[p * 3 + 1];
        a += c1w1[o * 3 + 2] * s_xyz[p * 3 + 2];
        s_h64[o * FS + p] = fmaxf(a, 0.f);
    }
    __syncthreads();
    // c1 layer2: 64 -> 128 -> s_int   (tile 4 outs x 4 pts)
    {
        int o0 = (t & 31) * 4, pg = t >> 5;
        ull acc[8];
#pragma unroll
        for (int i = 0; i < 8; i++) acc[i] = 0ull;
#pragma unroll 4
        for (int c = 0; c < 64; c++) {
            float4 w = *(const float4*)(g_c1w2t + c * 128 + o0);
            ull w0 = f2pk(w.x, w.x), w1 = f2pk(w.y, w.y);
            ull w2 = f2pk(w.z, w.z), w3 = f2pk(w.w, w.w);
            ulonglong2 v = *(const ulonglong2*)(s_h64 + c * FS + pg * 4);
            acc[0] = fma2(w0, v.x, acc[0]); acc[1] = fma2(w0, v.y, acc[1]);
            acc[2] = fma2(w1, v.x, acc[2]); acc[3] = fma2(w1, v.y, acc[3]);
            acc[4] = fma2(w2, v.x, acc[4]); acc[5] = fma2(w2, v.y, acc[5]);
            acc[6] = fma2(w3, v.x, acc[6]); acc[7] = fma2(w3, v.y, acc[7]);
        }
        float4 bq = *(const float4*)(c1b2 + o0);
        float bb[4] = { bq.x, bq.y, bq.z, bq.w };
        __syncthreads();
#pragma unroll
        for (int oi = 0; oi < 4; oi++) {
            ull bp = f2pk(bb[oi], bb[oi]);
            *(ull*)(s_int + (o0 + oi) * FS + pg * 4)     = addx2(acc[oi * 2], bp);
            *(ull*)(s_int + (o0 + oi) * FS + pg * 4 + 2) = addx2(acc[oi * 2 + 1], bp);
        }
    }
    __syncthreads();
    // cs layer1: 128 -> 256 (gvec part folded into g_hg), relu (tile 4x8)
    {
        int o0 = (t & 63) * 4, pg = t >> 6;
        ull acc[16];
#pragma unroll
        for (int i = 0; i < 16; i++) acc[i] = 0ull;
#pragma unroll 2
        for (int c = 0; c < 128; c++) {
            float4 w = *(const float4*)(g_csw1t + c * 256 + o0);
            ull w0 = f2pk(w.x, w.x), w1 = f2pk(w.y, w.y);
            ull w2 = f2pk(w.z, w.z), w3 = f2pk(w.w, w.w);
            ulonglong2 v01 = *(const ulonglong2*)(s_int + c * FS + pg * 8);
            ulonglong2 v23 = *(const ulonglong2*)(s_int + c * FS + pg * 8 + 4);
            acc[0]  = fma2(w0, v01.x, acc[0]);  acc[1]  = fma2(w0, v01.y, acc[1]);
            acc[2]  = fma2(w0, v23.x, acc[2]);  acc[3]  = fma2(w0, v23.y, acc[3]);
            acc[4]  = fma2(w1, v01.x, acc[4]);  acc[5]  = fma2(w1, v01.y, acc[5]);
            acc[6]  = fma2(w1, v23.x, acc[6]);  acc[7]  = fma2(w1, v23.y, acc[7]);
            acc[8]  = fma2(w2, v01.x, acc[8]);  acc[9]  = fma2(w2, v01.y, acc[9]);
            acc[10] = fma2(w2, v23.x, acc[10]); acc[11] = fma2(w2, v23.y, acc[11]);
            acc[12] = fma2(w3, v01.x, acc[12]); acc[13] = fma2(w3, v01.y, acc[13]);
            acc[14] = fma2(w3, v23.x, acc[14]); acc[15] = fma2(w3, v23.y, acc[15]);
        }
        float4 bq = *(const float4*)(g_hg + b * 256 + o0);
        float bb[4] = { bq.x, bq.y, bq.z, bq.w };
        __syncthreads();
#pragma unroll
        for (int oi = 0; oi < 4; oi++) {
#pragma unroll
            for (int g = 0; g < 4; g++) {
                float lo, hi; f2up(acc[oi * 4 + g], lo, hi);
                lo = fmaxf(lo + bb[oi], 0.f); hi = fmaxf(hi + bb[oi], 0.f);
                *(ull*)(s_ht + (o0 + oi) * FS + pg * 8 + g * 2) = f2pk(lo, hi);
            }
        }
    }
    __syncthreads();
    // cs layer2: 256 -> 128 -> g_f2 point-major (tile 4x4)
    {
        int o0 = (t & 31) * 4, pg = t >> 5;
        ull acc[8];
#pragma unroll
        for (int i = 0; i < 8; i++) acc[i] = 0ull;
#pragma unroll 2
        for (int c = 0; c < 256; c++) {
            float4 w = *(const float4*)(g_csw2t + c * 128 + o0);
            ull w0 = f2pk(w.x, w.x), w1 = f2pk(w.y, w.y);
            ull w2 = f2pk(w.z, w.z), w3 = f2pk(w.w, w.w);
            ulonglong2 v = *(const ulonglong2*)(s_ht + c * FS + pg * 4);
            acc[0] = fma2(w0, v.x, acc[0]); acc[1] = fma2(w0, v.y, acc[1]);
            acc[2] = fma2(w1, v.x, acc[2]); acc[3] = fma2(w1, v.y, acc[3]);
            acc[4] = fma2(w2, v.x, acc[4]); acc[5] = fma2(w2, v.y, acc[5]);
            acc[6] = fma2(w3, v.x, acc[6]); acc[7] = fma2(w3, v.y, acc[7]);
        }
        float4 bq = *(const float4*)(csb2 + o0);
        float bb[4] = { bq.x, bq.y, bq.z, bq.w };
#pragma unroll
        for (int pp = 0; pp < 4; pp++) {
            float4 val;
            float lo, hi;
            f2up(acc[0 + (pp >> 1)], lo, hi); val.x = ((pp & 1) ? hi : lo) + bb[0];
            f2up(acc[2 + (pp >> 1)], lo, hi); val.y = ((pp & 1) ? hi : lo) + bb[1];
            f2up(acc[4 + (pp >> 1)], lo, hi); val.z = ((pp & 1) ? hi : lo) + bb[2];
            f2up(acc[6 + (pp >> 1)], lo, hi); val.w = ((pp & 1) ? hi : lo) + bb[3];
            *(float4*)(g_f2 + (size_t)(base + pg * 4 + pp) * 128 + o0) = val;
        }
    }
}

// ---------------- FPS (bit-exact; SoA; ONE barrier per iteration) ---------
__global__ void __launch_bounds__(1024, 1) k_fps(const float* __restrict__ x,
                                                 float* __restrict__ out_down) {
    extern __shared__ float sp[];
    float* sxx = sp;
    float* syy = sp + NP;
    float* szz = sp + 2 * NP;
    __shared__ unsigned s_bv[2][32];
    __shared__ unsigned s_bi[2][32];
    int b = blockIdx.x, t = threadIdx.x, lane = t & 31, wid = t >> 5;
    const float* xb = x + (size_t)b * NP * 3;
    for (int i = t; i < NP; i += 1024) {
        sxx[i] = xb[3 * i]; syy[i] = xb[3 * i + 1]; szz[i] = xb[3 * i + 2];
    }
    __syncthreads();
    float cx = sxx[0], cy = syy[0], cz = szz[0];
    if (t == 0) {
        int o3 = b * MP * 3;
        g_down[o3 + 0] = cx; g_down[o3 + 1] = cy; g_down[o3 + 2] = cz;
        out_down[o3 + 0] = cx; out_down[o3 + 1] = cy; out_down[o3 + 2] = cz;
    }
    int base = t * 8;
    ull pxp[4], pyp[4], pzp[4];
    float md[8];
#pragma unroll
    for (int j = 0; j < 4; j++) {
        pxp[j] = *(const ull*)(sxx + base + 2 * j);
        pyp[j] = *(const ull*)(syy + base + 2 * j);
        pzp[j] = *(const ull*)(szz + base + 2 * j);
        md[2 * j] = 1e10f; md[2 * j + 1] = 1e10f;
    }
    int buf = 0;
    for (int it = 1; it < MP; it++) {
        ull ncx = f2pk(-cx, -cx), ncy = f2pk(-cy, -cy), ncz = f2pk(-cz, -cz);
#pragma unroll
        for (int j = 0; j < 4; j++) {
            ull dx = addx2(pxp[j], ncx);
            ull dy = addx2(pyp[j], ncy);
            ull dz = addx2(pzp[j], ncz);
            ull s = addx2(addx2(mulx2(dx, dx), mulx2(dy, dy)), mulx2(dz, dz));
            float lo, hi; f2up(s, lo, hi);
            md[2 * j]     = fminf(md[2 * j], lo);
            md[2 * j + 1] = fminf(md[2 * j + 1], hi);
        }
        float m01 = fmaxf(md[0], md[1]), m23 = fmaxf(md[2], md[3]);
        float m45 = fmaxf(md[4], md[5]), m67 = fmaxf(md[6], md[7]);
        float m = fmaxf(fmaxf(m01, m23), fmaxf(m45, m67));
        unsigned wm = __reduce_max_sync(0xffffffffu, __float_as_uint(m));
        unsigned li = 0xffffffffu;
#pragma unroll
        for (int j = 7; j >= 0; j--)
            li = (__float_as_uint(md[j]) == wm) ? (unsigned)(base + j) : li;
        unsigned wi = __reduce_min_sync(0xffffffffu, li);
        if (lane == 0) { s_bv[buf][wid] = wm; s_bi[buf][wid] = wi; }
        __syncthreads();
        unsigned v = s_bv[buf][lane];
        unsigned gm = __reduce_max_sync(0xffffffffu, v);
        unsigned cand = (v == gm) ? s_bi[buf][lane] : 0xffffffffu;
        unsigned gi = __reduce_min_sync(0xffffffffu, cand);
        cx = sxx[gi]; cy = syy[gi]; cz = szz[gi];
        if (t == 0) {
            int o3 = (b * MP + it) * 3;
            g_down[o3 + 0] = cx; g_down[o3 + 1] = cy; g_down[o3 + 2] = cz;
            out_down[o3 + 0] = cx; out_down[o3 + 1] = cy; out_down[o3 + 2] = cz;
        }
        buf ^= 1;
    }
}

// ---------------- KNN top-17 (stable; SoA; f32x2 pair per iter) -----------
__global__ void __launch_bounds__(64) k_knn(const float* __restrict__ x) {
    extern __shared__ float kp[];
    float* sxx = kp;
    float* syy = kp + NP;
    float* szz = kp + 2 * NP;
    int gid = blockIdx.x * 64 + threadIdx.x;
    int b = gid >> 10;
    const float* xb = x + (size_t)b * NP * 3;
    for (int i = threadIdx.x; i < NP; i += 64) {
        sxx[i] = xb[3 * i]; syy[i] = xb[3 * i + 1]; szz[i] = xb[3 * i + 2];
    }
    __syncthreads();
    float qx = g_down[gid * 3 + 0], qy = g_down[gid * 3 + 1], qz = g_down[gid * 3 + 2];
    float sd = __fadd_rn(__fadd_rn(__fmul_rn(qx, qx), __fmul_rn(qy, qy)), __fmul_rn(qz, qz));
    ull qxp = f2pk(qx, qx), qyp = f2pk(qy, qy), qzp = f2pk(qz, qz);
    ull sdp = f2pk(sd, sd), n2p = f2pk(-2.f, -2.f);
    float dist[17]; int ind[17];
#pragma unroll
    for (int i = 0; i < 17; i++) { dist[i] = 3.4e38f; ind[i] = 0; }
    for (int n = 0; n < NP; n += 2) {
        ull axp = *(const ull*)(sxx + n);
        ull ayp = *(const ull*)(syy + n);
        ull azp = *(const ull*)(szz + n);
        ull sn = addx2(addx2(mulx2(axp, axp), mulx2(ayp, ayp)), mulx2(azp, azp));
        ull dt = addx2(addx2(mulx2(qxp, axp), mulx2(qyp, ayp)), mulx2(qzp, azp));
        ull d2p = addx2(addx2(sdp, sn), mulx2(n2p, dt));
        float dlo, dhi; f2up(d2p, dlo, dhi);
#pragma unroll
        for (int h = 0; h < 2; h++) {
            float d2 = h ? dhi : dlo;
            int ni = n + h;
            if (d2 < dist[16]) {
                int pos = 0;
#pragma unroll
                for (int s = 0; s < 17; s++) pos += (dist[s] <= d2) ? 1 : 0;
#pragma unroll
                for (int s = 16; s > 0; s--) {
                    if (s > pos) { dist[s] = dist[s - 1]; ind[s] = ind[s - 1]; }
                    else if (s == pos) { dist[s] = d2; ind[s] = ni; }
                }
                if (pos == 0) { dist[0] = d2; ind[0] = ni; }
            }
        }
    }
#pragma unroll
    for (int s = 0; s < 17; s++) g_knn[(size_t)gid * 17 + s] = ind[s];
}

// ---------------- attention (G=2; r2 only for query rows; z-trick) --------
// logit_mj = u_lo.knnf_j + z_m.h2_j + u_hi.b3 + vb.f_m0 + s0
__global__ void __launch_bounds__(256) k_attn(
    const float* __restrict__ x,
    const float* __restrict__ w3, const float* __restrict__ b3,
    float* __restrict__ out_new)
{
    extern __shared__ __align__(16) float sm[];
    float* feat = sm;                  // [34][128] knnf
    float* h1i  = sm + 4352;           // [17][128]  pair-interleaved
    float* h2i  = sm + 6528;           // [17][128]
    float* fr2  = sm + 8704;           // [2][128]
    float* us   = sm + 8960;           // [2][256]
    float* zs   = sm + 9472;           // [2][64][2]
    float* knnx = sm + 9728;           // 102
    float* dwn  = sm + 9830;           // 6
    float* lgA  = sm + 9836;           // 32
    float* lgB  = sm + 9868;           // 2
    float* lgC  = sm + 9870;           // 2
    int*   sidx = (int*)(sm + 9872);   // 34

    int t = threadIdx.x;
    int wid = t >> 5, lane = t & 31;
    int bm0 = blockIdx.x * 2;
    int b = bm0 >> 10;
    const float* xb = x + (size_t)b * NP * 3;

    if (t < 34) {
        int id = g_knn[(size_t)bm0 * 17 + t];
        sidx[t] = id;
        knnx[t * 3 + 0] = xb[id * 3 + 0];
        knnx[t * 3 + 1] = xb[id * 3 + 1];
        knnx[t * 3 + 2] = xb[id * 3 + 2];
    }
    if (t < 6) dwn[t] = g_down[(size_t)bm0 * 3 + t];
    __syncthreads();

    // gather knn_f
    for (int r = wid; r < 34; r += 8) {
        const float4* src = (const float4*)(g_f2 + ((size_t)(b * NP) + sidx[r]) * 128);
        ((float4*)(feat + r * 128))[lane] = src[lane];
    }

    // h1: 9 -> 64 (prefolded bn), leaky, pair-interleaved store
    for (int i = 0; i < 9; i++) {
        int task = t + 256 * i;
        if (task < 2176) {
            int o = task & 63, row = task >> 6;
            int j = (row >= 17) ? 1 : 0;
            int pr = row - 17 * j;
            const float* kpp = knnx + row * 3;
            const float* dp = dwn + j * 3;
            float r0 = dp[0], r1 = dp[1], r2v = dp[2];
            float r3 = kpp[0], r4 = kpp[1], r5 = kpp[2];
            const float* w = g_w1f + o * 9;
            float a = g_b1f[o];
            a += w[0] * r0 + w[1] * r1 + w[2] * r2v;
            a += w[3] * r3 + w[4] * r4 + w[5] * r5;
            a += w[6] * (r0 - r3) + w[7] * (r1 - r4) + w[8] * (r2v - r5);
            a = a > 0.f ? a : 0.01f * a;
            h1i[pr * 128 + o * 2 + j] = a;
        }
    }
    __syncthreads();
    // h2: 64 -> 64 via f32x2 row-pairs; tasks (prow, 2 outs)
    {
        const ulonglong2* w2d = (const ulonglong2*)g_s2w2d;
        for (int i = 0; i < 3; i++) {
            int task = t + 256 * i;
            if (task < 544) {
                int prow = task >> 5, o = task & 31;
                int o2 = o + 32;
                const ulonglong2* hv = (const ulonglong2*)(h1i + prow * 128);
                float ba = g_b2f[o], bb2v = g_b2f[o2];
                ull accA = f2pk(ba, ba), accB = f2pk(bb2v, bb2v);
#pragma unroll 4
                for (int c2 = 0; c2 < 32; c2++) {
                    ulonglong2 v = hv[c2];
                    ulonglong2 wA = w2d[c2 * 64 + o];
                    ulonglong2 wB = w2d[c2 * 64 + o2];
                    accA = fma2(wA.x, v.x, accA); accA = fma2(wA.y, v.y, accA);
                    accB = fma2(wB.x, v.x, accB); accB = fma2(wB.y, v.y, accB);
                }
                float a0, a1; f2up(accA, a0, a1);
                a0 = a0 > 0.f ? a0 : 0.01f * a0;
                a1 = a1 > 0.f ? a1 : 0.01f * a1;
                h2i[prow * 128 + o * 2]     = a0;
                h2i[prow * 128 + o * 2 + 1] = a1;
                f2up(accB, a0, a1);
                a0 = a0 > 0.f ? a0 : 0.01f * a0;
                a1 = a1 > 0.f ? a1 : 0.01f * a1;
                h2i[prow * 128 + o2 * 2]     = a0;
                h2i[prow * 128 + o2 * 2 + 1] = a1;
            }
        }
    }
    __syncthreads();
    // r2 only for query rows (prow 0 pair): 256 tasks
    {
        int mi = t >> 7, o = t & 127;
        const ulonglong2* hc2 = (const ulonglong2*)h2i;   // prow 0 base
        float acc = b3[o];
#pragma unroll 4
        for (int c4 = 0; c4 < 16; c4++) {
            float4 w = ((const float4*)g_s2w3p)[c4 * 128 + o];
            ulonglong2 p0 = hc2[2 * c4], p1 = hc2[2 * c4 + 1];
            float l0, h0v, l1, h1v, l2, h2v, l3, h3v;
            f2up(p0.x, l0, h0v); f2up(p0.y, l1, h1v);
            f2up(p1.x, l2, h2v); f2up(p1.y, l3, h3v);
            float v0 = mi ? h0v : l0, v1 = mi ? h1v : l1;
            float v2 = mi ? h2v : l2, v3 = mi ? h3v : l3;
            acc += w.x * v0 + w.y * v1 + w.z * v2 + w.w * v3;
        }
        fr2[mi * 128 + o] = acc;
    }
    __syncthreads();
    // u_m = A f_m0 + c   (f_m0 = [feat row mi*17 ; fr2 row mi])
    {
        const float4* ap = (const float4*)g_Ap;
        float a0 = 0.f, a1 = 0.f;
        for (int c4 = 0; c4 < 32; c4++) {
            float4 w = ap[c4 * 256 + t];
            float4 v0 = *(const float4*)(feat + c4 * 4);             // row 0
            float4 v1 = *(const float4*)(feat + 17 * 128 + c4 * 4);  // row 17
            a0 += w.x * v0.x + w.y * v0.y + w.z * v0.z + w.w * v0.w;
            a1 += w.x * v1.x + w.y * v1.y + w.z * v1.z + w.w * v1.w;
        }
        for (int c4 = 0; c4 < 32; c4++) {
            float4 w = ap[(32 + c4) * 256 + t];
            float4 v0 = *(const float4*)(fr2 + c4 * 4);
            float4 v1 = *(const float4*)(fr2 + 128 + c4 * 4);
            a0 += w.x * v0.x + w.y * v0.y + w.z * v0.z + w.w * v0.w;
            a1 += w.x * v1.x + w.y * v1.y + w.z * v1.z + w.w * v1.w;
        }
        float cv = g_cvec[t];
        us[t] = a0 + cv;
        us[256 + t] = a1 + cv;
    }
    __syncthreads();
    // z_m = W3^T u_hi (split o-halves): 256 tasks
    {
        int mi = t >> 7, rem = t & 127, c = rem >> 1, oh = rem & 1;
        const float* ur = us + mi * 256 + 128 + oh * 64;
        float acc = 0.f;
#pragma unroll 4
        for (int o = 0; o < 64; o++) acc += __ldg(w3 + (oh * 64 + o) * 64 + c) * ur[o];
        zs[(mi * 64 + c) * 2 + oh] = acc;
    }
    __syncthreads();
    // logits: 32 typeA + 2 typeB + 2 typeC
    for (int task = wid; task < 36; task += 8) {
        float s = 0.f;
        if (task < 32) {
            int mi = task >> 4, j = task & 15;
            const float* uf = us + mi * 256;
            const float* fr = feat + (mi * 17 + 1 + j) * 128;
#pragma unroll
            for (int k = 0; k < 4; k++) { int o = lane + 32 * k; s += uf[o] * fr[o]; }
            const float* hj = h2i + (1 + j) * 128;
#pragma unroll
            for (int k = 0; k < 2; k++) {
                int c = lane + 32 * k;
                s += (zs[(mi * 64 + c) * 2] + zs[(mi * 64 + c) * 2 + 1]) * hj[c * 2 + mi];
            }
        } else if (task < 34) {
            int mi = task - 32;
            const float* fl = feat + mi * 17 * 128;
            const float* fh = fr2 + mi * 128;
#pragma unroll
            for (int k = 0; k < 4; k++) {
                int o = lane + 32 * k;
                s += __ldg(&g_vb[o]) * fl[o] + __ldg(&g_vb[128 + o]) * fh[o];
            }
        } else {
            int mi = task - 34;
            const float* uh = us + mi * 256 + 128;
#pragma unroll
            for (int k = 0; k < 4; k++) { int o = lane + 32 * k; s += uh[o] * __ldg(b3 + o); }
        }
#pragma unroll
        for (int off = 16; off; off >>= 1) s += __shfl_down_sync(0xffffffffu, s, off);
        if (lane == 0) {
            if (task < 32) lgA[task] = s;
            else if (task < 34) lgB[task - 32] = s;
            else lgC[task - 34] = s;
        }
    }
    __syncthreads();

    // softmax + weighted neighbor sum
    if (t < 2) {
        float ex = lgB[t] + lgC[t] + g_s0[0];
        float l[16], mx = -3.4e38f;
#pragma unroll
        for (int j = 0; j < 16; j++) { l[j] = lgA[t * 16 + j] + ex; mx = fmaxf(mx, l[j]); }
        float sum = 0.f;
#pragma unroll
        for (int j = 0; j < 16; j++) { l[j] = expf(l[j] - mx); sum += l[j]; }
        float inv = 1.f / sum;
        float nx = 0.f, ny = 0.f, nz = 0.f;
#pragma unroll
        for (int j = 0; j < 16; j++) {
            float w = l[j] * inv;
            const float* kpp = knnx + (t * 17 + 1 + j) * 3;
            nx += w * kpp[0]; ny += w * kpp[1]; nz += w * kpp[2];
        }
        float* po = out_new + (size_t)(bm0 + t) * 3;
        po[0] = nx; po[1] = ny; po[2] = nz;
    }
}

// ---------------- launch ---------------------------------------------------
extern "C" void kernel_launch(void* const* d_in, const int* in_sizes, int n_in,
                              void* d_out, int out_size) {
    const float* x      = (const float*)d_in[0];
    const float* gf     = (const float*)d_in[1];
    const float* c1_w1  = (const float*)d_in[2];
    const float* c1_b1  = (const float*)d_in[3];
    const float* c1_w2  = (const float*)d_in[4];
    const float* c1_b2  = (const float*)d_in[5];
    const float* cf_w1  = (const float*)d_in[6];
    const float* cf_b1  = (const float*)d_in[7];
    const float* cf_w2  = (const float*)d_in[8];
    const float* cf_b2  = (const float*)d_in[9];
    const float* cs_w1  = (const float*)d_in[10];
    const float* cs_b1  = (const float*)d_in[11];
    const float* cs_w2  = (const float*)d_in[12];
    const float* cs_b2  = (const float*)d_in[13];
    const float* s2_w1  = (const float*)d_in[14];
    const float* s2_b1  = (const float*)d_in[15];
    const float* s2_g1  = (const float*)d_in[16];
    const float* s2_bb1 = (const float*)d_in[17];
    const float* s2_w2  = (const float*)d_in[18];
    const float* s2_b2  = (const float*)d_in[19];
    const float* s2_g2  = (const float*)d_in[20];
    const float* s2_bb2 = (const float*)d_in[21];
    const float* s2_w3  = (const float*)d_in[22];
    const float* s2_b3  = (const float*)d_in[23];
    const float* q_w    = (const float*)d_in[24];
    const float* q_b    = (const float*)d_in[25];
    const float* k_w    = (const float*)d_in[26];
    const float* k_b    = (const float*)d_in[27];
    float* out = (float*)d_out;

    static bool s_init = false;
    static cudaStream_t st;
    static cudaEvent_t evF, evD;
    const int FEAT_SMEM = (384 * FS + 96) * 4;
    const int ATTN_SMEM = 9920 * 4;
    if (!s_init) {
        cudaStreamCreateWithFlags(&st, cudaStreamNonBlocking);
        cudaEventCreateWithFlags(&evF, cudaEventDisableTiming);
        cudaEventCreateWithFlags(&evD, cudaEventDisableTiming);
        cudaFuncSetAttribute(k_feat, cudaFuncAttributeMaxDynamicSharedMemorySize, FEAT_SMEM);
        cudaFuncSetAttribute(k_knn,  cudaFuncAttributeMaxDynamicSharedMemorySize, NP * 3 * 4);
        cudaFuncSetAttribute(k_fps,  cudaFuncAttributeMaxDynamicSharedMemorySize, NP * 3 * 4);
        cudaFuncSetAttribute(k_attn, cudaFuncAttributeMaxDynamicSharedMemorySize, ATTN_SMEM);
        s_init = true;
    }

    // fork for the geometric chain
    cudaEventRecord(evF, 0);
    cudaStreamWaitEvent(st, evF, 0);
    k_fps<<<BN, 1024, NP * 3 * 4, st>>>(x, out);                      // #1

    // main stream
    k_prep<<<730, 256>>>(cs_w1, cs_w2, c1_w2,                         // #2
                         s2_w1, s2_b1, s2_g1, s2_bb1,
                         s2_w2, s2_b2, s2_g2, s2_bb2, s2_w3,
                         q_w, k_w, q_b, k_b,
                         gf, cf_w1, cf_b1, cf_w2, cf_b2);
    k_prep2<<<BN, 256>>>(cs_b1);                                      // #3
    k_feat<<<(BN * NP) / 32, 256, FEAT_SMEM>>>(x,                     // #4 <- profiled
        c1_w1, c1_b1, c1_b2, cs_b2);

    k_knn<<<(BN * MP) / 64, 64, NP * 3 * 4, st>>>(x);                 // #5 (side)
    cudaEventRecord(evD, st);
    cudaStreamWaitEvent(0, evD, 0);
    k_attn<<<(BN * MP) / 2, 256, ATTN_SMEM>>>(x, s2_w3, s2_b3,        // #6
        out + (size_t)BN * MP * 3);
}

// round 9
// speedup vs baseline: 10.3815x; 1.2324x over previous
#include <cuda_runtime.h>
#include <math.h>

#define BN 8
#define NP 8192
#define MP 1024
#define KNB 17
#define FS 36   // transposed-row stride (floats), 16B-aligned

typedef unsigned long long ull;

// ---------------- scratch (device globals; no allocation) ----------------
__device__ float g_gvec[BN * 128];
__device__ float g_f2[BN * NP * 128];
__device__ float g_down[BN * MP * 3];
__device__ int   g_knn[BN * MP * KNB];
// transposed weights for feat: T[c*O + o] = W[o][c]
__device__ float g_csw1t[256 * 256];
__device__ float g_csw2t[256 * 128];
__device__ float g_c1w2t[64 * 128];
// per-batch folded cs1 bias
__device__ float g_hg[BN * 256];
// h2 dup-packed weights (bn prefolded)
__device__ ull   g_s2w2d[64 * 64];
// r2 packed weights
__device__ float g_s2w3p[128 * 64];
// prefolded h1 weights/biases
__device__ float g_w1f[64 * 9];
__device__ float g_b1f[64];
__device__ float g_b2f[64];
// fused attention mats
__device__ float g_Ap[256 * 256];
__device__ float g_cvec[256];
__device__ float g_vb[256];
__device__ float g_s0[1];

__device__ __forceinline__ ull f2pk(float lo, float hi) {
    ull r; asm("mov.b64 %0,{%1,%2};" : "=l"(r) : "f"(lo), "f"(hi)); return r;
}
__device__ __forceinline__ void f2up(ull v, float& lo, float& hi) {
    asm("mov.b64 {%0,%1},%2;" : "=f"(lo), "=f"(hi) : "l"(v));
}
__device__ __forceinline__ ull addx2(ull a, ull b) {
    ull r; asm("add.rn.f32x2 %0,%1,%2;" : "=l"(r) : "l"(a), "l"(b)); return r;
}
__device__ __forceinline__ ull mulx2(ull a, ull b) {
    ull r; asm("mul.rn.f32x2 %0,%1,%2;" : "=l"(r) : "l"(a), "l"(b)); return r;
}
__device__ __forceinline__ ull fma2(ull a, ull b, ull c) {
    ull r; asm("fma.rn.f32x2 %0,%1,%2,%3;" : "=l"(r) : "l"(a), "l"(b), "l"(c)); return r;
}

// ---------------- prep ----------------------------------------------------
__device__ __forceinline__ void rp_t(const float* __restrict__ w, float* __restrict__ o,
                                     int O, int C, int blk) {
    int g = blk * 256 + threadIdx.x;
    if (g >= O * C) return;
    int c = g / O, oo = g - c * O;
    o[c * O + oo] = w[oo * C + c];
}

__global__ void k_prep(const float* __restrict__ cs_w1, const float* __restrict__ cs_w2,
                       const float* __restrict__ c1_w2,
                       const float* __restrict__ s2_w1, const float* __restrict__ s2_b1,
                       const float* __restrict__ s2_g1, const float* __restrict__ s2_bb1,
                       const float* __restrict__ s2_w2, const float* __restrict__ s2_b2,
                       const float* __restrict__ s2_g2, const float* __restrict__ s2_bb2,
                       const float* __restrict__ s2_w3,
                       const float* __restrict__ q_w, const float* __restrict__ k_w,
                       const float* __restrict__ q_b, const float* __restrict__ k_b,
                       const float* __restrict__ gf,
                       const float* __restrict__ cf_w1, const float* __restrict__ cf_b1,
                       const float* __restrict__ cf_w2, const float* __restrict__ cf_b2) {
    __shared__ float s_buf[512];
    __shared__ float s_h[256];
    __shared__ float s_red[8];
    const float bnc = 1.f / sqrtf(1.0f + 1e-5f);
    int blk = blockIdx.x, t = threadIdx.x;
    if (blk < 256)  { rp_t(cs_w1, g_csw1t, 256, 256, blk); return; }
    if (blk < 384)  { rp_t(cs_w2, g_csw2t, 128, 256, blk - 256); return; }
    if (blk < 416)  { rp_t(c1_w2, g_c1w2t, 128, 64, blk - 384); return; }
    if (blk < 432) {
        int g = (blk - 416) * 256 + t;
        int j = g & 1, o = (g >> 1) & 63, c2 = g >> 7;
        float v = s2_w2[o * 64 + 2 * c2 + j] * (s2_g2[o] * bnc);
        g_s2w2d[g] = f2pk(v, v);
        return;
    }
    if (blk < 464) {
        int g = (blk - 432) * 256 + t;
        int o = g >> 6, c = g & 63;
        g_s2w3p[((c >> 2) * 128 + o) * 4 + (c & 3)] = s2_w3[o * 64 + c];
        return;
    }
    if (blk < 720) {
        int i = blk - 464;
        s_buf[t] = k_w[t * 256 + i];
        __syncthreads();
        float acc = 0.f;
        for (int o = 0; o < 256; o++) acc += s_buf[o] * __ldg(q_w + o * 256 + t);
        g_Ap[((t >> 2) * 256 + i) * 4 + (t & 3)] = acc;
        float part = s_buf[t] * q_b[t];
#pragma unroll
        for (int off = 16; off; off >>= 1) part += __shfl_down_sync(0xffffffffu, part, off);
        if ((t & 31) == 0) s_red[t >> 5] = part;
        __syncthreads();
        if (t == 0) { float s = 0.f; for (int w = 0; w < 8; w++) s += s_red[w]; g_cvec[i] = s; }
        return;
    }
    if (blk < 728) {
        int b = blk - 720;
        for (int i = t; i < 512; i += 256) s_buf[i] = gf[b * 512 + i];
        __syncthreads();
        float a = cf_b1[t];
        const float* wr = cf_w1 + t * 512;
        for (int c = 0; c < 512; c++) a += wr[c] * s_buf[c];
        s_h[t] = fmaxf(a, 0.f);
        __syncthreads();
        if (t < 128) {
            float a2 = cf_b2[t];
            const float* w2r = cf_w2 + t * 256;
            for (int c = 0; c < 256; c++) a2 += w2r[c] * s_h[c];
            g_gvec[b * 128 + t] = a2;
        }
        return;
    }
    if (blk == 728) {
        float acc = 0.f;
        for (int o = 0; o < 256; o++) acc += __ldg(q_w + o * 256 + t) * k_b[o];
        g_vb[t] = acc;
        if (t == 0) {
            float s = 0.f;
            for (int o = 0; o < 256; o++) s += q_b[o] * k_b[o];
            g_s0[0] = s;
        }
        return;
    }
    for (int i = t; i < 576; i += 256) {
        int o = i / 9;
        g_w1f[i] = s2_w1[i] * (s2_g1[o] * bnc);
    }
    if (t < 64) {
        g_b1f[t] = s2_b1[t] * (s2_g1[t] * bnc) + s2_bb1[t];
        g_b2f[t] = s2_b2[t] * (s2_g2[t] * bnc) + s2_bb2[t];
    }
}

// prep2: fold gvec through cs_w1 upper half into per-batch bias g_hg
__global__ void k_prep2(const float* __restrict__ csb1) {
    __shared__ float gv[128];
    int b = blockIdx.x, t = threadIdx.x;
    if (t < 128) gv[t] = g_gvec[b * 128 + t];
    __syncthreads();
    float acc = csb1[t];
    for (int c = 0; c < 128; c++) acc += g_csw1t[(128 + c) * 256 + t] * gv[c];
    g_hg[b * 256 + t] = acc;
}

// ---------------- fused c1 + cs MLP (unchanged from R8) -------------------
__global__ void __launch_bounds__(256) k_feat(const float* __restrict__ x,
                                              const float* __restrict__ c1w1,
                                              const float* __restrict__ c1b1,
                                              const float* __restrict__ c1b2,
                                              const float* __restrict__ csb2) {
    extern __shared__ __align__(16) float fm[];
    float* s_int = fm;                 // [128][FS]
    float* s_ht  = fm + 128 * FS;      // [256][FS]
    float* s_h64 = s_ht;
    float* s_xyz = fm + 384 * FS;
    int t = threadIdx.x;
    int base = blockIdx.x * 32;
    int b = base >> 13;
    if (t < 96) s_xyz[t] = x[(size_t)base * 3 + t];
    __syncthreads();
    for (int i = 0; i < 8; i++) {
        int task = t + 256 * i;
        int p = task & 31, o = task >> 5;
        float a = c1b1[o];
        a += c1w1[o * 3 + 0] * s_xyz[p * 3 + 0];
        a += c1w1[o * 3 + 1] * s_xyz[p * 3 + 1];
        a += c1w1[o * 3 + 2] * s_xyz[p * 3 + 2];
        s_h64[o * FS + p] = fmaxf(a, 0.f);
    }
    __syncthreads();
    {
        int o0 = (t & 31) * 4, pg = t >> 5;
        ull acc[8];
#pragma unroll
        for (int i = 0; i < 8; i++) acc[i] = 0ull;
#pragma unroll 4
        for (int c = 0; c < 64; c++) {
            float4 w = *(const float4*)(g_c1w2t + c * 128 + o0);
            ull w0 = f2pk(w.x, w.x), w1 = f2pk(w.y, w.y);
            ull w2 = f2pk(w.z, w.z), w3 = f2pk(w.w, w.w);
            ulonglong2 v = *(const ulonglong2*)(s_h64 + c * FS + pg * 4);
            acc[0] = fma2(w0, v.x, acc[0]); acc[1] = fma2(w0, v.y, acc[1]);
            acc[2] = fma2(w1, v.x, acc[2]); acc[3] = fma2(w1, v.y, acc[3]);
            acc[4] = fma2(w2, v.x, acc[4]); acc[5] = fma2(w2, v.y, acc[5]);
            acc[6] = fma2(w3, v.x, acc[6]); acc[7] = fma2(w3, v.y, acc[7]);
        }
        float4 bq = *(const float4*)(c1b2 + o0);
        float bb[4] = { bq.x, bq.y, bq.z, bq.w };
        __syncthreads();
#pragma unroll
        for (int oi = 0; oi < 4; oi++) {
            ull bp = f2pk(bb[oi], bb[oi]);
            *(ull*)(s_int + (o0 + oi) * FS + pg * 4)     = addx2(acc[oi * 2], bp);
            *(ull*)(s_int + (o0 + oi) * FS + pg * 4 + 2) = addx2(acc[oi * 2 + 1], bp);
        }
    }
    __syncthreads();
    {
        int o0 = (t & 63) * 4, pg = t >> 6;
        ull acc[16];
#pragma unroll
        for (int i = 0; i < 16; i++) acc[i] = 0ull;
#pragma unroll 2
        for (int c = 0; c < 128; c++) {
            float4 w = *(const float4*)(g_csw1t + c * 256 + o0);
            ull w0 = f2pk(w.x, w.x), w1 = f2pk(w.y, w.y);
            ull w2 = f2pk(w.z, w.z), w3 = f2pk(w.w, w.w);
            ulonglong2 v01 = *(const ulonglong2*)(s_int + c * FS + pg * 8);
            ulonglong2 v23 = *(const ulonglong2*)(s_int + c * FS + pg * 8 + 4);
            acc[0]  = fma2(w0, v01.x, acc[0]);  acc[1]  = fma2(w0, v01.y, acc[1]);
            acc[2]  = fma2(w0, v23.x, acc[2]);  acc[3]  = fma2(w0, v23.y, acc[3]);
            acc[4]  = fma2(w1, v01.x, acc[4]);  acc[5]  = fma2(w1, v01.y, acc[5]);
            acc[6]  = fma2(w1, v23.x, acc[6]);  acc[7]  = fma2(w1, v23.y, acc[7]);
            acc[8]  = fma2(w2, v01.x, acc[8]);  acc[9]  = fma2(w2, v01.y, acc[9]);
            acc[10] = fma2(w2, v23.x, acc[10]); acc[11] = fma2(w2, v23.y, acc[11]);
            acc[12] = fma2(w3, v01.x, acc[12]); acc[13] = fma2(w3, v01.y, acc[13]);
            acc[14] = fma2(w3, v23.x, acc[14]); acc[15] = fma2(w3, v23.y, acc[15]);
        }
        float4 bq = *(const float4*)(g_hg + b * 256 + o0);
        float bb[4] = { bq.x, bq.y, bq.z, bq.w };
        __syncthreads();
#pragma unroll
        for (int oi = 0; oi < 4; oi++) {
#pragma unroll
            for (int g = 0; g < 4; g++) {
                float lo, hi; f2up(acc[oi * 4 + g], lo, hi);
                lo = fmaxf(lo + bb[oi], 0.f); hi = fmaxf(hi + bb[oi], 0.f);
                *(ull*)(s_ht + (o0 + oi) * FS + pg * 8 + g * 2) = f2pk(lo, hi);
            }
        }
    }
    __syncthreads();
    {
        int o0 = (t & 31) * 4, pg = t >> 5;
        ull acc[8];
#pragma unroll
        for (int i = 0; i < 8; i++) acc[i] = 0ull;
#pragma unroll 2
        for (int c = 0; c < 256; c++) {
            float4 w = *(const float4*)(g_csw2t + c * 128 + o0);
            ull w0 = f2pk(w.x, w.x), w1 = f2pk(w.y, w.y);
            ull w2 = f2pk(w.z, w.z), w3 = f2pk(w.w, w.w);
            ulonglong2 v = *(const ulonglong2*)(s_ht + c * FS + pg * 4);
            acc[0] = fma2(w0, v.x, acc[0]); acc[1] = fma2(w0, v.y, acc[1]);
            acc[2] = fma2(w1, v.x, acc[2]); acc[3] = fma2(w1, v.y, acc[3]);
            acc[4] = fma2(w2, v.x, acc[4]); acc[5] = fma2(w2, v.y, acc[5]);
            acc[6] = fma2(w3, v.x, acc[6]); acc[7] = fma2(w3, v.y, acc[7]);
        }
        float4 bq = *(const float4*)(csb2 + o0);
        float bb[4] = { bq.x, bq.y, bq.z, bq.w };
#pragma unroll
        for (int pp = 0; pp < 4; pp++) {
            float4 val;
            float lo, hi;
            f2up(acc[0 + (pp >> 1)], lo, hi); val.x = ((pp & 1) ? hi : lo) + bb[0];
            f2up(acc[2 + (pp >> 1)], lo, hi); val.y = ((pp & 1) ? hi : lo) + bb[1];
            f2up(acc[4 + (pp >> 1)], lo, hi); val.z = ((pp & 1) ? hi : lo) + bb[2];
            f2up(acc[6 + (pp >> 1)], lo, hi); val.w = ((pp & 1) ? hi : lo) + bb[3];
            *(float4*)(g_f2 + (size_t)(base + pg * 4 + pp) * 128 + o0) = val;
        }
    }
}

// ---------------- FPS v3: 512 thr x 16 pts; match-gated index path --------
__global__ void __launch_bounds__(512, 1) k_fps(const float* __restrict__ x,
                                                float* __restrict__ out_down) {
    extern __shared__ float sp[];
    float* sxx = sp;
    float* syy = sp + NP;
    float* szz = sp + 2 * NP;
    __shared__ unsigned s_bv[2][16];
    __shared__ unsigned s_gi[2];
    int b = blockIdx.x, t = threadIdx.x, lane = t & 31, wid = t >> 5;
    const float* xb = x + (size_t)b * NP * 3;
    for (int i = t; i < NP; i += 512) {
        sxx[i] = xb[3 * i]; syy[i] = xb[3 * i + 1]; szz[i] = xb[3 * i + 2];
    }
    if (t == 0) { s_gi[0] = 0xFFFFFFFFu; s_gi[1] = 0xFFFFFFFFu; }
    __syncthreads();
    float cx = sxx[0], cy = syy[0], cz = szz[0];
    if (t == 0) {
        int o3 = b * MP * 3;
        g_down[o3 + 0] = cx; g_down[o3 + 1] = cy; g_down[o3 + 2] = cz;
        out_down[o3 + 0] = cx; out_down[o3 + 1] = cy; out_down[o3 + 2] = cz;
    }
    int base = t * 16;
    ull pxp[8], pyp[8], pzp[8];
    float md[16];
#pragma unroll
    for (int j = 0; j < 8; j++) {
        pxp[j] = *(const ull*)(sxx + base + 2 * j);
        pyp[j] = *(const ull*)(syy + base + 2 * j);
        pzp[j] = *(const ull*)(szz + base + 2 * j);
        md[2 * j] = 1e10f; md[2 * j + 1] = 1e10f;
    }
    int buf = 0;
    for (int it = 1; it < MP; it++) {
        ull ncx = f2pk(-cx, -cx), ncy = f2pk(-cy, -cy), ncz = f2pk(-cz, -cz);
#pragma unroll
        for (int j = 0; j < 8; j++) {
            ull dx = addx2(pxp[j], ncx);
            ull dy = addx2(pyp[j], ncy);
            ull dz = addx2(pzp[j], ncz);
            ull s = addx2(addx2(mulx2(dx, dx), mulx2(dy, dy)), mulx2(dz, dz));
            float lo, hi; f2up(s, lo, hi);
            md[2 * j]     = fminf(md[2 * j], lo);
            md[2 * j + 1] = fminf(md[2 * j + 1], hi);
        }
        // 16-way max tree
        float a0 = fmaxf(md[0], md[1]),  a1 = fmaxf(md[2], md[3]);
        float a2 = fmaxf(md[4], md[5]),  a3 = fmaxf(md[6], md[7]);
        float a4 = fmaxf(md[8], md[9]),  a5 = fmaxf(md[10], md[11]);
        float a6 = fmaxf(md[12], md[13]), a7 = fmaxf(md[14], md[15]);
        float b0 = fmaxf(a0, a1), b1 = fmaxf(a2, a3);
        float b2 = fmaxf(a4, a5), b3 = fmaxf(a6, a7);
        float m = fmaxf(fmaxf(b0, b1), fmaxf(b2, b3));
        unsigned wm = __reduce_max_sync(0xffffffffu, __float_as_uint(m));
        if (lane == 0) s_bv[buf][wid] = wm;
        __syncthreads();
        if (t == 0) s_gi[buf ^ 1] = 0xFFFFFFFFu;   // recycle slot for next iter
        unsigned gm = __reduce_max_sync(0xffffffffu, s_bv[buf][lane & 15]);
        if (wm == gm) {          // warp-uniform: only matching warp(s) pay
            unsigned li = 0xFFFFFFFFu;
#pragma unroll
            for (int j = 15; j >= 0; j--)
                li = (__float_as_uint(md[j]) == gm) ? (unsigned)(base + j) : li;
            unsigned wi = __reduce_min_sync(0xffffffffu, li);
            if (lane == 0) atomicMin(&s_gi[buf], wi);
        }
        __syncthreads();
        unsigned gi = s_gi[buf];
        cx = sxx[gi]; cy = syy[gi]; cz = szz[gi];
        if (t == 0) {
            int o3 = (b * MP + it) * 3;
            g_down[o3 + 0] = cx; g_down[o3 + 1] = cy; g_down[o3 + 2] = cz;
            out_down[o3 + 0] = cx; out_down[o3 + 1] = cy; out_down[o3 + 2] = cz;
        }
        buf ^= 1;
    }
}

// ---------------- KNN v2: 128 thr, split candidates + stable merge --------
__global__ void __launch_bounds__(128) k_knn(const float* __restrict__ x) {
    extern __shared__ float kp[];
    float* sxx = kp;
    float* syy = kp + NP;
    float* szz = kp + 2 * NP;
    float* sdl = kp + 3 * NP;                 // [2][64][17] dists
    int*   sil = (int*)(kp + 3 * NP + 2176);  // [2][64][17] idx
    int t = threadIdx.x;
    int q = t & 63, half = t >> 6;
    int gid = blockIdx.x * 64 + q;
    int b = gid >> 10;
    const float* xb = x + (size_t)b * NP * 3;
    for (int i = t; i < NP; i += 128) {
        sxx[i] = xb[3 * i]; syy[i] = xb[3 * i + 1]; szz[i] = xb[3 * i + 2];
    }
    __syncthreads();
    float qx = g_down[gid * 3 + 0], qy = g_down[gid * 3 + 1], qz = g_down[gid * 3 + 2];
    float sd = __fadd_rn(__fadd_rn(__fmul_rn(qx, qx), __fmul_rn(qy, qy)), __fmul_rn(qz, qz));
    ull qxp = f2pk(qx, qx), qyp = f2pk(qy, qy), qzp = f2pk(qz, qz);
    ull sdp = f2pk(sd, sd), n2p = f2pk(-2.f, -2.f);
    float dist[17]; int ind[17];
#pragma unroll
    for (int i = 0; i < 17; i++) { dist[i] = 3.4e38f; ind[i] = 0; }
    int n0 = half * 4096;
    for (int n = n0; n < n0 + 4096; n += 2) {
        ull axp = *(const ull*)(sxx + n);
        ull ayp = *(const ull*)(syy + n);
        ull azp = *(const ull*)(szz + n);
        ull sn = addx2(addx2(mulx2(axp, axp), mulx2(ayp, ayp)), mulx2(azp, azp));
        ull dt = addx2(addx2(mulx2(qxp, axp), mulx2(qyp, ayp)), mulx2(qzp, azp));
        ull d2p = addx2(addx2(sdp, sn), mulx2(n2p, dt));
        float dlo, dhi; f2up(d2p, dlo, dhi);
#pragma unroll
        for (int h = 0; h < 2; h++) {
            float d2 = h ? dhi : dlo;
            int ni = n + h;
            if (d2 < dist[16]) {
                int pos = 0;
#pragma unroll
                for (int s = 0; s < 17; s++) pos += (dist[s] <= d2) ? 1 : 0;
#pragma unroll
                for (int s = 16; s > 0; s--) {
                    if (s > pos) { dist[s] = dist[s - 1]; ind[s] = ind[s - 1]; }
                    else if (s == pos) { dist[s] = d2; ind[s] = ni; }
                }
                if (pos == 0) { dist[0] = d2; ind[0] = ni; }
            }
        }
    }
    // write local lists
    {
        float* dptr = sdl + (half * 64 + q) * 17;
        int*   iptr = sil + (half * 64 + q) * 17;
#pragma unroll
        for (int s = 0; s < 17; s++) { dptr[s] = dist[s]; iptr[s] = ind[s]; }
    }
    __syncthreads();
    // stable merge (half 0 wins ties -> lower index, matching lax.top_k)
    if (t < 64) {
        const float* dA = sdl + q * 17;
        const float* dB = sdl + (64 + q) * 17;
        const int*   iA = sil + q * 17;
        const int*   iB = sil + (64 + q) * 17;
        int ia = 0, ib = 0;
        int* outp = g_knn + (size_t)gid * 17;
#pragma unroll
        for (int k = 0; k < 17; k++) {
            float da = dA[ia], db = dB[ib];
            bool takeA = (da <= db);
            outp[k] = takeA ? iA[ia] : iB[ib];
            ia += takeA ? 1 : 0;
            ib += takeA ? 0 : 1;
        }
    }
}

// ---------------- attention (unchanged from R8) ----------------------------
__global__ void __launch_bounds__(256) k_attn(
    const float* __restrict__ x,
    const float* __restrict__ w3, const float* __restrict__ b3,
    float* __restrict__ out_new)
{
    extern __shared__ __align__(16) float sm[];
    float* feat = sm;                  // [34][128] knnf
    float* h1i  = sm + 4352;           // [17][128]  pair-interleaved
    float* h2i  = sm + 6528;           // [17][128]
    float* fr2  = sm + 8704;           // [2][128]
    float* us   = sm + 8960;           // [2][256]
    float* zs   = sm + 9472;           // [2][64][2]
    float* knnx = sm + 9728;           // 102
    float* dwn  = sm + 9830;           // 6
    float* lgA  = sm + 9836;           // 32
    float* lgB  = sm + 9868;           // 2
    float* lgC  = sm + 9870;           // 2
    int*   sidx = (int*)(sm + 9872);   // 34

    int t = threadIdx.x;
    int wid = t >> 5, lane = t & 31;
    int bm0 = blockIdx.x * 2;
    int b = bm0 >> 10;
    const float* xb = x + (size_t)b * NP * 3;

    if (t < 34) {
        int id = g_knn[(size_t)bm0 * 17 + t];
        sidx[t] = id;
        knnx[t * 3 + 0] = xb[id * 3 + 0];
        knnx[t * 3 + 1] = xb[id * 3 + 1];
        knnx[t * 3 + 2] = xb[id * 3 + 2];
    }
    if (t < 6) dwn[t] = g_down[(size_t)bm0 * 3 + t];
    __syncthreads();

    for (int r = wid; r < 34; r += 8) {
        const float4* src = (const float4*)(g_f2 + ((size_t)(b * NP) + sidx[r]) * 128);
        ((float4*)(feat + r * 128))[lane] = src[lane];
    }

    for (int i = 0; i < 9; i++) {
        int task = t + 256 * i;
        if (task < 2176) {
            int o = task & 63, row = task >> 6;
            int j = (row >= 17) ? 1 : 0;
            int pr = row - 17 * j;
            const float* kpp = knnx + row * 3;
            const float* dp = dwn + j * 3;
            float r0 = dp[0], r1 = dp[1], r2v = dp[2];
            float r3 = kpp[0], r4 = kpp[1], r5 = kpp[2];
            const float* w = g_w1f + o * 9;
            float a = g_b1f[o];
            a += w[0] * r0 + w[1] * r1 + w[2] * r2v;
            a += w[3] * r3 + w[4] * r4 + w[5] * r5;
            a += w[6] * (r0 - r3) + w[7] * (r1 - r4) + w[8] * (r2v - r5);
            a = a > 0.f ? a : 0.01f * a;
            h1i[pr * 128 + o * 2 + j] = a;
        }
    }
    __syncthreads();
    {
        const ulonglong2* w2d = (const ulonglong2*)g_s2w2d;
        for (int i = 0; i < 3; i++) {
            int task = t + 256 * i;
            if (task < 544) {
                int prow = task >> 5, o = task & 31;
                int o2 = o + 32;
                const ulonglong2* hv = (const ulonglong2*)(h1i + prow * 128);
                float ba = g_b2f[o], bb2v = g_b2f[o2];
                ull accA = f2pk(ba, ba), accB = f2pk(bb2v, bb2v);
#pragma unroll 4
                for (int c2 = 0; c2 < 32; c2++) {
                    ulonglong2 v = hv[c2];
                    ulonglong2 wA = w2d[c2 * 64 + o];
                    ulonglong2 wB = w2d[c2 * 64 + o2];
                    accA = fma2(wA.x, v.x, accA); accA = fma2(wA.y, v.y, accA);
                    accB = fma2(wB.x, v.x, accB); accB = fma2(wB.y, v.y, accB);
                }
                float a0, a1; f2up(accA, a0, a1);
                a0 = a0 > 0.f ? a0 : 0.01f * a0;
                a1 = a1 > 0.f ? a1 : 0.01f * a1;
                h2i[prow * 128 + o * 2]     = a0;
                h2i[prow * 128 + o * 2 + 1] = a1;
                f2up(accB, a0, a1);
                a0 = a0 > 0.f ? a0 : 0.01f * a0;
                a1 = a1 > 0.f ? a1 : 0.01f * a1;
                h2i[prow * 128 + o2 * 2]     = a0;
                h2i[prow * 128 + o2 * 2 + 1] = a1;
            }
        }
    }
    __syncthreads();
    {
        int mi = t >> 7, o = t & 127;
        const ulonglong2* hc2 = (const ulonglong2*)h2i;
        float acc = b3[o];
#pragma unroll 4
        for (int c4 = 0; c4 < 16; c4++) {
            float4 w = ((const float4*)g_s2w3p)[c4 * 128 + o];
            ulonglong2 p0 = hc2[2 * c4], p1 = hc2[2 * c4 + 1];
            float l0, h0v, l1, h1v, l2, h2v, l3, h3v;
            f2up(p0.x, l0, h0v); f2up(p0.y, l1, h1v);
            f2up(p1.x, l2, h2v); f2up(p1.y, l3, h3v);
            float v0 = mi ? h0v : l0, v1 = mi ? h1v : l1;
            float v2 = mi ? h2v : l2, v3 = mi ? h3v : l3;
            acc += w.x * v0 + w.y * v1 + w.z * v2 + w.w * v3;
        }
        fr2[mi * 128 + o] = acc;
    }
    __syncthreads();
    {
        const float4* ap = (const float4*)g_Ap;
        float a0 = 0.f, a1 = 0.f;
        for (int c4 = 0; c4 < 32; c4++) {
            float4 w = ap[c4 * 256 + t];
            float4 v0 = *(const float4*)(feat + c4 * 4);
            float4 v1 = *(const float4*)(feat + 17 * 128 + c4 * 4);
            a0 += w.x * v0.x + w.y * v0.y + w.z * v0.z + w.w * v0.w;
            a1 += w.x * v1.x + w.y * v1.y + w.z * v1.z + w.w * v1.w;
        }
        for (int c4 = 0; c4 < 32; c4++) {
            float4 w = ap[(32 + c4) * 256 + t];
            float4 v0 = *(const float4*)(fr2 + c4 * 4);
            float4 v1 = *(const float4*)(fr2 + 128 + c4 * 4);
            a0 += w.x * v0.x + w.y * v0.y + w.z * v0.z + w.w * v0.w;
            a1 += w.x * v1.x + w.y * v1.y + w.z * v1.z + w.w * v1.w;
        }
        float cv = g_cvec[t];
        us[t] = a0 + cv;
        us[256 + t] = a1 + cv;
    }
    __syncthreads();
    {
        int mi = t >> 7, rem = t & 127, c = rem >> 1, oh = rem & 1;
        const float* ur = us + mi * 256 + 128 + oh * 64;
        float acc = 0.f;
#pragma unroll 4
        for (int o = 0; o < 64; o++) acc += __ldg(w3 + (oh * 64 + o) * 64 + c) * ur[o];
        zs[(mi * 64 + c) * 2 + oh] = acc;
    }
    __syncthreads();
    for (int task = wid; task < 36; task += 8) {
        float s = 0.f;
        if (task < 32) {
            int mi = task >> 4, j = task & 15;
            const float* uf = us + mi * 256;
            const float* fr = feat + (mi * 17 + 1 + j) * 128;
#pragma unroll
            for (int k = 0; k < 4; k++) { int o = lane + 32 * k; s += uf[o] * fr[o]; }
            const float* hj = h2i + (1 + j) * 128;
#pragma unroll
            for (int k = 0; k < 2; k++) {
                int c = lane + 32 * k;
                s += (zs[(mi * 64 + c) * 2] + zs[(mi * 64 + c) * 2 + 1]) * hj[c * 2 + mi];
            }
        } else if (task < 34) {
            int mi = task - 32;
            const float* fl = feat + mi * 17 * 128;
            const float* fh = fr2 + mi * 128;
#pragma unroll
            for (int k = 0; k < 4; k++) {
                int o = lane + 32 * k;
                s += __ldg(&g_vb[o]) * fl[o] + __ldg(&g_vb[128 + o]) * fh[o];
            }
        } else {
            int mi = task - 34;
            const float* uh = us + mi * 256 + 128;
#pragma unroll
            for (int k = 0; k < 4; k++) { int o = lane + 32 * k; s += uh[o] * __ldg(b3 + o); }
        }
#pragma unroll
        for (int off = 16; off; off >>= 1) s += __shfl_down_sync(0xffffffffu, s, off);
        if (lane == 0) {
            if (task < 32) lgA[task] = s;
            else if (task < 34) lgB[task - 32] = s;
            else lgC[task - 34] = s;
        }
    }
    __syncthreads();

    if (t < 2) {
        float ex = lgB[t] + lgC[t] + g_s0[0];
        float l[16], mx = -3.4e38f;
#pragma unroll
        for (int j = 0; j < 16; j++) { l[j] = lgA[t * 16 + j] + ex; mx = fmaxf(mx, l[j]); }
        float sum = 0.f;
#pragma unroll
        for (int j = 0; j < 16; j++) { l[j] = expf(l[j] - mx); sum += l[j]; }
        float inv = 1.f / sum;
        float nx = 0.f, ny = 0.f, nz = 0.f;
#pragma unroll
        for (int j = 0; j < 16; j++) {
            float w = l[j] * inv;
            const float* kpp = knnx + (t * 17 + 1 + j) * 3;
            nx += w * kpp[0]; ny += w * kpp[1]; nz += w * kpp[2];
        }
        float* po = out_new + (size_t)(bm0 + t) * 3;
        po[0] = nx; po[1] = ny; po[2] = nz;
    }
}

// ---------------- launch ---------------------------------------------------
extern "C" void kernel_launch(void* const* d_in, const int* in_sizes, int n_in,
                              void* d_out, int out_size) {
    const float* x      = (const float*)d_in[0];
    const float* gf     = (const float*)d_in[1];
    const float* c1_w1  = (const float*)d_in[2];
    const float* c1_b1  = (const float*)d_in[3];
    const float* c1_w2  = (const float*)d_in[4];
    const float* c1_b2  = (const float*)d_in[5];
    const float* cf_w1  = (const float*)d_in[6];
    const float* cf_b1  = (const float*)d_in[7];
    const float* cf_w2  = (const float*)d_in[8];
    const float* cf_b2  = (const float*)d_in[9];
    const float* cs_w1  = (const float*)d_in[10];
    const float* cs_b1  = (const float*)d_in[11];
    const float* cs_w2  = (const float*)d_in[12];
    const float* cs_b2  = (const float*)d_in[13];
    const float* s2_w1  = (const float*)d_in[14];
    const float* s2_b1  = (const float*)d_in[15];
    const float* s2_g1  = (const float*)d_in[16];
    const float* s2_bb1 = (const float*)d_in[17];
    const float* s2_w2  = (const float*)d_in[18];
    const float* s2_b2  = (const float*)d_in[19];
    const float* s2_g2  = (const float*)d_in[20];
    const float* s2_bb2 = (const float*)d_in[21];
    const float* s2_w3  = (const float*)d_in[22];
    const float* s2_b3  = (const float*)d_in[23];
    const float* q_w    = (const float*)d_in[24];
    const float* q_b    = (const float*)d_in[25];
    const float* k_w    = (const float*)d_in[26];
    const float* k_b    = (const float*)d_in[27];
    float* out = (float*)d_out;

    static bool s_init = false;
    static cudaStream_t st;
    static cudaEvent_t evF, evD;
    const int FEAT_SMEM = (384 * FS + 96) * 4;
    const int ATTN_SMEM = 9920 * 4;
    const int KNN_SMEM  = (3 * NP + 2 * 2176) * 4;
    if (!s_init) {
        cudaStreamCreateWithFlags(&st, cudaStreamNonBlocking);
        cudaEventCreateWithFlags(&evF, cudaEventDisableTiming);
        cudaEventCreateWithFlags(&evD, cudaEventDisableTiming);
        cudaFuncSetAttribute(k_feat, cudaFuncAttributeMaxDynamicSharedMemorySize, FEAT_SMEM);
        cudaFuncSetAttribute(k_knn,  cudaFuncAttributeMaxDynamicSharedMemorySize, KNN_SMEM);
        cudaFuncSetAttribute(k_fps,  cudaFuncAttributeMaxDynamicSharedMemorySize, NP * 3 * 4);
        cudaFuncSetAttribute(k_attn, cudaFuncAttributeMaxDynamicSharedMemorySize, ATTN_SMEM);
        s_init = true;
    }

    // fork point recorded first so side stream starts immediately
    cudaEventRecord(evF, 0);
    cudaStreamWaitEvent(st, evF, 0);

    // main stream first in submission order; fps lands at profiled slot #4
    k_prep<<<730, 256>>>(cs_w1, cs_w2, c1_w2,                         // #1
                         s2_w1, s2_b1, s2_g1, s2_bb1,
                         s2_w2, s2_b2, s2_g2, s2_bb2, s2_w3,
                         q_w, k_w, q_b, k_b,
                         gf, cf_w1, cf_b1, cf_w2, cf_b2);
    k_prep2<<<BN, 256>>>(cs_b1);                                      // #2
    k_feat<<<(BN * NP) / 32, 256, FEAT_SMEM>>>(x,                     // #3
        c1_w1, c1_b1, c1_b2, cs_b2);

    k_fps<<<BN, 512, NP * 3 * 4, st>>>(x, out);                       // #4 <- profiled
    k_knn<<<(BN * MP) / 64, 128, KNN_SMEM, st>>>(x);                  // #5
    cudaEventRecord(evD, st);
    cudaStreamWaitEvent(0, evD, 0);
    k_attn<<<(BN * MP) / 2, 256, ATTN_SMEM>>>(x, s2_w3, s2_b3,        // #6
        out + (size_t)BN * MP * 3);
}